// round 2
// baseline (speedup 1.0000x reference)
#include <cuda_runtime.h>

// ---------------- problem constants ----------------
#define BB 2
#define TT 1024
#define EE 1024
#define HH 16
#define DD 64
#define LL 6
#define FF 4096
#define VV 32000
#define RR (BB*TT)   // 2048 token rows

// ---------------- device scratch (static, no allocations) ----------------
__device__ float g_x [RR*EE];
__device__ float g_h [RR*EE];
__device__ float g_q [RR*EE];
__device__ float g_k [RR*EE];
__device__ float g_v [RR*EE];
__device__ float g_o [RR*EE];
__device__ float g_ff[RR*FF];
__device__ float g_S [(size_t)BB*HH*TT*TT];   // 134 MB attention scores

// ---------------- embed: x = tok_emb[idx] + pos_emb ----------------
__global__ void k_embed(const int* __restrict__ idx, const float* __restrict__ tok,
                        const float* __restrict__ pos, float* __restrict__ x) {
    int r = blockIdx.x;              // 0..2047
    int t = r & (TT - 1);
    int tokid = idx[r];
    const float4* te = (const float4*)(tok + (size_t)tokid * EE);
    const float4* pe = (const float4*)(pos + (size_t)t * EE);
    float4* xr = (float4*)(x + (size_t)r * EE);
    int c = threadIdx.x;             // 256 threads, 256 float4 per row
    float4 a = te[c], b = pe[c];
    xr[c] = make_float4(a.x + b.x, a.y + b.y, a.z + b.z, a.w + b.w);
}

// ---------------- block reduce helper ----------------
__device__ __forceinline__ float blockReduceSum(float val, float* red) {
    int tid = threadIdx.x;
    #pragma unroll
    for (int o = 16; o; o >>= 1) val += __shfl_xor_sync(0xffffffffu, val, o);
    if ((tid & 31) == 0) red[tid >> 5] = val;
    __syncthreads();
    if (tid < 32) {
        float v = (tid < 8) ? red[tid] : 0.f;
        #pragma unroll
        for (int o = 4; o; o >>= 1) v += __shfl_xor_sync(0xffffffffu, v, o);
        if (tid == 0) red[0] = v;
    }
    __syncthreads();
    float r = red[0];
    __syncthreads();
    return r;
}

// ---------------- layernorm (two-pass, one block per row) ----------------
__global__ void k_ln(const float* __restrict__ x, const float* __restrict__ g,
                     const float* __restrict__ b, float* __restrict__ out) {
    __shared__ float red[32];
    int row = blockIdx.x, tid = threadIdx.x;
    const float* xr = x + (size_t)row * EE;
    float v[4];
    float s = 0.f;
    #pragma unroll
    for (int i = 0; i < 4; i++) { v[i] = xr[tid + 256 * i]; s += v[i]; }
    s = blockReduceSum(s, red);
    float mean = s * (1.f / EE);
    float s2 = 0.f;
    #pragma unroll
    for (int i = 0; i < 4; i++) { float d = v[i] - mean; s2 += d * d; }
    s2 = blockReduceSum(s2, red);
    float inv = rsqrtf(s2 * (1.f / EE) + 1e-5f);
    #pragma unroll
    for (int i = 0; i < 4; i++) {
        int c = tid + 256 * i;
        out[(size_t)row * EE + c] = (v[i] - mean) * inv * g[c] + b[c];
    }
}

// ---------------- SGEMM: C = A[MxK] * B[KxN] (+bias)(+resid)(relu) ----------------
// BM=BN=128, BK=8, 256 threads, 8x8 per-thread tile. All dims multiples of 128/8.
template<bool BIAS, bool RELU, bool RESID>
__global__ void k_sgemm(const float* __restrict__ A, const float* __restrict__ B,
                        const float* __restrict__ bias, const float* __restrict__ resid,
                        float* __restrict__ C, int M, int N, int K) {
    __shared__ float As[8][128];
    __shared__ float Bs[8][128];
    int tid = threadIdx.x;
    int rowBase = blockIdx.y * 128;
    int colBase = blockIdx.x * 128;
    int aRow = tid >> 1;              // 0..127
    int aCol = (tid & 1) * 4;         // 0 or 4
    int bRow = tid >> 5;              // 0..7
    int bCol = (tid & 31) * 4;        // 0..124
    int tx = tid & 15, ty = tid >> 4;

    const float* Aptr = A + (size_t)(rowBase + aRow) * K + aCol;
    const float* Bptr = B + (size_t)bRow * N + colBase + bCol;

    float acc[8][8];
    #pragma unroll
    for (int i = 0; i < 8; i++)
        #pragma unroll
        for (int j = 0; j < 8; j++) acc[i][j] = 0.f;

    for (int k0 = 0; k0 < K; k0 += 8) {
        float4 a4 = *(const float4*)(Aptr + k0);
        As[aCol + 0][aRow] = a4.x;
        As[aCol + 1][aRow] = a4.y;
        As[aCol + 2][aRow] = a4.z;
        As[aCol + 3][aRow] = a4.w;
        float4 b4 = *(const float4*)(Bptr + (size_t)k0 * N);
        *(float4*)&Bs[bRow][bCol] = b4;
        __syncthreads();
        #pragma unroll
        for (int kk = 0; kk < 8; kk++) {
            float ra[8], rb[8];
            #pragma unroll
            for (int i = 0; i < 8; i++) ra[i] = As[kk][ty * 8 + i];
            #pragma unroll
            for (int j = 0; j < 8; j++) rb[j] = Bs[kk][tx * 8 + j];
            #pragma unroll
            for (int i = 0; i < 8; i++)
                #pragma unroll
                for (int j = 0; j < 8; j++)
                    acc[i][j] = fmaf(ra[i], rb[j], acc[i][j]);
        }
        __syncthreads();
    }

    int cbase = colBase + tx * 8;
    float bvec[8];
    if (BIAS) {
        #pragma unroll
        for (int j = 0; j < 8; j++) bvec[j] = bias[cbase + j];
    }
    #pragma unroll
    for (int i = 0; i < 8; i++) {
        size_t row = rowBase + ty * 8 + i;
        float* Crow = C + row * (size_t)N + cbase;
        float outv[8];
        #pragma unroll
        for (int j = 0; j < 8; j++) {
            float vv = acc[i][j];
            if (BIAS)  vv += bvec[j];
            if (RESID) vv += resid[row * (size_t)N + cbase + j];
            if (RELU)  vv = fmaxf(vv, 0.f);
            outv[j] = vv;
        }
        *(float4*)(Crow)     = make_float4(outv[0], outv[1], outv[2], outv[3]);
        *(float4*)(Crow + 4) = make_float4(outv[4], outv[5], outv[6], outv[7]);
    }
}

// ---------------- attention scores: S = (Q K^T) * scale, causal masked ----------------
// grid (ktile=16, qtile=16, bh=32), 256 threads, 64x64 tile, K-dim = 64 fully resident
__global__ void k_scores(const float* __restrict__ q, const float* __restrict__ k) {
    int bh = blockIdx.z, b = bh >> 4, h = bh & 15;
    int q0 = blockIdx.y * 64, k0 = blockIdx.x * 64;
    int tid = threadIdx.x;
    size_t base = ((size_t)bh * TT + q0) * TT + k0;
    if (k0 > q0 + 63) {   // fully masked tile
        for (int i = tid; i < 64 * 64; i += 256)
            g_S[base + (size_t)(i >> 6) * TT + (i & 63)] = -1e30f;
        return;
    }
    __shared__ float Qs[64][65];
    __shared__ float Ks[64][65];
    for (int i = tid; i < 64 * 64; i += 256) {
        int rr = i >> 6, cc = i & 63;
        Qs[rr][cc] = q[(size_t)(b * TT + q0 + rr) * EE + h * DD + cc];
        Ks[rr][cc] = k[(size_t)(b * TT + k0 + rr) * EE + h * DD + cc];
    }
    __syncthreads();
    int tx = tid & 15, ty = tid >> 4;
    float acc[4][4];
    #pragma unroll
    for (int i = 0; i < 4; i++)
        #pragma unroll
        for (int j = 0; j < 4; j++) acc[i][j] = 0.f;
    #pragma unroll 8
    for (int d = 0; d < 64; d++) {
        float ra[4], rb[4];
        #pragma unroll
        for (int i = 0; i < 4; i++) ra[i] = Qs[ty * 4 + i][d];
        #pragma unroll
        for (int j = 0; j < 4; j++) rb[j] = Ks[tx * 4 + j][d];
        #pragma unroll
        for (int i = 0; i < 4; i++)
            #pragma unroll
            for (int j = 0; j < 4; j++)
                acc[i][j] = fmaf(ra[i], rb[j], acc[i][j]);
    }
    #pragma unroll
    for (int i = 0; i < 4; i++)
        #pragma unroll
        for (int j = 0; j < 4; j++) {
            int qi = q0 + ty * 4 + i, kj = k0 + tx * 4 + j;
            g_S[((size_t)bh * TT + qi) * TT + kj] =
                (kj <= qi) ? acc[i][j] * 0.125f : -1e30f;
        }
}

// ---------------- softmax per row ----------------
__global__ void k_softmax() {
    __shared__ float red[32];
    size_t row = blockIdx.x;
    float* r = g_S + row * (size_t)TT;
    int tid = threadIdx.x;
    float v[4], m = -1e30f;
    #pragma unroll
    for (int i = 0; i < 4; i++) { v[i] = r[tid + 256 * i]; m = fmaxf(m, v[i]); }
    #pragma unroll
    for (int o = 16; o; o >>= 1) m = fmaxf(m, __shfl_xor_sync(0xffffffffu, m, o));
    if ((tid & 31) == 0) red[tid >> 5] = m;
    __syncthreads();
    if (tid < 32) {
        float t = (tid < 8) ? red[tid] : -1e30f;
        #pragma unroll
        for (int o = 4; o; o >>= 1) t = fmaxf(t, __shfl_xor_sync(0xffffffffu, t, o));
        if (tid == 0) red[0] = t;
    }
    __syncthreads();
    m = red[0];
    __syncthreads();
    float s = 0.f;
    #pragma unroll
    for (int i = 0; i < 4; i++) { v[i] = __expf(v[i] - m); s += v[i]; }
    s = blockReduceSum(s, red);
    float inv = 1.f / s;
    #pragma unroll
    for (int i = 0; i < 4; i++) r[tid + 256 * i] = v[i] * inv;
}

// ---------------- O = softmax(S) @ V ----------------
// grid (qtile=16, bh=32), 256 threads, output tile 64 rows x 64 (full head dim)
__global__ void k_av(const float* __restrict__ v, float* __restrict__ o) {
    int bh = blockIdx.y, b = bh >> 4, h = bh & 15;
    int q0 = blockIdx.x * 64;
    __shared__ float Ss[64][65];
    __shared__ float Vs[64][65];
    int tid = threadIdx.x, tx = tid & 15, ty = tid >> 4;
    float acc[4][4];
    #pragma unroll
    for (int i = 0; i < 4; i++)
        #pragma unroll
        for (int j = 0; j < 4; j++) acc[i][j] = 0.f;
    int kend = q0 + 64;   // causal: rows beyond are exactly 0 after softmax
    for (int j0 = 0; j0 < kend; j0 += 64) {
        for (int i = tid; i < 64 * 64; i += 256) {
            int rr = i >> 6, cc = i & 63;
            Ss[rr][cc] = g_S[((size_t)bh * TT + q0 + rr) * TT + j0 + cc];
            Vs[rr][cc] = v[(size_t)(b * TT + j0 + rr) * EE + h * DD + cc];
        }
        __syncthreads();
        #pragma unroll 8
        for (int jj = 0; jj < 64; jj++) {
            float ra[4], rb[4];
            #pragma unroll
            for (int i = 0; i < 4; i++) ra[i] = Ss[ty * 4 + i][jj];
            #pragma unroll
            for (int j = 0; j < 4; j++) rb[j] = Vs[jj][tx * 4 + j];
            #pragma unroll
            for (int i = 0; i < 4; i++)
                #pragma unroll
                for (int j = 0; j < 4; j++)
                    acc[i][j] = fmaf(ra[i], rb[j], acc[i][j]);
        }
        __syncthreads();
    }
    #pragma unroll
    for (int i = 0; i < 4; i++)
        #pragma unroll
        for (int j = 0; j < 4; j++)
            o[(size_t)(b * TT + q0 + ty * 4 + i) * EE + h * DD + tx * 4 + j] = acc[i][j];
}

// ---------------- host orchestration ----------------
extern "C" void kernel_launch(void* const* d_in, const int* in_sizes, int n_in,
                              void* d_out, int out_size) {
    const int*   idx  = (const int*)  d_in[0];
    const float* tok  = (const float*)d_in[1];
    const float* pos  = (const float*)d_in[2];
    const float* Wq   = (const float*)d_in[3];
    const float* Wk   = (const float*)d_in[4];
    const float* Wv   = (const float*)d_in[5];
    const float* Wp   = (const float*)d_in[6];
    const float* bp   = (const float*)d_in[7];
    const float* g1   = (const float*)d_in[8];
    const float* b1   = (const float*)d_in[9];
    const float* g2   = (const float*)d_in[10];
    const float* b2   = (const float*)d_in[11];
    const float* W1   = (const float*)d_in[12];
    const float* bf1  = (const float*)d_in[13];
    const float* W2   = (const float*)d_in[14];
    const float* bf2  = (const float*)d_in[15];
    const float* gf   = (const float*)d_in[16];
    const float* bff  = (const float*)d_in[17];
    const float* Wlm  = (const float*)d_in[18];
    const float* blm  = (const float*)d_in[19];
    float* out = (float*)d_out;

    float *x, *h, *q, *k, *v, *o, *ff;
    cudaGetSymbolAddress((void**)&x,  g_x);
    cudaGetSymbolAddress((void**)&h,  g_h);
    cudaGetSymbolAddress((void**)&q,  g_q);
    cudaGetSymbolAddress((void**)&k,  g_k);
    cudaGetSymbolAddress((void**)&v,  g_v);
    cudaGetSymbolAddress((void**)&o,  g_o);
    cudaGetSymbolAddress((void**)&ff, g_ff);

    k_embed<<<RR, 256>>>(idx, tok, pos, x);

    dim3 gEE(EE / 128, RR / 128);      // (8, 16)
    dim3 gFF(FF / 128, RR / 128);      // (32, 16)
    dim3 gLM(VV / 128, RR / 128);      // (250, 16)

    for (int l = 0; l < LL; l++) {
        const float* wq = Wq + (size_t)l * EE * EE;
        const float* wk = Wk + (size_t)l * EE * EE;
        const float* wv = Wv + (size_t)l * EE * EE;
        const float* wp = Wp + (size_t)l * EE * EE;
        const float* w1 = W1 + (size_t)l * EE * FF;
        const float* w2 = W2 + (size_t)l * FF * EE;

        k_ln<<<RR, 256>>>(x, g1 + l * EE, b1 + l * EE, h);
        k_sgemm<false,false,false><<<gEE, 256>>>(h, wq, nullptr, nullptr, q, RR, EE, EE);
        k_sgemm<false,false,false><<<gEE, 256>>>(h, wk, nullptr, nullptr, k, RR, EE, EE);
        k_sgemm<false,false,false><<<gEE, 256>>>(h, wv, nullptr, nullptr, v, RR, EE, EE);

        k_scores<<<dim3(16, 16, 32), 256>>>(q, k);
        k_softmax<<<BB * HH * TT, 256>>>();
        k_av<<<dim3(16, 32), 256>>>(v, o);

        // x = x + o @ Wp + bp   (in-place residual: each elem read+written by same thread)
        k_sgemm<true,false,true><<<gEE, 256>>>(o, wp, bp + l * EE, x, x, RR, EE, EE);

        k_ln<<<RR, 256>>>(x, g2 + l * EE, b2 + l * EE, h);
        // ff = relu(h @ W1 + bf1)
        k_sgemm<true,true,false><<<gFF, 256>>>(h, w1, bf1 + l * FF, nullptr, ff, RR, FF, EE);
        // x = x + ff @ W2 + bf2
        k_sgemm<true,false,true><<<gEE, 256>>>(ff, w2, bf2 + l * EE, x, x, RR, EE, FF);
    }

    k_ln<<<RR, 256>>>(x, gf, bff, h);
    k_sgemm<true,false,false><<<gLM, 256>>>(h, Wlm, blm, nullptr, out, RR, VV, EE);
}

// round 5
// speedup vs baseline: 1.6214x; 1.6214x over previous
#include <cuda_runtime.h>
#include <cstdint>

// ---------------- problem constants ----------------
#define BB 2
#define TT 1024
#define EE 1024
#define HH 16
#define DD 64
#define LL 6
#define FF 4096
#define VV 32000
#define RR (BB*TT)   // 2048 token rows

// ---------------- device scratch (static, no allocations) ----------------
__device__ float g_x [RR*EE];
__device__ float g_h [RR*EE];
__device__ float g_q [RR*EE];
__device__ float g_k [RR*EE];
__device__ float g_v [RR*EE];
__device__ float g_o [RR*EE];
__device__ float g_ff[RR*FF];
__device__ float g_S [(size_t)BB*HH*TT*TT];   // 134 MB attention scores

__device__ __forceinline__ uint32_t smem_u32(const void* p) {
    uint32_t a;
    asm("{ .reg .u64 t; cvta.to.shared.u64 t, %1; cvt.u32.u64 %0, t; }"
        : "=r"(a) : "l"(p));
    return a;
}

#define SW128(o) ((o) ^ (((o) >> 3) & 0x70))

__device__ __forceinline__ void ldsm_x4(uint32_t& r0, uint32_t& r1,
                                        uint32_t& r2, uint32_t& r3, uint32_t addr) {
    asm volatile("ldmatrix.sync.aligned.m8n8.x4.shared.b16 {%0,%1,%2,%3}, [%4];"
                 : "=r"(r0), "=r"(r1), "=r"(r2), "=r"(r3) : "r"(addr));
}

__device__ __forceinline__ void mma_tf32(float& c0, float& c1, float& c2, float& c3,
                                         uint32_t a0, uint32_t a1, uint32_t a2, uint32_t a3,
                                         uint32_t b0, uint32_t b1) {
    asm volatile("mma.sync.aligned.m16n8k8.row.col.f32.tf32.tf32.f32 "
                 "{%0,%1,%2,%3}, {%4,%5,%6,%7}, {%8,%9}, {%0,%1,%2,%3};"
                 : "+f"(c0), "+f"(c1), "+f"(c2), "+f"(c3)
                 : "r"(a0), "r"(a1), "r"(a2), "r"(a3), "r"(b0), "r"(b1));
}

// split fp32 (raw bits) into hi/lo tf32 pair: x ≈ hi + lo, each exactly tf32
__device__ __forceinline__ void split_tf32(uint32_t x, uint32_t& hi, uint32_t& lo) {
    float xf = __uint_as_float(x);
    uint32_t h;
    asm("cvt.rna.tf32.f32 %0, %1;" : "=r"(h) : "f"(xf));
    float rf = xf - __uint_as_float(h);
    uint32_t l;
    asm("cvt.rna.tf32.f32 %0, %1;" : "=r"(l) : "f"(rf));
    hi = h; lo = l;
}

// ================= 3xTF32 tensor-core GEMM (fp32-accurate) =================
// C[M,N] = A[M,K] @ B[K,N] (+bias)(+resid)(relu). 128x128 CTA tile, BK=32.
// grid = (N/128, M/128), 256 threads (8 warps, 2x4 of 64x32 warp tiles).
#define TG_SMEM 65536

template<bool BIAS, bool RELU, bool RESID>
__global__ void __launch_bounds__(256, 1)
k_tgemm(const float* __restrict__ A, const float* __restrict__ B,
        const float* __restrict__ bias, const float* __restrict__ resid,
        float* __restrict__ C, int M, int N, int K) {
    extern __shared__ char smem[];
    const uint32_t sb = smem_u32(smem);
    const int tid = threadIdx.x, lane = tid & 31, wid = tid >> 5;
    const int wm = wid & 1, wn = wid >> 1;           // 2 x 4 warp grid
    const int rowBase = blockIdx.y * 128;
    const int colBase = blockIdx.x * 128;

    float acc[4][4][4];
    #pragma unroll
    for (int i = 0; i < 4; i++)
        #pragma unroll
        for (int j = 0; j < 4; j++)
            #pragma unroll
            for (int r = 0; r < 4; r++) acc[i][j][r] = 0.f;

    // ---- per-thread global-load indexing (coalesced) ----
    const int a_kq = tid & 7, a_m0 = tid >> 3;        // A: float4 at (m, kq*4)
    const int b_n  = tid & 127;                       // B: column n, 4 rows per i
    const int b_q0 = tid >> 7;                        // q = b_q0 + 2*i
    const int b_swz = (b_n >> 3) & 7;                 // XOR'd k-group

    // ---- per-thread ldmatrix addressing ----
    const int a_m_in = (lane & 7) + ((lane >> 3) & 1) * 8;
    const int a_kb   = ((lane >> 4) & 1) * 16;
    const int b_n_in = (lane & 7) + ((lane >> 4) & 1) * 8;
    const int b_kb   = ((lane >> 3) & 1) * 16;

    const int nchunk = K >> 5;
    float4 pa[4], pb[4];

    // ---- load chunk 0 straight to smem buf 0 ----
    {
        #pragma unroll
        for (int i = 0; i < 4; i++)
            pa[i] = *(const float4*)(A + (size_t)(rowBase + a_m0 + 32 * i) * K + a_kq * 4);
        #pragma unroll
        for (int i = 0; i < 4; i++) {
            int kq = (b_q0 + 2 * i) ^ b_swz;
            const float* bp = B + (size_t)(kq * 4) * N + colBase + b_n;
            pb[i] = make_float4(bp[0], bp[(size_t)N], bp[(size_t)2 * N], bp[(size_t)3 * N]);
        }
        #pragma unroll
        for (int i = 0; i < 4; i++) {
            uint32_t off = (uint32_t)((a_m0 + 32 * i) * 128 + a_kq * 16);
            *(float4*)(smem + SW128(off)) = pa[i];
        }
        #pragma unroll
        for (int i = 0; i < 4; i++) {
            int kq = (b_q0 + 2 * i) ^ b_swz;
            uint32_t off = (uint32_t)(b_n * 128 + kq * 16);
            *(float4*)(smem + 16384 + SW128(off)) = pb[i];
        }
    }
    __syncthreads();

    for (int c = 0; c < nchunk; c++) {
        const int buf = c & 1;
        const uint32_t abase = sb + buf * 32768;
        const uint32_t bbase = abase + 16384;

        // ---- prefetch next chunk into registers ----
        if (c + 1 < nchunk) {
            int k0 = (c + 1) << 5;
            #pragma unroll
            for (int i = 0; i < 4; i++)
                pa[i] = *(const float4*)(A + (size_t)(rowBase + a_m0 + 32 * i) * K + k0 + a_kq * 4);
            #pragma unroll
            for (int i = 0; i < 4; i++) {
                int kq = (b_q0 + 2 * i) ^ b_swz;
                const float* bp = B + (size_t)(k0 + kq * 4) * N + colBase + b_n;
                pb[i] = make_float4(bp[0], bp[(size_t)N], bp[(size_t)2 * N], bp[(size_t)3 * N]);
            }
        }

        // ---- compute: 4 k-steps of m16n8k8, 3xTF32 each ----
        #pragma unroll
        for (int kt = 0; kt < 4; kt++) {
            uint32_t afh[4][4], afl[4][4];
            #pragma unroll
            for (int mt = 0; mt < 4; mt++) {
                uint32_t r0, r1, r2, r3;
                int row = wm * 64 + mt * 16 + a_m_in;
                int kb  = kt * 32 + a_kb;
                uint32_t addr = abase + (uint32_t)(row * 128 + (kb ^ ((row & 7) << 4)));
                ldsm_x4(r0, r1, r2, r3, addr);
                split_tf32(r0, afh[mt][0], afl[mt][0]);
                split_tf32(r1, afh[mt][1], afl[mt][1]);
                split_tf32(r2, afh[mt][2], afl[mt][2]);
                split_tf32(r3, afh[mt][3], afl[mt][3]);
            }
            uint32_t bfh[2][4], bfl[2][4];
            #pragma unroll
            for (int ntp = 0; ntp < 2; ntp++) {
                uint32_t r0, r1, r2, r3;
                int row = wn * 32 + ntp * 16 + b_n_in;
                int kb  = kt * 32 + b_kb;
                uint32_t addr = bbase + (uint32_t)(row * 128 + (kb ^ ((row & 7) << 4)));
                ldsm_x4(r0, r1, r2, r3, addr);
                split_tf32(r0, bfh[ntp][0], bfl[ntp][0]);
                split_tf32(r1, bfh[ntp][1], bfl[ntp][1]);
                split_tf32(r2, bfh[ntp][2], bfl[ntp][2]);
                split_tf32(r3, bfh[ntp][3], bfl[ntp][3]);
            }
            #pragma unroll
            for (int mt = 0; mt < 4; mt++)
                #pragma unroll
                for (int nt = 0; nt < 4; nt++) {
                    const int np = nt >> 1, ne = (nt & 1) * 2;
                    // lo*hi + hi*lo + hi*hi (3xTF32 emulated fp32)
                    mma_tf32(acc[mt][nt][0], acc[mt][nt][1], acc[mt][nt][2], acc[mt][nt][3],
                             afl[mt][0], afl[mt][1], afl[mt][2], afl[mt][3],
                             bfh[np][ne], bfh[np][ne + 1]);
                    mma_tf32(acc[mt][nt][0], acc[mt][nt][1], acc[mt][nt][2], acc[mt][nt][3],
                             afh[mt][0], afh[mt][1], afh[mt][2], afh[mt][3],
                             bfl[np][ne], bfl[np][ne + 1]);
                    mma_tf32(acc[mt][nt][0], acc[mt][nt][1], acc[mt][nt][2], acc[mt][nt][3],
                             afh[mt][0], afh[mt][1], afh[mt][2], afh[mt][3],
                             bfh[np][ne], bfh[np][ne + 1]);
                }
        }

        // ---- stage prefetched regs into the other buffer ----
        if (c + 1 < nchunk) {
            const int nb = (c + 1) & 1;
            char* ab = smem + nb * 32768;
            char* bbuf = ab + 16384;
            __syncthreads();   // ensure all warps done reading before overwrite
            #pragma unroll
            for (int i = 0; i < 4; i++) {
                uint32_t off = (uint32_t)((a_m0 + 32 * i) * 128 + a_kq * 16);
                *(float4*)(ab + SW128(off)) = pa[i];
            }
            #pragma unroll
            for (int i = 0; i < 4; i++) {
                int kq = (b_q0 + 2 * i) ^ b_swz;
                uint32_t off = (uint32_t)(b_n * 128 + kq * 16);
                *(float4*)(bbuf + SW128(off)) = pb[i];
            }
            __syncthreads();
        }
    }

    // ---- epilogue ----
    const int row0 = lane >> 2, col0 = (lane & 3) * 2;
    #pragma unroll
    for (int mt = 0; mt < 4; mt++) {
        #pragma unroll
        for (int nt = 0; nt < 4; nt++) {
            int gm = rowBase + wm * 64 + mt * 16 + row0;
            int gn = colBase + wn * 32 + nt * 8 + col0;
            float o0 = acc[mt][nt][0], o1 = acc[mt][nt][1];
            float o2 = acc[mt][nt][2], o3 = acc[mt][nt][3];
            if (BIAS) {
                float bv0 = bias[gn], bv1 = bias[gn + 1];
                o0 += bv0; o1 += bv1; o2 += bv0; o3 += bv1;
            }
            size_t p0 = (size_t)gm * N + gn;
            size_t p1 = (size_t)(gm + 8) * N + gn;
            if (RESID) {
                float2 r0v = *(const float2*)(resid + p0);
                float2 r1v = *(const float2*)(resid + p1);
                o0 += r0v.x; o1 += r0v.y; o2 += r1v.x; o3 += r1v.y;
            }
            if (RELU) {
                o0 = fmaxf(o0, 0.f); o1 = fmaxf(o1, 0.f);
                o2 = fmaxf(o2, 0.f); o3 = fmaxf(o3, 0.f);
            }
            *(float2*)(C + p0) = make_float2(o0, o1);
            *(float2*)(C + p1) = make_float2(o2, o3);
        }
    }
}

// ---------------- embed: x = tok_emb[idx] + pos_emb ----------------
__global__ void k_embed(const int* __restrict__ idx, const float* __restrict__ tok,
                        const float* __restrict__ pos, float* __restrict__ x) {
    int r = blockIdx.x;
    int t = r & (TT - 1);
    int tokid = idx[r];
    const float4* te = (const float4*)(tok + (size_t)tokid * EE);
    const float4* pe = (const float4*)(pos + (size_t)t * EE);
    float4* xr = (float4*)(x + (size_t)r * EE);
    int c = threadIdx.x;
    float4 a = te[c], b = pe[c];
    xr[c] = make_float4(a.x + b.x, a.y + b.y, a.z + b.z, a.w + b.w);
}

// ---------------- block reduce helper ----------------
__device__ __forceinline__ float blockReduceSum(float val, float* red) {
    int tid = threadIdx.x;
    #pragma unroll
    for (int o = 16; o; o >>= 1) val += __shfl_xor_sync(0xffffffffu, val, o);
    if ((tid & 31) == 0) red[tid >> 5] = val;
    __syncthreads();
    if (tid < 32) {
        float v = (tid < 8) ? red[tid] : 0.f;
        #pragma unroll
        for (int o = 4; o; o >>= 1) v += __shfl_xor_sync(0xffffffffu, v, o);
        if (tid == 0) red[0] = v;
    }
    __syncthreads();
    float r = red[0];
    __syncthreads();
    return r;
}

// ---------------- layernorm ----------------
__global__ void k_ln(const float* __restrict__ x, const float* __restrict__ g,
                     const float* __restrict__ b, float* __restrict__ out) {
    __shared__ float red[32];
    int row = blockIdx.x, tid = threadIdx.x;
    const float* xr = x + (size_t)row * EE;
    float v[4];
    float s = 0.f;
    #pragma unroll
    for (int i = 0; i < 4; i++) { v[i] = xr[tid + 256 * i]; s += v[i]; }
    s = blockReduceSum(s, red);
    float mean = s * (1.f / EE);
    float s2 = 0.f;
    #pragma unroll
    for (int i = 0; i < 4; i++) { float d = v[i] - mean; s2 += d * d; }
    s2 = blockReduceSum(s2, red);
    float inv = rsqrtf(s2 * (1.f / EE) + 1e-5f);
    #pragma unroll
    for (int i = 0; i < 4; i++) {
        int c = tid + 256 * i;
        out[(size_t)row * EE + c] = (v[i] - mean) * inv * g[c] + b[c];
    }
}

// ---------------- attention scores ----------------
__global__ void k_scores(const float* __restrict__ q, const float* __restrict__ k) {
    int bh = blockIdx.z, b = bh >> 4, h = bh & 15;
    int q0 = blockIdx.y * 64, k0 = blockIdx.x * 64;
    int tid = threadIdx.x;
    size_t base = ((size_t)bh * TT + q0) * TT + k0;
    if (k0 > q0 + 63) {
        for (int i = tid; i < 64 * 64; i += 256)
            g_S[base + (size_t)(i >> 6) * TT + (i & 63)] = -1e30f;
        return;
    }
    __shared__ float Qs[64][65];
    __shared__ float Ks[64][65];
    for (int i = tid; i < 64 * 64; i += 256) {
        int rr = i >> 6, cc = i & 63;
        Qs[rr][cc] = q[(size_t)(b * TT + q0 + rr) * EE + h * DD + cc];
        Ks[rr][cc] = k[(size_t)(b * TT + k0 + rr) * EE + h * DD + cc];
    }
    __syncthreads();
    int tx = tid & 15, ty = tid >> 4;
    float acc[4][4];
    #pragma unroll
    for (int i = 0; i < 4; i++)
        #pragma unroll
        for (int j = 0; j < 4; j++) acc[i][j] = 0.f;
    #pragma unroll 8
    for (int d = 0; d < 64; d++) {
        float ra[4], rb[4];
        #pragma unroll
        for (int i = 0; i < 4; i++) ra[i] = Qs[ty * 4 + i][d];
        #pragma unroll
        for (int j = 0; j < 4; j++) rb[j] = Ks[tx * 4 + j][d];
        #pragma unroll
        for (int i = 0; i < 4; i++)
            #pragma unroll
            for (int j = 0; j < 4; j++)
                acc[i][j] = fmaf(ra[i], rb[j], acc[i][j]);
    }
    #pragma unroll
    for (int i = 0; i < 4; i++)
        #pragma unroll
        for (int j = 0; j < 4; j++) {
            int qi = q0 + ty * 4 + i, kj = k0 + tx * 4 + j;
            g_S[((size_t)bh * TT + qi) * TT + kj] =
                (kj <= qi) ? acc[i][j] * 0.125f : -1e30f;
        }
}

// ---------------- softmax per row ----------------
__global__ void k_softmax() {
    __shared__ float red[32];
    size_t row = blockIdx.x;
    float* r = g_S + row * (size_t)TT;
    int tid = threadIdx.x;
    float v[4], m = -1e30f;
    #pragma unroll
    for (int i = 0; i < 4; i++) { v[i] = r[tid + 256 * i]; m = fmaxf(m, v[i]); }
    #pragma unroll
    for (int o = 16; o; o >>= 1) m = fmaxf(m, __shfl_xor_sync(0xffffffffu, m, o));
    if ((tid & 31) == 0) red[tid >> 5] = m;
    __syncthreads();
    if (tid < 32) {
        float t = (tid < 8) ? red[tid] : -1e30f;
        #pragma unroll
        for (int o = 4; o; o >>= 1) t = fmaxf(t, __shfl_xor_sync(0xffffffffu, t, o));
        if (tid == 0) red[0] = t;
    }
    __syncthreads();
    m = red[0];
    __syncthreads();
    float s = 0.f;
    #pragma unroll
    for (int i = 0; i < 4; i++) { v[i] = __expf(v[i] - m); s += v[i]; }
    s = blockReduceSum(s, red);
    float inv = 1.f / s;
    #pragma unroll
    for (int i = 0; i < 4; i++) r[tid + 256 * i] = v[i] * inv;
}

// ---------------- O = softmax(S) @ V ----------------
__global__ void k_av(const float* __restrict__ v, float* __restrict__ o) {
    int bh = blockIdx.y, b = bh >> 4, h = bh & 15;
    int q0 = blockIdx.x * 64;
    __shared__ float Ss[64][65];
    __shared__ float Vs[64][65];
    int tid = threadIdx.x, tx = tid & 15, ty = tid >> 4;
    float acc[4][4];
    #pragma unroll
    for (int i = 0; i < 4; i++)
        #pragma unroll
        for (int j = 0; j < 4; j++) acc[i][j] = 0.f;
    int kend = q0 + 64;
    for (int j0 = 0; j0 < kend; j0 += 64) {
        for (int i = tid; i < 64 * 64; i += 256) {
            int rr = i >> 6, cc = i & 63;
            Ss[rr][cc] = g_S[((size_t)bh * TT + q0 + rr) * TT + j0 + cc];
            Vs[rr][cc] = v[(size_t)(b * TT + j0 + rr) * EE + h * DD + cc];
        }
        __syncthreads();
        #pragma unroll 8
        for (int jj = 0; jj < 64; jj++) {
            float ra[4], rb[4];
            #pragma unroll
            for (int i = 0; i < 4; i++) ra[i] = Ss[ty * 4 + i][jj];
            #pragma unroll
            for (int j = 0; j < 4; j++) rb[j] = Vs[jj][tx * 4 + j];
            #pragma unroll
            for (int i = 0; i < 4; i++)
                #pragma unroll
                for (int j = 0; j < 4; j++)
                    acc[i][j] = fmaf(ra[i], rb[j], acc[i][j]);
        }
        __syncthreads();
    }
    #pragma unroll
    for (int i = 0; i < 4; i++)
        #pragma unroll
        for (int j = 0; j < 4; j++)
            o[(size_t)(b * TT + q0 + ty * 4 + i) * EE + h * DD + tx * 4 + j] = acc[i][j];
}

// ---------------- host orchestration ----------------
extern "C" void kernel_launch(void* const* d_in, const int* in_sizes, int n_in,
                              void* d_out, int out_size) {
    const int*   idx  = (const int*)  d_in[0];
    const float* tok  = (const float*)d_in[1];
    const float* pos  = (const float*)d_in[2];
    const float* Wq   = (const float*)d_in[3];
    const float* Wk   = (const float*)d_in[4];
    const float* Wv   = (const float*)d_in[5];
    const float* Wp   = (const float*)d_in[6];
    const float* bp   = (const float*)d_in[7];
    const float* g1   = (const float*)d_in[8];
    const float* b1   = (const float*)d_in[9];
    const float* g2   = (const float*)d_in[10];
    const float* b2   = (const float*)d_in[11];
    const float* W1   = (const float*)d_in[12];
    const float* bf1  = (const float*)d_in[13];
    const float* W2   = (const float*)d_in[14];
    const float* bf2  = (const float*)d_in[15];
    const float* gf   = (const float*)d_in[16];
    const float* bff  = (const float*)d_in[17];
    const float* Wlm  = (const float*)d_in[18];
    const float* blm  = (const float*)d_in[19];
    float* out = (float*)d_out;

    float *x, *h, *q, *k, *v, *o, *ff;
    cudaGetSymbolAddress((void**)&x,  g_x);
    cudaGetSymbolAddress((void**)&h,  g_h);
    cudaGetSymbolAddress((void**)&q,  g_q);
    cudaGetSymbolAddress((void**)&k,  g_k);
    cudaGetSymbolAddress((void**)&v,  g_v);
    cudaGetSymbolAddress((void**)&o,  g_o);
    cudaGetSymbolAddress((void**)&ff, g_ff);

    cudaFuncSetAttribute(k_tgemm<false,false,false>,
                         cudaFuncAttributeMaxDynamicSharedMemorySize, TG_SMEM);
    cudaFuncSetAttribute(k_tgemm<true,false,true>,
                         cudaFuncAttributeMaxDynamicSharedMemorySize, TG_SMEM);
    cudaFuncSetAttribute(k_tgemm<true,true,false>,
                         cudaFuncAttributeMaxDynamicSharedMemorySize, TG_SMEM);
    cudaFuncSetAttribute(k_tgemm<true,false,false>,
                         cudaFuncAttributeMaxDynamicSharedMemorySize, TG_SMEM);

    k_embed<<<RR, 256>>>(idx, tok, pos, x);

    dim3 gEE(EE / 128, RR / 128);      // (8, 16)
    dim3 gFF(FF / 128, RR / 128);      // (32, 16)
    dim3 gLM(VV / 128, RR / 128);      // (250, 16)

    for (int l = 0; l < LL; l++) {
        const float* wq = Wq + (size_t)l * EE * EE;
        const float* wk = Wk + (size_t)l * EE * EE;
        const float* wv = Wv + (size_t)l * EE * EE;
        const float* wp = Wp + (size_t)l * EE * EE;
        const float* w1 = W1 + (size_t)l * EE * FF;
        const float* w2 = W2 + (size_t)l * FF * EE;

        k_ln<<<RR, 256>>>(x, g1 + l * EE, b1 + l * EE, h);
        k_tgemm<false,false,false><<<gEE, 256, TG_SMEM>>>(h, wq, nullptr, nullptr, q, RR, EE, EE);
        k_tgemm<false,false,false><<<gEE, 256, TG_SMEM>>>(h, wk, nullptr, nullptr, k, RR, EE, EE);
        k_tgemm<false,false,false><<<gEE, 256, TG_SMEM>>>(h, wv, nullptr, nullptr, v, RR, EE, EE);

        k_scores<<<dim3(16, 16, 32), 256>>>(q, k);
        k_softmax<<<BB * HH * TT, 256>>>();
        k_av<<<dim3(16, 32), 256>>>(v, o);

        // x = x + o @ Wp + bp
        k_tgemm<true,false,true><<<gEE, 256, TG_SMEM>>>(o, wp, bp + l * EE, x, x, RR, EE, EE);

        k_ln<<<RR, 256>>>(x, g2 + l * EE, b2 + l * EE, h);
        // ff = relu(h @ W1 + bf1)
        k_tgemm<true,true,false><<<gFF, 256, TG_SMEM>>>(h, w1, bf1 + l * FF, nullptr, ff, RR, FF, EE);
        // x = x + ff @ W2 + bf2
        k_tgemm<true,false,true><<<gEE, 256, TG_SMEM>>>(ff, w2, bf2 + l * EE, x, x, RR, EE, FF);
    }

    k_ln<<<RR, 256>>>(x, gf, bff, h);
    k_tgemm<true,false,false><<<gLM, 256, TG_SMEM>>>(h, Wlm, blm, nullptr, out, RR, VV, EE);
}

// round 6
// speedup vs baseline: 1.7351x; 1.0701x over previous
#include <cuda_runtime.h>
#include <cstdint>

// ---------------- problem constants ----------------
#define BB 2
#define TT 1024
#define EE 1024
#define HH 16
#define DD 64
#define LL 6
#define FF 4096
#define VV 32000
#define RR (BB*TT)   // 2048 token rows

// ---------------- device scratch (static, no allocations) ----------------
__device__ float g_x [RR*EE];
__device__ float g_h [RR*EE];
__device__ float g_q [RR*EE];
__device__ float g_k [RR*EE];
__device__ float g_v [RR*EE];
__device__ float g_o [RR*EE];
__device__ float g_ff[RR*FF];
__device__ float g_S [(size_t)BB*HH*TT*TT];   // 134 MB attention scores

__device__ __forceinline__ uint32_t smem_u32(const void* p) {
    uint32_t a;
    asm("{ .reg .u64 t; cvta.to.shared.u64 t, %1; cvt.u32.u64 %0, t; }"
        : "=r"(a) : "l"(p));
    return a;
}

#define SW128(o) ((o) ^ (((o) >> 3) & 0x70))

__device__ __forceinline__ void ldsm_x4(uint32_t& r0, uint32_t& r1,
                                        uint32_t& r2, uint32_t& r3, uint32_t addr) {
    asm volatile("ldmatrix.sync.aligned.m8n8.x4.shared.b16 {%0,%1,%2,%3}, [%4];"
                 : "=r"(r0), "=r"(r1), "=r"(r2), "=r"(r3) : "r"(addr));
}

__device__ __forceinline__ void mma_tf32(float& c0, float& c1, float& c2, float& c3,
                                         uint32_t a0, uint32_t a1, uint32_t a2, uint32_t a3,
                                         uint32_t b0, uint32_t b1) {
    asm volatile("mma.sync.aligned.m16n8k8.row.col.f32.tf32.tf32.f32 "
                 "{%0,%1,%2,%3}, {%4,%5,%6,%7}, {%8,%9}, {%0,%1,%2,%3};"
                 : "+f"(c0), "+f"(c1), "+f"(c2), "+f"(c3)
                 : "r"(a0), "r"(a1), "r"(a2), "r"(a3), "r"(b0), "r"(b1));
}

// split fp32 into hi/lo tf32 pair: x ~= hi + lo, each exactly representable in tf32
__device__ __forceinline__ void split_tf32(float xf, uint32_t& hi, uint32_t& lo) {
    uint32_t h;
    asm("cvt.rna.tf32.f32 %0, %1;" : "=r"(h) : "f"(xf));
    float rf = xf - __uint_as_float(h);
    uint32_t l;
    asm("cvt.rna.tf32.f32 %0, %1;" : "=r"(l) : "f"(rf));
    hi = h; lo = l;
}

__device__ __forceinline__ void split4(float4 v, uint4& hi, uint4& lo) {
    split_tf32(v.x, hi.x, lo.x);
    split_tf32(v.y, hi.y, lo.y);
    split_tf32(v.z, hi.z, lo.z);
    split_tf32(v.w, hi.w, lo.w);
}

// ================= 3xTF32 tensor-core GEMM, pre-split hi/lo tiles =================
// C[M,N] = A[M,K] @ B[K,N] (+bias)(+resid)(relu). 128x128 CTA tile, BK=32.
// grid = (N/128, M/128), 512 threads (16 warps, 4x4 grid of 32x32 warp tiles).
// SMEM per buffer: Ah,Al,Bh,Bl each 16KB (128 rows x 32 fp32 K-major SW128).
// Double buffered: 128KB total.
#define TG_SMEM 131072

template<bool BIAS, bool RELU, bool RESID>
__global__ void __launch_bounds__(512, 1)
k_tgemm(const float* __restrict__ A, const float* __restrict__ B,
        const float* __restrict__ bias, const float* __restrict__ resid,
        float* __restrict__ C, int M, int N, int K) {
    extern __shared__ char smem[];
    const uint32_t sb = smem_u32(smem);
    const int tid = threadIdx.x, lane = tid & 31, wid = tid >> 5;
    const int wm = wid & 3, wn = wid >> 2;           // 4 x 4 warp grid
    const int rowBase = blockIdx.y * 128;
    const int colBase = blockIdx.x * 128;

    float acc[2][4][4];
    #pragma unroll
    for (int i = 0; i < 2; i++)
        #pragma unroll
        for (int j = 0; j < 4; j++)
            #pragma unroll
            for (int r = 0; r < 4; r++) acc[i][j][r] = 0.f;

    // ---- per-thread global-load indexing (2 float4 each for A and B) ----
    // A: position idx = tid + 512*i -> (m = idx>>3, kq = idx&7)
    // B: position idx -> (n = idx&127, q = idx>>7), kq = q ^ swz(n)
    const int b_n = tid & 127;
    const int b_swz = (b_n >> 3) & 7;

    // ---- per-thread ldmatrix addressing (same fragment layout as validated) ----
    const int a_m_in = (lane & 7) + ((lane >> 3) & 1) * 8;
    const int a_kb   = ((lane >> 4) & 1) * 16;
    const int b_n_in = (lane & 7) + ((lane >> 4) & 1) * 8;
    const int b_kb   = ((lane >> 3) & 1) * 16;

    const int nchunk = K >> 5;
    float4 pa[2], pb[2];

    // ---- load + split + store chunk 0 into buffer 0 ----
    {
        #pragma unroll
        for (int i = 0; i < 2; i++) {
            int idx = tid + 512 * i;
            int m = idx >> 3, kq = idx & 7;
            pa[i] = *(const float4*)(A + (size_t)(rowBase + m) * K + kq * 4);
        }
        #pragma unroll
        for (int i = 0; i < 2; i++) {
            int idx = tid + 512 * i;
            int kq = (idx >> 7) ^ b_swz;
            const float* bp = B + (size_t)(kq * 4) * N + colBase + b_n;
            pb[i] = make_float4(bp[0], bp[(size_t)N], bp[(size_t)2 * N], bp[(size_t)3 * N]);
        }
        #pragma unroll
        for (int i = 0; i < 2; i++) {
            int idx = tid + 512 * i;
            int m = idx >> 3, kq = idx & 7;
            uint32_t off = SW128((uint32_t)(m * 128 + kq * 16));
            uint4 hi, lo;
            split4(pa[i], hi, lo);
            *(uint4*)(smem + off)         = hi;   // Ah @ 0
            *(uint4*)(smem + 16384 + off) = lo;   // Al @ 16K
        }
        #pragma unroll
        for (int i = 0; i < 2; i++) {
            int idx = tid + 512 * i;
            int kq = (idx >> 7) ^ b_swz;
            uint32_t off = SW128((uint32_t)(b_n * 128 + kq * 16));
            uint4 hi, lo;
            split4(pb[i], hi, lo);
            *(uint4*)(smem + 32768 + off) = hi;   // Bh @ 32K
            *(uint4*)(smem + 49152 + off) = lo;   // Bl @ 48K
        }
    }
    __syncthreads();

    for (int c = 0; c < nchunk; c++) {
        const uint32_t base = sb + (uint32_t)(c & 1) * 65536;
        const uint32_t ah = base, al = base + 16384;
        const uint32_t bh = base + 32768, bl = base + 49152;

        // ---- prefetch next chunk into registers ----
        if (c + 1 < nchunk) {
            int k0 = (c + 1) << 5;
            #pragma unroll
            for (int i = 0; i < 2; i++) {
                int idx = tid + 512 * i;
                int m = idx >> 3, kq = idx & 7;
                pa[i] = *(const float4*)(A + (size_t)(rowBase + m) * K + k0 + kq * 4);
            }
            #pragma unroll
            for (int i = 0; i < 2; i++) {
                int idx = tid + 512 * i;
                int kq = (idx >> 7) ^ b_swz;
                const float* bp = B + (size_t)(k0 + kq * 4) * N + colBase + b_n;
                pb[i] = make_float4(bp[0], bp[(size_t)N], bp[(size_t)2 * N], bp[(size_t)3 * N]);
            }
        }

        // ---- compute: 4 k-steps of m16n8k8, 3xTF32, pure ldsm+mma ----
        #pragma unroll
        for (int kt = 0; kt < 4; kt++) {
            const int kb_a = kt * 32 + a_kb;
            const int kb_b = kt * 32 + b_kb;
            uint32_t afh[2][4], afl[2][4], bfh[2][4], bfl[2][4];
            #pragma unroll
            for (int mt = 0; mt < 2; mt++) {
                int row = wm * 32 + mt * 16 + a_m_in;
                uint32_t off = (uint32_t)(row * 128 + (kb_a ^ ((row & 7) << 4)));
                ldsm_x4(afh[mt][0], afh[mt][1], afh[mt][2], afh[mt][3], ah + off);
                ldsm_x4(afl[mt][0], afl[mt][1], afl[mt][2], afl[mt][3], al + off);
            }
            #pragma unroll
            for (int ntp = 0; ntp < 2; ntp++) {
                int row = wn * 32 + ntp * 16 + b_n_in;
                uint32_t off = (uint32_t)(row * 128 + (kb_b ^ ((row & 7) << 4)));
                ldsm_x4(bfh[ntp][0], bfh[ntp][1], bfh[ntp][2], bfh[ntp][3], bh + off);
                ldsm_x4(bfl[ntp][0], bfl[ntp][1], bfl[ntp][2], bfl[ntp][3], bl + off);
            }
            #pragma unroll
            for (int mt = 0; mt < 2; mt++)
                #pragma unroll
                for (int nt = 0; nt < 4; nt++) {
                    const int np = nt >> 1, ne = (nt & 1) * 2;
                    mma_tf32(acc[mt][nt][0], acc[mt][nt][1], acc[mt][nt][2], acc[mt][nt][3],
                             afl[mt][0], afl[mt][1], afl[mt][2], afl[mt][3],
                             bfh[np][ne], bfh[np][ne + 1]);
                    mma_tf32(acc[mt][nt][0], acc[mt][nt][1], acc[mt][nt][2], acc[mt][nt][3],
                             afh[mt][0], afh[mt][1], afh[mt][2], afh[mt][3],
                             bfl[np][ne], bfl[np][ne + 1]);
                    mma_tf32(acc[mt][nt][0], acc[mt][nt][1], acc[mt][nt][2], acc[mt][nt][3],
                             afh[mt][0], afh[mt][1], afh[mt][2], afh[mt][3],
                             bfh[np][ne], bfh[np][ne + 1]);
                }
        }

        // ---- split + store prefetched regs into the other buffer ----
        if (c + 1 < nchunk) {
            char* nb = smem + ((c + 1) & 1) * 65536;
            #pragma unroll
            for (int i = 0; i < 2; i++) {
                int idx = tid + 512 * i;
                int m = idx >> 3, kq = idx & 7;
                uint32_t off = SW128((uint32_t)(m * 128 + kq * 16));
                uint4 hi, lo;
                split4(pa[i], hi, lo);
                *(uint4*)(nb + off)         = hi;
                *(uint4*)(nb + 16384 + off) = lo;
            }
            #pragma unroll
            for (int i = 0; i < 2; i++) {
                int idx = tid + 512 * i;
                int kq = (idx >> 7) ^ b_swz;
                uint32_t off = SW128((uint32_t)(b_n * 128 + kq * 16));
                uint4 hi, lo;
                split4(pb[i], hi, lo);
                *(uint4*)(nb + 32768 + off) = hi;
                *(uint4*)(nb + 49152 + off) = lo;
            }
            __syncthreads();
        }
    }

    // ---- epilogue ----
    const int row0 = lane >> 2, col0 = (lane & 3) * 2;
    #pragma unroll
    for (int mt = 0; mt < 2; mt++) {
        #pragma unroll
        for (int nt = 0; nt < 4; nt++) {
            int gm = rowBase + wm * 32 + mt * 16 + row0;
            int gn = colBase + wn * 32 + nt * 8 + col0;
            float o0 = acc[mt][nt][0], o1 = acc[mt][nt][1];
            float o2 = acc[mt][nt][2], o3 = acc[mt][nt][3];
            if (BIAS) {
                float bv0 = bias[gn], bv1 = bias[gn + 1];
                o0 += bv0; o1 += bv1; o2 += bv0; o3 += bv1;
            }
            size_t p0 = (size_t)gm * N + gn;
            size_t p1 = (size_t)(gm + 8) * N + gn;
            if (RESID) {
                float2 r0v = *(const float2*)(resid + p0);
                float2 r1v = *(const float2*)(resid + p1);
                o0 += r0v.x; o1 += r0v.y; o2 += r1v.x; o3 += r1v.y;
            }
            if (RELU) {
                o0 = fmaxf(o0, 0.f); o1 = fmaxf(o1, 0.f);
                o2 = fmaxf(o2, 0.f); o3 = fmaxf(o3, 0.f);
            }
            *(float2*)(C + p0) = make_float2(o0, o1);
            *(float2*)(C + p1) = make_float2(o2, o3);
        }
    }
}

// ---------------- embed: x = tok_emb[idx] + pos_emb ----------------
__global__ void k_embed(const int* __restrict__ idx, const float* __restrict__ tok,
                        const float* __restrict__ pos, float* __restrict__ x) {
    int r = blockIdx.x;
    int t = r & (TT - 1);
    int tokid = idx[r];
    const float4* te = (const float4*)(tok + (size_t)tokid * EE);
    const float4* pe = (const float4*)(pos + (size_t)t * EE);
    float4* xr = (float4*)(x + (size_t)r * EE);
    int c = threadIdx.x;
    float4 a = te[c], b = pe[c];
    xr[c] = make_float4(a.x + b.x, a.y + b.y, a.z + b.z, a.w + b.w);
}

// ---------------- block reduce helper ----------------
__device__ __forceinline__ float blockReduceSum(float val, float* red) {
    int tid = threadIdx.x;
    #pragma unroll
    for (int o = 16; o; o >>= 1) val += __shfl_xor_sync(0xffffffffu, val, o);
    if ((tid & 31) == 0) red[tid >> 5] = val;
    __syncthreads();
    if (tid < 32) {
        float v = (tid < 8) ? red[tid] : 0.f;
        #pragma unroll
        for (int o = 4; o; o >>= 1) v += __shfl_xor_sync(0xffffffffu, v, o);
        if (tid == 0) red[0] = v;
    }
    __syncthreads();
    float r = red[0];
    __syncthreads();
    return r;
}

// ---------------- layernorm ----------------
__global__ void k_ln(const float* __restrict__ x, const float* __restrict__ g,
                     const float* __restrict__ b, float* __restrict__ out) {
    __shared__ float red[32];
    int row = blockIdx.x, tid = threadIdx.x;
    const float* xr = x + (size_t)row * EE;
    float v[4];
    float s = 0.f;
    #pragma unroll
    for (int i = 0; i < 4; i++) { v[i] = xr[tid + 256 * i]; s += v[i]; }
    s = blockReduceSum(s, red);
    float mean = s * (1.f / EE);
    float s2 = 0.f;
    #pragma unroll
    for (int i = 0; i < 4; i++) { float d = v[i] - mean; s2 += d * d; }
    s2 = blockReduceSum(s2, red);
    float inv = rsqrtf(s2 * (1.f / EE) + 1e-5f);
    #pragma unroll
    for (int i = 0; i < 4; i++) {
        int c = tid + 256 * i;
        out[(size_t)row * EE + c] = (v[i] - mean) * inv * g[c] + b[c];
    }
}

// ---------------- attention scores ----------------
__global__ void k_scores(const float* __restrict__ q, const float* __restrict__ k) {
    int bh = blockIdx.z, b = bh >> 4, h = bh & 15;
    int q0 = blockIdx.y * 64, k0 = blockIdx.x * 64;
    int tid = threadIdx.x;
    size_t base = ((size_t)bh * TT + q0) * TT + k0;
    if (k0 > q0 + 63) {
        for (int i = tid; i < 64 * 64; i += 256)
            g_S[base + (size_t)(i >> 6) * TT + (i & 63)] = -1e30f;
        return;
    }
    __shared__ float Qs[64][65];
    __shared__ float Ks[64][65];
    for (int i = tid; i < 64 * 64; i += 256) {
        int rr = i >> 6, cc = i & 63;
        Qs[rr][cc] = q[(size_t)(b * TT + q0 + rr) * EE + h * DD + cc];
        Ks[rr][cc] = k[(size_t)(b * TT + k0 + rr) * EE + h * DD + cc];
    }
    __syncthreads();
    int tx = tid & 15, ty = tid >> 4;
    float acc[4][4];
    #pragma unroll
    for (int i = 0; i < 4; i++)
        #pragma unroll
        for (int j = 0; j < 4; j++) acc[i][j] = 0.f;
    #pragma unroll 8
    for (int d = 0; d < 64; d++) {
        float ra[4], rb[4];
        #pragma unroll
        for (int i = 0; i < 4; i++) ra[i] = Qs[ty * 4 + i][d];
        #pragma unroll
        for (int j = 0; j < 4; j++) rb[j] = Ks[tx * 4 + j][d];
        #pragma unroll
        for (int i = 0; i < 4; i++)
            #pragma unroll
            for (int j = 0; j < 4; j++)
                acc[i][j] = fmaf(ra[i], rb[j], acc[i][j]);
    }
    #pragma unroll
    for (int i = 0; i < 4; i++)
        #pragma unroll
        for (int j = 0; j < 4; j++) {
            int qi = q0 + ty * 4 + i, kj = k0 + tx * 4 + j;
            g_S[((size_t)bh * TT + qi) * TT + kj] =
                (kj <= qi) ? acc[i][j] * 0.125f : -1e30f;
        }
}

// ---------------- softmax per row ----------------
__global__ void k_softmax() {
    __shared__ float red[32];
    size_t row = blockIdx.x;
    float* r = g_S + row * (size_t)TT;
    int tid = threadIdx.x;
    float v[4], m = -1e30f;
    #pragma unroll
    for (int i = 0; i < 4; i++) { v[i] = r[tid + 256 * i]; m = fmaxf(m, v[i]); }
    #pragma unroll
    for (int o = 16; o; o >>= 1) m = fmaxf(m, __shfl_xor_sync(0xffffffffu, m, o));
    if ((tid & 31) == 0) red[tid >> 5] = m;
    __syncthreads();
    if (tid < 32) {
        float t = (tid < 8) ? red[tid] : -1e30f;
        #pragma unroll
        for (int o = 4; o; o >>= 1) t = fmaxf(t, __shfl_xor_sync(0xffffffffu, t, o));
        if (tid == 0) red[0] = t;
    }
    __syncthreads();
    m = red[0];
    __syncthreads();
    float s = 0.f;
    #pragma unroll
    for (int i = 0; i < 4; i++) { v[i] = __expf(v[i] - m); s += v[i]; }
    s = blockReduceSum(s, red);
    float inv = 1.f / s;
    #pragma unroll
    for (int i = 0; i < 4; i++) r[tid + 256 * i] = v[i] * inv;
}

// ---------------- O = softmax(S) @ V ----------------
__global__ void k_av(const float* __restrict__ v, float* __restrict__ o) {
    int bh = blockIdx.y, b = bh >> 4, h = bh & 15;
    int q0 = blockIdx.x * 64;
    __shared__ float Ss[64][65];
    __shared__ float Vs[64][65];
    int tid = threadIdx.x, tx = tid & 15, ty = tid >> 4;
    float acc[4][4];
    #pragma unroll
    for (int i = 0; i < 4; i++)
        #pragma unroll
        for (int j = 0; j < 4; j++) acc[i][j] = 0.f;
    int kend = q0 + 64;
    for (int j0 = 0; j0 < kend; j0 += 64) {
        for (int i = tid; i < 64 * 64; i += 256) {
            int rr = i >> 6, cc = i & 63;
            Ss[rr][cc] = g_S[((size_t)bh * TT + q0 + rr) * TT + j0 + cc];
            Vs[rr][cc] = v[(size_t)(b * TT + j0 + rr) * EE + h * DD + cc];
        }
        __syncthreads();
        #pragma unroll 8
        for (int jj = 0; jj < 64; jj++) {
            float ra[4], rb[4];
            #pragma unroll
            for (int i = 0; i < 4; i++) ra[i] = Ss[ty * 4 + i][jj];
            #pragma unroll
            for (int j = 0; j < 4; j++) rb[j] = Vs[jj][tx * 4 + j];
            #pragma unroll
            for (int i = 0; i < 4; i++)
                #pragma unroll
                for (int j = 0; j < 4; j++)
                    acc[i][j] = fmaf(ra[i], rb[j], acc[i][j]);
        }
        __syncthreads();
    }
    #pragma unroll
    for (int i = 0; i < 4; i++)
        #pragma unroll
        for (int j = 0; j < 4; j++)
            o[(size_t)(b * TT + q0 + ty * 4 + i) * EE + h * DD + tx * 4 + j] = acc[i][j];
}

// ---------------- host orchestration ----------------
extern "C" void kernel_launch(void* const* d_in, const int* in_sizes, int n_in,
                              void* d_out, int out_size) {
    const int*   idx  = (const int*)  d_in[0];
    const float* tok  = (const float*)d_in[1];
    const float* pos  = (const float*)d_in[2];
    const float* Wq   = (const float*)d_in[3];
    const float* Wk   = (const float*)d_in[4];
    const float* Wv   = (const float*)d_in[5];
    const float* Wp   = (const float*)d_in[6];
    const float* bp   = (const float*)d_in[7];
    const float* g1   = (const float*)d_in[8];
    const float* b1   = (const float*)d_in[9];
    const float* g2   = (const float*)d_in[10];
    const float* b2   = (const float*)d_in[11];
    const float* W1   = (const float*)d_in[12];
    const float* bf1  = (const float*)d_in[13];
    const float* W2   = (const float*)d_in[14];
    const float* bf2  = (const float*)d_in[15];
    const float* gf   = (const float*)d_in[16];
    const float* bff  = (const float*)d_in[17];
    const float* Wlm  = (const float*)d_in[18];
    const float* blm  = (const float*)d_in[19];
    float* out = (float*)d_out;

    float *x, *h, *q, *k, *v, *o, *ff;
    cudaGetSymbolAddress((void**)&x,  g_x);
    cudaGetSymbolAddress((void**)&h,  g_h);
    cudaGetSymbolAddress((void**)&q,  g_q);
    cudaGetSymbolAddress((void**)&k,  g_k);
    cudaGetSymbolAddress((void**)&v,  g_v);
    cudaGetSymbolAddress((void**)&o,  g_o);
    cudaGetSymbolAddress((void**)&ff, g_ff);

    cudaFuncSetAttribute(k_tgemm<false,false,false>,
                         cudaFuncAttributeMaxDynamicSharedMemorySize, TG_SMEM);
    cudaFuncSetAttribute(k_tgemm<true,false,true>,
                         cudaFuncAttributeMaxDynamicSharedMemorySize, TG_SMEM);
    cudaFuncSetAttribute(k_tgemm<true,true,false>,
                         cudaFuncAttributeMaxDynamicSharedMemorySize, TG_SMEM);
    cudaFuncSetAttribute(k_tgemm<true,false,false>,
                         cudaFuncAttributeMaxDynamicSharedMemorySize, TG_SMEM);

    k_embed<<<RR, 256>>>(idx, tok, pos, x);

    dim3 gEE(EE / 128, RR / 128);      // (8, 16)
    dim3 gFF(FF / 128, RR / 128);      // (32, 16)
    dim3 gLM(VV / 128, RR / 128);      // (250, 16)

    for (int l = 0; l < LL; l++) {
        const float* wq = Wq + (size_t)l * EE * EE;
        const float* wk = Wk + (size_t)l * EE * EE;
        const float* wv = Wv + (size_t)l * EE * EE;
        const float* wp = Wp + (size_t)l * EE * EE;
        const float* w1 = W1 + (size_t)l * EE * FF;
        const float* w2 = W2 + (size_t)l * FF * EE;

        k_ln<<<RR, 256>>>(x, g1 + l * EE, b1 + l * EE, h);
        k_tgemm<false,false,false><<<gEE, 512, TG_SMEM>>>(h, wq, nullptr, nullptr, q, RR, EE, EE);
        k_tgemm<false,false,false><<<gEE, 512, TG_SMEM>>>(h, wk, nullptr, nullptr, k, RR, EE, EE);
        k_tgemm<false,false,false><<<gEE, 512, TG_SMEM>>>(h, wv, nullptr, nullptr, v, RR, EE, EE);

        k_scores<<<dim3(16, 16, 32), 256>>>(q, k);
        k_softmax<<<BB * HH * TT, 256>>>();
        k_av<<<dim3(16, 32), 256>>>(v, o);

        // x = x + o @ Wp + bp
        k_tgemm<true,false,true><<<gEE, 512, TG_SMEM>>>(o, wp, bp + l * EE, x, x, RR, EE, EE);

        k_ln<<<RR, 256>>>(x, g2 + l * EE, b2 + l * EE, h);
        // ff = relu(h @ W1 + bf1)
        k_tgemm<true,true,false><<<gFF, 512, TG_SMEM>>>(h, w1, bf1 + l * FF, nullptr, ff, RR, FF, EE);
        // x = x + ff @ W2 + bf2
        k_tgemm<true,false,true><<<gEE, 512, TG_SMEM>>>(ff, w2, bf2 + l * EE, x, x, RR, EE, FF);
    }

    k_ln<<<RR, 256>>>(x, gf, bff, h);
    k_tgemm<true,false,false><<<gLM, 512, TG_SMEM>>>(h, Wlm, blm, nullptr, out, RR, VV, EE);
}

// round 7
// speedup vs baseline: 2.5545x; 1.4723x over previous
#include <cuda_runtime.h>
#include <cstdint>

// ---------------- problem constants ----------------
#define BB 2
#define TT 1024
#define EE 1024
#define HH 16
#define DD 64
#define LL 6
#define FF 4096
#define VV 32000
#define RR (BB*TT)   // 2048 token rows

// ---------------- device scratch (static, no allocations) ----------------
__device__ float g_x [RR*EE];
__device__ float g_h [RR*EE];
__device__ float g_q [RR*EE];
__device__ float g_k [RR*EE];
__device__ float g_v [RR*EE];
__device__ float g_o [RR*EE];
__device__ float g_ff[RR*FF];
__device__ float g_S [(size_t)BB*HH*TT*TT];   // 134 MB attention scores

__device__ __forceinline__ uint32_t smem_u32(const void* p) {
    uint32_t a;
    asm("{ .reg .u64 t; cvta.to.shared.u64 t, %1; cvt.u32.u64 %0, t; }"
        : "=r"(a) : "l"(p));
    return a;
}

__device__ __forceinline__ void ldsm_x4(uint32_t& r0, uint32_t& r1,
                                        uint32_t& r2, uint32_t& r3, uint32_t addr) {
    asm volatile("ldmatrix.sync.aligned.m8n8.x4.shared.b16 {%0,%1,%2,%3}, [%4];"
                 : "=r"(r0), "=r"(r1), "=r"(r2), "=r"(r3) : "r"(addr));
}

__device__ __forceinline__ void mma_bf16(float& c0, float& c1, float& c2, float& c3,
                                         uint32_t a0, uint32_t a1, uint32_t a2, uint32_t a3,
                                         uint32_t b0, uint32_t b1) {
    asm volatile("mma.sync.aligned.m16n8k16.row.col.f32.bf16.bf16.f32 "
                 "{%0,%1,%2,%3}, {%4,%5,%6,%7}, {%8,%9}, {%0,%1,%2,%3};"
                 : "+f"(c0), "+f"(c1), "+f"(c2), "+f"(c3)
                 : "r"(a0), "r"(a1), "r"(a2), "r"(a3), "r"(b0), "r"(b1));
}

// split two fp32 (k-consecutive x0,x1) into packed bf16x2 hi and lo:
// x ~= hi + lo, each exactly bf16. Packed with x0 in low half (memory order).
__device__ __forceinline__ void split2(float x0, float x1, uint32_t& h, uint32_t& l) {
    uint32_t hh;
    asm("cvt.rn.bf16x2.f32 %0, %1, %2;" : "=r"(hh) : "f"(x1), "f"(x0));
    float h0 = __uint_as_float(hh << 16);
    float h1 = __uint_as_float(hh & 0xFFFF0000u);
    float l0 = x0 - h0, l1 = x1 - h1;
    uint32_t ll;
    asm("cvt.rn.bf16x2.f32 %0, %1, %2;" : "=r"(ll) : "f"(l1), "f"(l0));
    h = hh; l = ll;
}

// ================= 3xBF16 tensor-core GEMM (fp32-accurate) =================
// C[M,N] = A[M,K] @ B[K,N] (+bias)(+resid)(relu). 128x128 CTA tile, BK=32.
// grid = (N/128, M/128), 512 threads (16 warps, 4x4 grid of 32x32 warp tiles).
// SMEM per buffer (32KB): Ah@0, Al@8K, Bh@16K, Bl@24K — each 128 rows x 32 bf16
// (64B rows, swizzle: byte ^ (((row>>1)&3)<<4)). Double buffered: 64KB.
#define TG_SMEM 65536

template<bool BIAS, bool RELU, bool RESID>
__global__ void __launch_bounds__(512, 1)
k_tgemm(const float* __restrict__ A, const float* __restrict__ B,
        const float* __restrict__ bias, const float* __restrict__ resid,
        float* __restrict__ C, int M, int N, int K) {
    extern __shared__ char smem[];
    const uint32_t sb = smem_u32(smem);
    const int tid = threadIdx.x, lane = tid & 31, wid = tid >> 5;
    const int wm = wid & 3, wn = wid >> 2;           // 4 x 4 warp grid
    const int rowBase = blockIdx.y * 128;
    const int colBase = blockIdx.x * 128;

    float acc[2][4][4];
    #pragma unroll
    for (int i = 0; i < 2; i++)
        #pragma unroll
        for (int j = 0; j < 4; j++)
            #pragma unroll
            for (int r = 0; r < 4; r++) acc[i][j][r] = 0.f;

    // ---- per-thread global-load indexing ----
    const int a_m = tid >> 3, a_kq = tid & 7;        // A: float4 at (m + 64i, kq*4)
    const int b_n = tid & 127, b_q = tid >> 7;       // B: col n, k-group (q+4i)^s
    const int b_s = (b_n >> 3) & 7;

    // ---- per-thread ldmatrix addressing ----
    const int a_m_in = (lane & 7) + ((lane >> 3) & 1) * 8;
    const int a_kb   = ((lane >> 4) & 1) * 16;
    const int b_n_in = (lane & 7) + ((lane >> 4) & 1) * 8;
    const int b_kb   = ((lane >> 3) & 1) * 16;

    const int nchunk = K >> 5;
    float4 pa[2], pb[2];

    // ---- load + split + store chunk 0 into buffer 0 ----
    {
        #pragma unroll
        for (int i = 0; i < 2; i++) {
            int m = a_m + 64 * i;
            pa[i] = *(const float4*)(A + (size_t)(rowBase + m) * K + a_kq * 4);
        }
        #pragma unroll
        for (int i = 0; i < 2; i++) {
            int kq = (b_q + 4 * i) ^ b_s;
            const float* bp = B + (size_t)(kq * 4) * N + colBase + b_n;
            pb[i] = make_float4(bp[0], bp[(size_t)N], bp[(size_t)2 * N], bp[(size_t)3 * N]);
        }
        #pragma unroll
        for (int i = 0; i < 2; i++) {
            int m = a_m + 64 * i;
            uint32_t h01, l01, h23, l23;
            split2(pa[i].x, pa[i].y, h01, l01);
            split2(pa[i].z, pa[i].w, h23, l23);
            uint32_t off = (uint32_t)(m * 64 + ((a_kq * 8) ^ (((m >> 1) & 3) << 4)));
            *(uint2*)(smem + off)        = make_uint2(h01, h23);
            *(uint2*)(smem + 8192 + off) = make_uint2(l01, l23);
        }
        #pragma unroll
        for (int i = 0; i < 2; i++) {
            int kq = (b_q + 4 * i) ^ b_s;
            uint32_t h01, l01, h23, l23;
            split2(pb[i].x, pb[i].y, h01, l01);
            split2(pb[i].z, pb[i].w, h23, l23);
            uint32_t off = (uint32_t)(b_n * 64 + ((kq * 8) ^ (((b_n >> 1) & 3) << 4)));
            *(uint2*)(smem + 16384 + off) = make_uint2(h01, h23);
            *(uint2*)(smem + 24576 + off) = make_uint2(l01, l23);
        }
    }
    __syncthreads();

    for (int c = 0; c < nchunk; c++) {
        const uint32_t base = sb + (uint32_t)(c & 1) * 32768;
        const uint32_t ah = base, al = base + 8192;
        const uint32_t bh = base + 16384, bl = base + 24576;

        // ---- prefetch next chunk into registers ----
        if (c + 1 < nchunk) {
            int k0 = (c + 1) << 5;
            #pragma unroll
            for (int i = 0; i < 2; i++) {
                int m = a_m + 64 * i;
                pa[i] = *(const float4*)(A + (size_t)(rowBase + m) * K + k0 + a_kq * 4);
            }
            #pragma unroll
            for (int i = 0; i < 2; i++) {
                int kq = (b_q + 4 * i) ^ b_s;
                const float* bp = B + (size_t)(k0 + kq * 4) * N + colBase + b_n;
                pb[i] = make_float4(bp[0], bp[(size_t)N], bp[(size_t)2 * N], bp[(size_t)3 * N]);
            }
        }

        // ---- compute: 2 k-steps of m16n8k16, 3xBF16 each ----
        #pragma unroll
        for (int kt = 0; kt < 2; kt++) {
            uint32_t afh[2][4], afl[2][4], bfh[2][4], bfl[2][4];
            #pragma unroll
            for (int mt = 0; mt < 2; mt++) {
                int row = wm * 32 + mt * 16 + a_m_in;
                uint32_t off = (uint32_t)(row * 64 + ((kt * 32 + a_kb) ^ (((row >> 1) & 3) << 4)));
                ldsm_x4(afh[mt][0], afh[mt][1], afh[mt][2], afh[mt][3], ah + off);
                ldsm_x4(afl[mt][0], afl[mt][1], afl[mt][2], afl[mt][3], al + off);
            }
            #pragma unroll
            for (int ntp = 0; ntp < 2; ntp++) {
                int row = wn * 32 + ntp * 16 + b_n_in;
                uint32_t off = (uint32_t)(row * 64 + ((kt * 32 + b_kb) ^ (((row >> 1) & 3) << 4)));
                ldsm_x4(bfh[ntp][0], bfh[ntp][1], bfh[ntp][2], bfh[ntp][3], bh + off);
                ldsm_x4(bfl[ntp][0], bfl[ntp][1], bfl[ntp][2], bfl[ntp][3], bl + off);
            }
            #pragma unroll
            for (int mt = 0; mt < 2; mt++)
                #pragma unroll
                for (int nt = 0; nt < 4; nt++) {
                    const int np = nt >> 1, ne = (nt & 1) * 2;
                    mma_bf16(acc[mt][nt][0], acc[mt][nt][1], acc[mt][nt][2], acc[mt][nt][3],
                             afh[mt][0], afh[mt][1], afh[mt][2], afh[mt][3],
                             bfh[np][ne], bfh[np][ne + 1]);
                    mma_bf16(acc[mt][nt][0], acc[mt][nt][1], acc[mt][nt][2], acc[mt][nt][3],
                             afh[mt][0], afh[mt][1], afh[mt][2], afh[mt][3],
                             bfl[np][ne], bfl[np][ne + 1]);
                    mma_bf16(acc[mt][nt][0], acc[mt][nt][1], acc[mt][nt][2], acc[mt][nt][3],
                             afl[mt][0], afl[mt][1], afl[mt][2], afl[mt][3],
                             bfh[np][ne], bfh[np][ne + 1]);
                }
        }

        // ---- split + store prefetched regs into the other buffer ----
        if (c + 1 < nchunk) {
            char* nb = smem + ((c + 1) & 1) * 32768;
            __syncthreads();
            #pragma unroll
            for (int i = 0; i < 2; i++) {
                int m = a_m + 64 * i;
                uint32_t h01, l01, h23, l23;
                split2(pa[i].x, pa[i].y, h01, l01);
                split2(pa[i].z, pa[i].w, h23, l23);
                uint32_t off = (uint32_t)(m * 64 + ((a_kq * 8) ^ (((m >> 1) & 3) << 4)));
                *(uint2*)(nb + off)        = make_uint2(h01, h23);
                *(uint2*)(nb + 8192 + off) = make_uint2(l01, l23);
            }
            #pragma unroll
            for (int i = 0; i < 2; i++) {
                int kq = (b_q + 4 * i) ^ b_s;
                uint32_t h01, l01, h23, l23;
                split2(pb[i].x, pb[i].y, h01, l01);
                split2(pb[i].z, pb[i].w, h23, l23);
                uint32_t off = (uint32_t)(b_n * 64 + ((kq * 8) ^ (((b_n >> 1) & 3) << 4)));
                *(uint2*)(nb + 16384 + off) = make_uint2(h01, h23);
                *(uint2*)(nb + 24576 + off) = make_uint2(l01, l23);
            }
            __syncthreads();
        }
    }

    // ---- epilogue ----
    const int row0 = lane >> 2, col0 = (lane & 3) * 2;
    #pragma unroll
    for (int mt = 0; mt < 2; mt++) {
        #pragma unroll
        for (int nt = 0; nt < 4; nt++) {
            int gm = rowBase + wm * 32 + mt * 16 + row0;
            int gn = colBase + wn * 32 + nt * 8 + col0;
            float o0 = acc[mt][nt][0], o1 = acc[mt][nt][1];
            float o2 = acc[mt][nt][2], o3 = acc[mt][nt][3];
            if (BIAS) {
                float bv0 = bias[gn], bv1 = bias[gn + 1];
                o0 += bv0; o1 += bv1; o2 += bv0; o3 += bv1;
            }
            size_t p0 = (size_t)gm * N + gn;
            size_t p1 = (size_t)(gm + 8) * N + gn;
            if (RESID) {
                float2 r0v = *(const float2*)(resid + p0);
                float2 r1v = *(const float2*)(resid + p1);
                o0 += r0v.x; o1 += r0v.y; o2 += r1v.x; o3 += r1v.y;
            }
            if (RELU) {
                o0 = fmaxf(o0, 0.f); o1 = fmaxf(o1, 0.f);
                o2 = fmaxf(o2, 0.f); o3 = fmaxf(o3, 0.f);
            }
            *(float2*)(C + p0) = make_float2(o0, o1);
            *(float2*)(C + p1) = make_float2(o2, o3);
        }
    }
}

// ---------------- embed: x = tok_emb[idx] + pos_emb ----------------
__global__ void k_embed(const int* __restrict__ idx, const float* __restrict__ tok,
                        const float* __restrict__ pos, float* __restrict__ x) {
    int r = blockIdx.x;
    int t = r & (TT - 1);
    int tokid = idx[r];
    const float4* te = (const float4*)(tok + (size_t)tokid * EE);
    const float4* pe = (const float4*)(pos + (size_t)t * EE);
    float4* xr = (float4*)(x + (size_t)r * EE);
    int c = threadIdx.x;
    float4 a = te[c], b = pe[c];
    xr[c] = make_float4(a.x + b.x, a.y + b.y, a.z + b.z, a.w + b.w);
}

// ---------------- block reduce helper ----------------
__device__ __forceinline__ float blockReduceSum(float val, float* red) {
    int tid = threadIdx.x;
    #pragma unroll
    for (int o = 16; o; o >>= 1) val += __shfl_xor_sync(0xffffffffu, val, o);
    if ((tid & 31) == 0) red[tid >> 5] = val;
    __syncthreads();
    if (tid < 32) {
        float v = (tid < 8) ? red[tid] : 0.f;
        #pragma unroll
        for (int o = 4; o; o >>= 1) v += __shfl_xor_sync(0xffffffffu, v, o);
        if (tid == 0) red[0] = v;
    }
    __syncthreads();
    float r = red[0];
    __syncthreads();
    return r;
}

// ---------------- layernorm ----------------
__global__ void k_ln(const float* __restrict__ x, const float* __restrict__ g,
                     const float* __restrict__ b, float* __restrict__ out) {
    __shared__ float red[32];
    int row = blockIdx.x, tid = threadIdx.x;
    const float* xr = x + (size_t)row * EE;
    float v[4];
    float s = 0.f;
    #pragma unroll
    for (int i = 0; i < 4; i++) { v[i] = xr[tid + 256 * i]; s += v[i]; }
    s = blockReduceSum(s, red);
    float mean = s * (1.f / EE);
    float s2 = 0.f;
    #pragma unroll
    for (int i = 0; i < 4; i++) { float d = v[i] - mean; s2 += d * d; }
    s2 = blockReduceSum(s2, red);
    float inv = rsqrtf(s2 * (1.f / EE) + 1e-5f);
    #pragma unroll
    for (int i = 0; i < 4; i++) {
        int c = tid + 256 * i;
        out[(size_t)row * EE + c] = (v[i] - mean) * inv * g[c] + b[c];
    }
}

// ---------------- attention scores ----------------
__global__ void k_scores(const float* __restrict__ q, const float* __restrict__ k) {
    int bh = blockIdx.z, b = bh >> 4, h = bh & 15;
    int q0 = blockIdx.y * 64, k0 = blockIdx.x * 64;
    int tid = threadIdx.x;
    size_t base = ((size_t)bh * TT + q0) * TT + k0;
    if (k0 > q0 + 63) {
        for (int i = tid; i < 64 * 64; i += 256)
            g_S[base + (size_t)(i >> 6) * TT + (i & 63)] = -1e30f;
        return;
    }
    __shared__ float Qs[64][65];
    __shared__ float Ks[64][65];
    for (int i = tid; i < 64 * 64; i += 256) {
        int rr = i >> 6, cc = i & 63;
        Qs[rr][cc] = q[(size_t)(b * TT + q0 + rr) * EE + h * DD + cc];
        Ks[rr][cc] = k[(size_t)(b * TT + k0 + rr) * EE + h * DD + cc];
    }
    __syncthreads();
    int tx = tid & 15, ty = tid >> 4;
    float acc[4][4];
    #pragma unroll
    for (int i = 0; i < 4; i++)
        #pragma unroll
        for (int j = 0; j < 4; j++) acc[i][j] = 0.f;
    #pragma unroll 8
    for (int d = 0; d < 64; d++) {
        float ra[4], rb[4];
        #pragma unroll
        for (int i = 0; i < 4; i++) ra[i] = Qs[ty * 4 + i][d];
        #pragma unroll
        for (int j = 0; j < 4; j++) rb[j] = Ks[tx * 4 + j][d];
        #pragma unroll
        for (int i = 0; i < 4; i++)
            #pragma unroll
            for (int j = 0; j < 4; j++)
                acc[i][j] = fmaf(ra[i], rb[j], acc[i][j]);
    }
    #pragma unroll
    for (int i = 0; i < 4; i++)
        #pragma unroll
        for (int j = 0; j < 4; j++) {
            int qi = q0 + ty * 4 + i, kj = k0 + tx * 4 + j;
            g_S[((size_t)bh * TT + qi) * TT + kj] =
                (kj <= qi) ? acc[i][j] * 0.125f : -1e30f;
        }
}

// ---------------- softmax per row ----------------
__global__ void k_softmax() {
    __shared__ float red[32];
    size_t row = blockIdx.x;
    float* r = g_S + row * (size_t)TT;
    int tid = threadIdx.x;
    float v[4], m = -1e30f;
    #pragma unroll
    for (int i = 0; i < 4; i++) { v[i] = r[tid + 256 * i]; m = fmaxf(m, v[i]); }
    #pragma unroll
    for (int o = 16; o; o >>= 1) m = fmaxf(m, __shfl_xor_sync(0xffffffffu, m, o));
    if ((tid & 31) == 0) red[tid >> 5] = m;
    __syncthreads();
    if (tid < 32) {
        float t = (tid < 8) ? red[tid] : -1e30f;
        #pragma unroll
        for (int o = 4; o; o >>= 1) t = fmaxf(t, __shfl_xor_sync(0xffffffffu, t, o));
        if (tid == 0) red[0] = t;
    }
    __syncthreads();
    m = red[0];
    __syncthreads();
    float s = 0.f;
    #pragma unroll
    for (int i = 0; i < 4; i++) { v[i] = __expf(v[i] - m); s += v[i]; }
    s = blockReduceSum(s, red);
    float inv = 1.f / s;
    #pragma unroll
    for (int i = 0; i < 4; i++) r[tid + 256 * i] = v[i] * inv;
}

// ---------------- O = softmax(S) @ V ----------------
__global__ void k_av(const float* __restrict__ v, float* __restrict__ o) {
    int bh = blockIdx.y, b = bh >> 4, h = bh & 15;
    int q0 = blockIdx.x * 64;
    __shared__ float Ss[64][65];
    __shared__ float Vs[64][65];
    int tid = threadIdx.x, tx = tid & 15, ty = tid >> 4;
    float acc[4][4];
    #pragma unroll
    for (int i = 0; i < 4; i++)
        #pragma unroll
        for (int j = 0; j < 4; j++) acc[i][j] = 0.f;
    int kend = q0 + 64;
    for (int j0 = 0; j0 < kend; j0 += 64) {
        for (int i = tid; i < 64 * 64; i += 256) {
            int rr = i >> 6, cc = i & 63;
            Ss[rr][cc] = g_S[((size_t)bh * TT + q0 + rr) * TT + j0 + cc];
            Vs[rr][cc] = v[(size_t)(b * TT + j0 + rr) * EE + h * DD + cc];
        }
        __syncthreads();
        #pragma unroll 8
        for (int jj = 0; jj < 64; jj++) {
            float ra[4], rb[4];
            #pragma unroll
            for (int i = 0; i < 4; i++) ra[i] = Ss[ty * 4 + i][jj];
            #pragma unroll
            for (int j = 0; j < 4; j++) rb[j] = Vs[jj][tx * 4 + j];
            #pragma unroll
            for (int i = 0; i < 4; i++)
                #pragma unroll
                for (int j = 0; j < 4; j++)
                    acc[i][j] = fmaf(ra[i], rb[j], acc[i][j]);
        }
        __syncthreads();
    }
    #pragma unroll
    for (int i = 0; i < 4; i++)
        #pragma unroll
        for (int j = 0; j < 4; j++)
            o[(size_t)(b * TT + q0 + ty * 4 + i) * EE + h * DD + tx * 4 + j] = acc[i][j];
}

// ---------------- host orchestration ----------------
extern "C" void kernel_launch(void* const* d_in, const int* in_sizes, int n_in,
                              void* d_out, int out_size) {
    const int*   idx  = (const int*)  d_in[0];
    const float* tok  = (const float*)d_in[1];
    const float* pos  = (const float*)d_in[2];
    const float* Wq   = (const float*)d_in[3];
    const float* Wk   = (const float*)d_in[4];
    const float* Wv   = (const float*)d_in[5];
    const float* Wp   = (const float*)d_in[6];
    const float* bp   = (const float*)d_in[7];
    const float* g1   = (const float*)d_in[8];
    const float* b1   = (const float*)d_in[9];
    const float* g2   = (const float*)d_in[10];
    const float* b2   = (const float*)d_in[11];
    const float* W1   = (const float*)d_in[12];
    const float* bf1  = (const float*)d_in[13];
    const float* W2   = (const float*)d_in[14];
    const float* bf2  = (const float*)d_in[15];
    const float* gf   = (const float*)d_in[16];
    const float* bff  = (const float*)d_in[17];
    const float* Wlm  = (const float*)d_in[18];
    const float* blm  = (const float*)d_in[19];
    float* out = (float*)d_out;

    float *x, *h, *q, *k, *v, *o, *ff;
    cudaGetSymbolAddress((void**)&x,  g_x);
    cudaGetSymbolAddress((void**)&h,  g_h);
    cudaGetSymbolAddress((void**)&q,  g_q);
    cudaGetSymbolAddress((void**)&k,  g_k);
    cudaGetSymbolAddress((void**)&v,  g_v);
    cudaGetSymbolAddress((void**)&o,  g_o);
    cudaGetSymbolAddress((void**)&ff, g_ff);

    cudaFuncSetAttribute(k_tgemm<false,false,false>,
                         cudaFuncAttributeMaxDynamicSharedMemorySize, TG_SMEM);
    cudaFuncSetAttribute(k_tgemm<true,false,true>,
                         cudaFuncAttributeMaxDynamicSharedMemorySize, TG_SMEM);
    cudaFuncSetAttribute(k_tgemm<true,true,false>,
                         cudaFuncAttributeMaxDynamicSharedMemorySize, TG_SMEM);
    cudaFuncSetAttribute(k_tgemm<true,false,false>,
                         cudaFuncAttributeMaxDynamicSharedMemorySize, TG_SMEM);

    k_embed<<<RR, 256>>>(idx, tok, pos, x);

    dim3 gEE(EE / 128, RR / 128);      // (8, 16)
    dim3 gFF(FF / 128, RR / 128);      // (32, 16)
    dim3 gLM(VV / 128, RR / 128);      // (250, 16)

    for (int l = 0; l < LL; l++) {
        const float* wq = Wq + (size_t)l * EE * EE;
        const float* wk = Wk + (size_t)l * EE * EE;
        const float* wv = Wv + (size_t)l * EE * EE;
        const float* wp = Wp + (size_t)l * EE * EE;
        const float* w1 = W1 + (size_t)l * EE * FF;
        const float* w2 = W2 + (size_t)l * FF * EE;

        k_ln<<<RR, 256>>>(x, g1 + l * EE, b1 + l * EE, h);
        k_tgemm<false,false,false><<<gEE, 512, TG_SMEM>>>(h, wq, nullptr, nullptr, q, RR, EE, EE);
        k_tgemm<false,false,false><<<gEE, 512, TG_SMEM>>>(h, wk, nullptr, nullptr, k, RR, EE, EE);
        k_tgemm<false,false,false><<<gEE, 512, TG_SMEM>>>(h, wv, nullptr, nullptr, v, RR, EE, EE);

        k_scores<<<dim3(16, 16, 32), 256>>>(q, k);
        k_softmax<<<BB * HH * TT, 256>>>();
        k_av<<<dim3(16, 32), 256>>>(v, o);

        // x = x + o @ Wp + bp
        k_tgemm<true,false,true><<<gEE, 512, TG_SMEM>>>(o, wp, bp + l * EE, x, x, RR, EE, EE);

        k_ln<<<RR, 256>>>(x, g2 + l * EE, b2 + l * EE, h);
        // ff = relu(h @ W1 + bf1)
        k_tgemm<true,true,false><<<gFF, 512, TG_SMEM>>>(h, w1, bf1 + l * FF, nullptr, ff, RR, FF, EE);
        // x = x + ff @ W2 + bf2
        k_tgemm<true,false,true><<<gEE, 512, TG_SMEM>>>(ff, w2, bf2 + l * EE, x, x, RR, EE, FF);
    }

    k_ln<<<RR, 256>>>(x, gf, bff, h);
    k_tgemm<true,false,false><<<gLM, 512, TG_SMEM>>>(h, Wlm, blm, nullptr, out, RR, VV, EE);
}

// round 8
// speedup vs baseline: 3.0432x; 1.1913x over previous
#include <cuda_runtime.h>
#include <cstdint>

// ---------------- problem constants ----------------
#define BB 2
#define TT 1024
#define EE 1024
#define HH 16
#define DD 64
#define LL 6
#define FF 4096
#define VV 32000
#define RR (BB*TT)   // 2048 token rows

// ---------------- device scratch (static, no allocations) ----------------
__device__ float g_x [RR*EE];
__device__ float g_h [RR*EE];
__device__ float g_q [RR*EE];
__device__ float g_k [RR*EE];
__device__ float g_v [RR*EE];
__device__ float g_o [RR*EE];
__device__ float g_ff[RR*FF];
__device__ float g_S [(size_t)BB*HH*TT*TT];   // 134 MB attention scores

__device__ __forceinline__ uint32_t smem_u32(const void* p) {
    uint32_t a;
    asm("{ .reg .u64 t; cvta.to.shared.u64 t, %1; cvt.u32.u64 %0, t; }"
        : "=r"(a) : "l"(p));
    return a;
}

__device__ __forceinline__ void ldsm_x4(uint32_t& r0, uint32_t& r1,
                                        uint32_t& r2, uint32_t& r3, uint32_t addr) {
    asm volatile("ldmatrix.sync.aligned.m8n8.x4.shared.b16 {%0,%1,%2,%3}, [%4];"
                 : "=r"(r0), "=r"(r1), "=r"(r2), "=r"(r3) : "r"(addr));
}

__device__ __forceinline__ void mma_bf16(float& c0, float& c1, float& c2, float& c3,
                                         uint32_t a0, uint32_t a1, uint32_t a2, uint32_t a3,
                                         uint32_t b0, uint32_t b1) {
    asm volatile("mma.sync.aligned.m16n8k16.row.col.f32.bf16.bf16.f32 "
                 "{%0,%1,%2,%3}, {%4,%5,%6,%7}, {%8,%9}, {%0,%1,%2,%3};"
                 : "+f"(c0), "+f"(c1), "+f"(c2), "+f"(c3)
                 : "r"(a0), "r"(a1), "r"(a2), "r"(a3), "r"(b0), "r"(b1));
}

// split two fp32 (k-consecutive x0,x1) into packed bf16x2 hi and lo
__device__ __forceinline__ void split2(float x0, float x1, uint32_t& h, uint32_t& l) {
    uint32_t hh;
    asm("cvt.rn.bf16x2.f32 %0, %1, %2;" : "=r"(hh) : "f"(x1), "f"(x0));
    float h0 = __uint_as_float(hh << 16);
    float h1 = __uint_as_float(hh & 0xFFFF0000u);
    float l0 = x0 - h0, l1 = x1 - h1;
    uint32_t ll;
    asm("cvt.rn.bf16x2.f32 %0, %1, %2;" : "=r"(ll) : "f"(l1), "f"(l0));
    h = hh; l = ll;
}

// 3 mma terms: ah*bh + ah*bl + al*bh
#define MMA3(ACC, AH, AL, BH0, BH1, BL0, BL1) do { \
    mma_bf16((ACC)[0], (ACC)[1], (ACC)[2], (ACC)[3], \
             (AH)[0], (AH)[1], (AH)[2], (AH)[3], (BH0), (BH1)); \
    mma_bf16((ACC)[0], (ACC)[1], (ACC)[2], (ACC)[3], \
             (AH)[0], (AH)[1], (AH)[2], (AH)[3], (BL0), (BL1)); \
    mma_bf16((ACC)[0], (ACC)[1], (ACC)[2], (ACC)[3], \
             (AL)[0], (AL)[1], (AL)[2], (AL)[3], (BH0), (BH1)); \
} while (0)

// ================= 3xBF16 tensor-core GEMM (fp32-accurate) =================
#define TG_SMEM 65536

template<bool BIAS, bool RELU, bool RESID>
__global__ void __launch_bounds__(512, 1)
k_tgemm(const float* __restrict__ A, const float* __restrict__ B,
        const float* __restrict__ bias, const float* __restrict__ resid,
        float* __restrict__ C, int M, int N, int K) {
    extern __shared__ char smem[];
    const uint32_t sb = smem_u32(smem);
    const int tid = threadIdx.x, lane = tid & 31, wid = tid >> 5;
    const int wm = wid & 3, wn = wid >> 2;
    const int rowBase = blockIdx.y * 128;
    const int colBase = blockIdx.x * 128;

    float acc[2][4][4];
    #pragma unroll
    for (int i = 0; i < 2; i++)
        #pragma unroll
        for (int j = 0; j < 4; j++)
            #pragma unroll
            for (int r = 0; r < 4; r++) acc[i][j][r] = 0.f;

    const int a_m = tid >> 3, a_kq = tid & 7;
    const int b_n = tid & 127, b_q = tid >> 7;
    const int b_s = (b_n >> 3) & 7;

    const int a_m_in = (lane & 7) + ((lane >> 3) & 1) * 8;
    const int a_kb   = ((lane >> 4) & 1) * 16;
    const int b_n_in = (lane & 7) + ((lane >> 4) & 1) * 8;
    const int b_kb   = ((lane >> 3) & 1) * 16;

    const int nchunk = K >> 5;
    float4 pa[2], pb[2];

    {
        #pragma unroll
        for (int i = 0; i < 2; i++) {
            int m = a_m + 64 * i;
            pa[i] = *(const float4*)(A + (size_t)(rowBase + m) * K + a_kq * 4);
        }
        #pragma unroll
        for (int i = 0; i < 2; i++) {
            int kq = (b_q + 4 * i) ^ b_s;
            const float* bp = B + (size_t)(kq * 4) * N + colBase + b_n;
            pb[i] = make_float4(bp[0], bp[(size_t)N], bp[(size_t)2 * N], bp[(size_t)3 * N]);
        }
        #pragma unroll
        for (int i = 0; i < 2; i++) {
            int m = a_m + 64 * i;
            uint32_t h01, l01, h23, l23;
            split2(pa[i].x, pa[i].y, h01, l01);
            split2(pa[i].z, pa[i].w, h23, l23);
            uint32_t off = (uint32_t)(m * 64 + ((a_kq * 8) ^ (((m >> 1) & 3) << 4)));
            *(uint2*)(smem + off)        = make_uint2(h01, h23);
            *(uint2*)(smem + 8192 + off) = make_uint2(l01, l23);
        }
        #pragma unroll
        for (int i = 0; i < 2; i++) {
            int kq = (b_q + 4 * i) ^ b_s;
            uint32_t h01, l01, h23, l23;
            split2(pb[i].x, pb[i].y, h01, l01);
            split2(pb[i].z, pb[i].w, h23, l23);
            uint32_t off = (uint32_t)(b_n * 64 + ((kq * 8) ^ (((b_n >> 1) & 3) << 4)));
            *(uint2*)(smem + 16384 + off) = make_uint2(h01, h23);
            *(uint2*)(smem + 24576 + off) = make_uint2(l01, l23);
        }
    }
    __syncthreads();

    for (int c = 0; c < nchunk; c++) {
        const uint32_t base = sb + (uint32_t)(c & 1) * 32768;
        const uint32_t ah = base, al = base + 8192;
        const uint32_t bh = base + 16384, bl = base + 24576;

        if (c + 1 < nchunk) {
            int k0 = (c + 1) << 5;
            #pragma unroll
            for (int i = 0; i < 2; i++) {
                int m = a_m + 64 * i;
                pa[i] = *(const float4*)(A + (size_t)(rowBase + m) * K + k0 + a_kq * 4);
            }
            #pragma unroll
            for (int i = 0; i < 2; i++) {
                int kq = (b_q + 4 * i) ^ b_s;
                const float* bp = B + (size_t)(k0 + kq * 4) * N + colBase + b_n;
                pb[i] = make_float4(bp[0], bp[(size_t)N], bp[(size_t)2 * N], bp[(size_t)3 * N]);
            }
        }

        #pragma unroll
        for (int kt = 0; kt < 2; kt++) {
            uint32_t afh[2][4], afl[2][4], bfh[2][4], bfl[2][4];
            #pragma unroll
            for (int mt = 0; mt < 2; mt++) {
                int row = wm * 32 + mt * 16 + a_m_in;
                uint32_t off = (uint32_t)(row * 64 + ((kt * 32 + a_kb) ^ (((row >> 1) & 3) << 4)));
                ldsm_x4(afh[mt][0], afh[mt][1], afh[mt][2], afh[mt][3], ah + off);
                ldsm_x4(afl[mt][0], afl[mt][1], afl[mt][2], afl[mt][3], al + off);
            }
            #pragma unroll
            for (int ntp = 0; ntp < 2; ntp++) {
                int row = wn * 32 + ntp * 16 + b_n_in;
                uint32_t off = (uint32_t)(row * 64 + ((kt * 32 + b_kb) ^ (((row >> 1) & 3) << 4)));
                ldsm_x4(bfh[ntp][0], bfh[ntp][1], bfh[ntp][2], bfh[ntp][3], bh + off);
                ldsm_x4(bfl[ntp][0], bfl[ntp][1], bfl[ntp][2], bfl[ntp][3], bl + off);
            }
            #pragma unroll
            for (int mt = 0; mt < 2; mt++)
                #pragma unroll
                for (int nt = 0; nt < 4; nt++) {
                    const int np = nt >> 1, ne = (nt & 1) * 2;
                    MMA3(acc[mt][nt], afh[mt], afl[mt],
                         bfh[np][ne], bfh[np][ne + 1], bfl[np][ne], bfl[np][ne + 1]);
                }
        }

        if (c + 1 < nchunk) {
            char* nb = smem + ((c + 1) & 1) * 32768;
            __syncthreads();
            #pragma unroll
            for (int i = 0; i < 2; i++) {
                int m = a_m + 64 * i;
                uint32_t h01, l01, h23, l23;
                split2(pa[i].x, pa[i].y, h01, l01);
                split2(pa[i].z, pa[i].w, h23, l23);
                uint32_t off = (uint32_t)(m * 64 + ((a_kq * 8) ^ (((m >> 1) & 3) << 4)));
                *(uint2*)(nb + off)        = make_uint2(h01, h23);
                *(uint2*)(nb + 8192 + off) = make_uint2(l01, l23);
            }
            #pragma unroll
            for (int i = 0; i < 2; i++) {
                int kq = (b_q + 4 * i) ^ b_s;
                uint32_t h01, l01, h23, l23;
                split2(pb[i].x, pb[i].y, h01, l01);
                split2(pb[i].z, pb[i].w, h23, l23);
                uint32_t off = (uint32_t)(b_n * 64 + ((kq * 8) ^ (((b_n >> 1) & 3) << 4)));
                *(uint2*)(nb + 16384 + off) = make_uint2(h01, h23);
                *(uint2*)(nb + 24576 + off) = make_uint2(l01, l23);
            }
            __syncthreads();
        }
    }

    const int row0 = lane >> 2, col0 = (lane & 3) * 2;
    #pragma unroll
    for (int mt = 0; mt < 2; mt++) {
        #pragma unroll
        for (int nt = 0; nt < 4; nt++) {
            int gm = rowBase + wm * 32 + mt * 16 + row0;
            int gn = colBase + wn * 32 + nt * 8 + col0;
            float o0 = acc[mt][nt][0], o1 = acc[mt][nt][1];
            float o2 = acc[mt][nt][2], o3 = acc[mt][nt][3];
            if (BIAS) {
                float bv0 = bias[gn], bv1 = bias[gn + 1];
                o0 += bv0; o1 += bv1; o2 += bv0; o3 += bv1;
            }
            size_t p0 = (size_t)gm * N + gn;
            size_t p1 = (size_t)(gm + 8) * N + gn;
            if (RESID) {
                float2 r0v = *(const float2*)(resid + p0);
                float2 r1v = *(const float2*)(resid + p1);
                o0 += r0v.x; o1 += r0v.y; o2 += r1v.x; o3 += r1v.y;
            }
            if (RELU) {
                o0 = fmaxf(o0, 0.f); o1 = fmaxf(o1, 0.f);
                o2 = fmaxf(o2, 0.f); o3 = fmaxf(o3, 0.f);
            }
            *(float2*)(C + p0) = make_float2(o0, o1);
            *(float2*)(C + p1) = make_float2(o2, o3);
        }
    }
}

// ================= tensor-core attention scores =================
// S[q][kj] = 0.125 * sum_d Q[q][d]*K[kj][d], causal masked.
// grid (8 ktile, 8 qtile, 32 bh), 512 threads, 128x128 tile, 3xBF16.
// SMEM: Qh@0, Ql@16K, Kh@32K, Kl@48K — each 128 rows x 64 bf16 (128B rows, SW128).
#define SC_SMEM 65536

__global__ void __launch_bounds__(512, 1)
k_scores_t(const float* __restrict__ q, const float* __restrict__ k) {
    const int bh = blockIdx.z, b = bh >> 4, h = bh & 15;
    const int q0 = blockIdx.y * 128, k0 = blockIdx.x * 128;
    const int tid = threadIdx.x;

    if (k0 > q0 + 127) {   // fully masked tile: pure fill
        float* base = g_S + ((size_t)bh * TT + q0) * TT + k0;
        for (int i = tid; i < 128 * 32; i += 512) {
            int rr = i >> 5, cc = (i & 31) * 4;
            *(float4*)(base + (size_t)rr * TT + cc) =
                make_float4(-1e30f, -1e30f, -1e30f, -1e30f);
        }
        return;
    }

    extern __shared__ char smem[];
    const uint32_t sb = smem_u32(smem);
    const int lane = tid & 31, wid = tid >> 5;
    const int wm = wid & 3, wn = wid >> 2;

    // load Q and K tiles (both row-major [token][d], d contiguous)
    {
        #pragma unroll
        for (int i = 0; i < 4; i++) {
            int idx = tid + 512 * i;
            int row = idx >> 4, dq = idx & 15;
            float4 v = *(const float4*)(q + (size_t)(b * TT + q0 + row) * EE + h * DD + dq * 4);
            uint32_t h01, l01, h23, l23;
            split2(v.x, v.y, h01, l01);
            split2(v.z, v.w, h23, l23);
            uint32_t off = (uint32_t)(row * 128 + ((dq * 8) ^ ((row & 7) << 4)));
            *(uint2*)(smem + off)         = make_uint2(h01, h23);
            *(uint2*)(smem + 16384 + off) = make_uint2(l01, l23);
        }
        #pragma unroll
        for (int i = 0; i < 4; i++) {
            int idx = tid + 512 * i;
            int row = idx >> 4, dq = idx & 15;
            float4 v = *(const float4*)(k + (size_t)(b * TT + k0 + row) * EE + h * DD + dq * 4);
            uint32_t h01, l01, h23, l23;
            split2(v.x, v.y, h01, l01);
            split2(v.z, v.w, h23, l23);
            uint32_t off = (uint32_t)(row * 128 + ((dq * 8) ^ ((row & 7) << 4)));
            *(uint2*)(smem + 32768 + off) = make_uint2(h01, h23);
            *(uint2*)(smem + 49152 + off) = make_uint2(l01, l23);
        }
    }
    __syncthreads();

    const int a_m_in = (lane & 7) + ((lane >> 3) & 1) * 8;
    const int a_kb   = ((lane >> 4) & 1) * 16;
    const int b_n_in = (lane & 7) + ((lane >> 4) & 1) * 8;
    const int b_kb   = ((lane >> 3) & 1) * 16;

    float acc[2][4][4];
    #pragma unroll
    for (int i = 0; i < 2; i++)
        #pragma unroll
        for (int j = 0; j < 4; j++)
            #pragma unroll
            for (int r = 0; r < 4; r++) acc[i][j][r] = 0.f;

    #pragma unroll
    for (int kt = 0; kt < 4; kt++) {
        uint32_t afh[2][4], afl[2][4], bfh[2][4], bfl[2][4];
        #pragma unroll
        for (int mt = 0; mt < 2; mt++) {
            int row = wm * 32 + mt * 16 + a_m_in;
            uint32_t off = (uint32_t)(row * 128 + ((kt * 32 + a_kb) ^ ((row & 7) << 4)));
            ldsm_x4(afh[mt][0], afh[mt][1], afh[mt][2], afh[mt][3], sb + off);
            ldsm_x4(afl[mt][0], afl[mt][1], afl[mt][2], afl[mt][3], sb + 16384 + off);
        }
        #pragma unroll
        for (int ntp = 0; ntp < 2; ntp++) {
            int row = wn * 32 + ntp * 16 + b_n_in;
            uint32_t off = (uint32_t)(row * 128 + ((kt * 32 + b_kb) ^ ((row & 7) << 4)));
            ldsm_x4(bfh[ntp][0], bfh[ntp][1], bfh[ntp][2], bfh[ntp][3], sb + 32768 + off);
            ldsm_x4(bfl[ntp][0], bfl[ntp][1], bfl[ntp][2], bfl[ntp][3], sb + 49152 + off);
        }
        #pragma unroll
        for (int mt = 0; mt < 2; mt++)
            #pragma unroll
            for (int nt = 0; nt < 4; nt++) {
                const int np = nt >> 1, ne = (nt & 1) * 2;
                MMA3(acc[mt][nt], afh[mt], afl[mt],
                     bfh[np][ne], bfh[np][ne + 1], bfl[np][ne], bfl[np][ne + 1]);
            }
    }

    const int row0 = lane >> 2, col0 = (lane & 3) * 2;
    #pragma unroll
    for (int mt = 0; mt < 2; mt++) {
        #pragma unroll
        for (int nt = 0; nt < 4; nt++) {
            int qi = q0 + wm * 32 + mt * 16 + row0;
            int kj = k0 + wn * 32 + nt * 8 + col0;
            float s0 = (kj     <= qi) ? acc[mt][nt][0] * 0.125f : -1e30f;
            float s1 = (kj + 1 <= qi) ? acc[mt][nt][1] * 0.125f : -1e30f;
            float s2 = (kj     <= qi + 8) ? acc[mt][nt][2] * 0.125f : -1e30f;
            float s3 = (kj + 1 <= qi + 8) ? acc[mt][nt][3] * 0.125f : -1e30f;
            *(float2*)(g_S + ((size_t)bh * TT + qi) * TT + kj)       = make_float2(s0, s1);
            *(float2*)(g_S + ((size_t)bh * TT + qi + 8) * TT + kj)   = make_float2(s2, s3);
        }
    }
}

// ================= tensor-core O = P @ V =================
// grid (8 qtile, 32 bh), 256 threads (8 warps, 4x2 of 32x32), out 128x64.
// SMEM per buffer: Ph@0(8K), Pl@8K, Vh@16K(4K), Vl@20K; double buffered 48K.
#define AV_SMEM 49152

__global__ void __launch_bounds__(256, 1)
k_av_t(const float* __restrict__ v, float* __restrict__ o) {
    extern __shared__ char smem[];
    const uint32_t sb = smem_u32(smem);
    const int bh = blockIdx.y, b = bh >> 4, h = bh & 15;
    const int q0 = blockIdx.x * 128;
    const int tid = threadIdx.x, lane = tid & 31, wid = tid >> 5;
    const int wm = wid & 3, wn = wid >> 2;

    const int a_m = tid >> 3, a_kq = tid & 7;        // P: row, k-float4
    const int b_n = tid & 63;                        // V: d index
    const int b_q0 = tid >> 6;                       // k-group base (0..3), +4 on i=1
    const int b_s = (b_n >> 3) & 7;

    const int a_m_in = (lane & 7) + ((lane >> 3) & 1) * 8;
    const int a_kb   = ((lane >> 4) & 1) * 16;
    const int b_n_in = (lane & 7) + ((lane >> 4) & 1) * 8;
    const int b_kb   = ((lane >> 3) & 1) * 16;

    float acc[2][4][4];
    #pragma unroll
    for (int i = 0; i < 2; i++)
        #pragma unroll
        for (int j = 0; j < 4; j++)
            #pragma unroll
            for (int r = 0; r < 4; r++) acc[i][j][r] = 0.f;

    const int nchunk = (q0 + 128) >> 5;
    const float* Prow = g_S + ((size_t)bh * TT + q0) * TT;  // P row base (stride TT)
    float4 pa[4], pb[2];

    // load chunk 0
    {
        #pragma unroll
        for (int i = 0; i < 4; i++) {
            int idx = tid + 256 * i;
            int m = idx >> 3, kq = idx & 7;
            pa[i] = *(const float4*)(Prow + (size_t)m * TT + kq * 4);
        }
        #pragma unroll
        for (int i = 0; i < 2; i++) {
            int kq = (b_q0 + 4 * i) ^ b_s;
            const float* bp = v + (size_t)(b * TT + kq * 4) * EE + h * DD + b_n;
            pb[i] = make_float4(bp[0], bp[(size_t)EE], bp[(size_t)2 * EE], bp[(size_t)3 * EE]);
        }
        #pragma unroll
        for (int i = 0; i < 4; i++) {
            int idx = tid + 256 * i;
            int m = idx >> 3, kq = idx & 7;
            uint32_t h01, l01, h23, l23;
            split2(pa[i].x, pa[i].y, h01, l01);
            split2(pa[i].z, pa[i].w, h23, l23);
            uint32_t off = (uint32_t)(m * 64 + ((kq * 8) ^ (((m >> 1) & 3) << 4)));
            *(uint2*)(smem + off)        = make_uint2(h01, h23);
            *(uint2*)(smem + 8192 + off) = make_uint2(l01, l23);
        }
        #pragma unroll
        for (int i = 0; i < 2; i++) {
            int kq = (b_q0 + 4 * i) ^ b_s;
            uint32_t h01, l01, h23, l23;
            split2(pb[i].x, pb[i].y, h01, l01);
            split2(pb[i].z, pb[i].w, h23, l23);
            uint32_t off = (uint32_t)(b_n * 64 + ((kq * 8) ^ (((b_n >> 1) & 3) << 4)));
            *(uint2*)(smem + 16384 + off) = make_uint2(h01, h23);
            *(uint2*)(smem + 20480 + off) = make_uint2(l01, l23);
        }
    }
    __syncthreads();

    for (int c = 0; c < nchunk; c++) {
        const uint32_t base = sb + (uint32_t)(c & 1) * 24576;
        const uint32_t ph = base, pl = base + 8192;
        const uint32_t vh = base + 16384, vl = base + 20480;

        if (c + 1 < nchunk) {
            int j0 = (c + 1) << 5;
            #pragma unroll
            for (int i = 0; i < 4; i++) {
                int idx = tid + 256 * i;
                int m = idx >> 3, kq = idx & 7;
                pa[i] = *(const float4*)(Prow + (size_t)m * TT + j0 + kq * 4);
            }
            #pragma unroll
            for (int i = 0; i < 2; i++) {
                int kq = (b_q0 + 4 * i) ^ b_s;
                const float* bp = v + (size_t)(b * TT + j0 + kq * 4) * EE + h * DD + b_n;
                pb[i] = make_float4(bp[0], bp[(size_t)EE], bp[(size_t)2 * EE], bp[(size_t)3 * EE]);
            }
        }

        #pragma unroll
        for (int kt = 0; kt < 2; kt++) {
            uint32_t afh[2][4], afl[2][4], bfh[2][4], bfl[2][4];
            #pragma unroll
            for (int mt = 0; mt < 2; mt++) {
                int row = wm * 32 + mt * 16 + a_m_in;
                uint32_t off = (uint32_t)(row * 64 + ((kt * 32 + a_kb) ^ (((row >> 1) & 3) << 4)));
                ldsm_x4(afh[mt][0], afh[mt][1], afh[mt][2], afh[mt][3], ph + off);
                ldsm_x4(afl[mt][0], afl[mt][1], afl[mt][2], afl[mt][3], pl + off);
            }
            #pragma unroll
            for (int ntp = 0; ntp < 2; ntp++) {
                int row = wn * 32 + ntp * 16 + b_n_in;
                uint32_t off = (uint32_t)(row * 64 + ((kt * 32 + b_kb) ^ (((row >> 1) & 3) << 4)));
                ldsm_x4(bfh[ntp][0], bfh[ntp][1], bfh[ntp][2], bfh[ntp][3], vh + off);
                ldsm_x4(bfl[ntp][0], bfl[ntp][1], bfl[ntp][2], bfl[ntp][3], vl + off);
            }
            #pragma unroll
            for (int mt = 0; mt < 2; mt++)
                #pragma unroll
                for (int nt = 0; nt < 4; nt++) {
                    const int np = nt >> 1, ne = (nt & 1) * 2;
                    MMA3(acc[mt][nt], afh[mt], afl[mt],
                         bfh[np][ne], bfh[np][ne + 1], bfl[np][ne], bfl[np][ne + 1]);
                }
        }

        if (c + 1 < nchunk) {
            char* nb = smem + ((c + 1) & 1) * 24576;
            __syncthreads();
            #pragma unroll
            for (int i = 0; i < 4; i++) {
                int idx = tid + 256 * i;
                int m = idx >> 3, kq = idx & 7;
                uint32_t h01, l01, h23, l23;
                split2(pa[i].x, pa[i].y, h01, l01);
                split2(pa[i].z, pa[i].w, h23, l23);
                uint32_t off = (uint32_t)(m * 64 + ((kq * 8) ^ (((m >> 1) & 3) << 4)));
                *(uint2*)(nb + off)        = make_uint2(h01, h23);
                *(uint2*)(nb + 8192 + off) = make_uint2(l01, l23);
            }
            #pragma unroll
            for (int i = 0; i < 2; i++) {
                int kq = (b_q0 + 4 * i) ^ b_s;
                uint32_t h01, l01, h23, l23;
                split2(pb[i].x, pb[i].y, h01, l01);
                split2(pb[i].z, pb[i].w, h23, l23);
                uint32_t off = (uint32_t)(b_n * 64 + ((kq * 8) ^ (((b_n >> 1) & 3) << 4)));
                *(uint2*)(nb + 16384 + off) = make_uint2(h01, h23);
                *(uint2*)(nb + 20480 + off) = make_uint2(l01, l23);
            }
            __syncthreads();
        }
    }

    const int row0 = lane >> 2, col0 = (lane & 3) * 2;
    #pragma unroll
    for (int mt = 0; mt < 2; mt++) {
        #pragma unroll
        for (int nt = 0; nt < 4; nt++) {
            int gm = q0 + wm * 32 + mt * 16 + row0;
            int gn = wn * 32 + nt * 8 + col0;
            size_t p0 = (size_t)(b * TT + gm) * EE + h * DD + gn;
            size_t p1 = (size_t)(b * TT + gm + 8) * EE + h * DD + gn;
            *(float2*)(o + p0) = make_float2(acc[mt][nt][0], acc[mt][nt][1]);
            *(float2*)(o + p1) = make_float2(acc[mt][nt][2], acc[mt][nt][3]);
        }
    }
}

// ---------------- embed ----------------
__global__ void k_embed(const int* __restrict__ idx, const float* __restrict__ tok,
                        const float* __restrict__ pos, float* __restrict__ x) {
    int r = blockIdx.x;
    int t = r & (TT - 1);
    int tokid = idx[r];
    const float4* te = (const float4*)(tok + (size_t)tokid * EE);
    const float4* pe = (const float4*)(pos + (size_t)t * EE);
    float4* xr = (float4*)(x + (size_t)r * EE);
    int c = threadIdx.x;
    float4 a = te[c], b = pe[c];
    xr[c] = make_float4(a.x + b.x, a.y + b.y, a.z + b.z, a.w + b.w);
}

// ---------------- block reduce ----------------
__device__ __forceinline__ float blockReduceSum(float val, float* red) {
    int tid = threadIdx.x;
    #pragma unroll
    for (int o = 16; o; o >>= 1) val += __shfl_xor_sync(0xffffffffu, val, o);
    if ((tid & 31) == 0) red[tid >> 5] = val;
    __syncthreads();
    if (tid < 32) {
        float v = (tid < 8) ? red[tid] : 0.f;
        #pragma unroll
        for (int o = 4; o; o >>= 1) v += __shfl_xor_sync(0xffffffffu, v, o);
        if (tid == 0) red[0] = v;
    }
    __syncthreads();
    float r = red[0];
    __syncthreads();
    return r;
}

// ---------------- layernorm ----------------
__global__ void k_ln(const float* __restrict__ x, const float* __restrict__ g,
                     const float* __restrict__ b, float* __restrict__ out) {
    __shared__ float red[32];
    int row = blockIdx.x, tid = threadIdx.x;
    const float* xr = x + (size_t)row * EE;
    float v[4];
    float s = 0.f;
    #pragma unroll
    for (int i = 0; i < 4; i++) { v[i] = xr[tid + 256 * i]; s += v[i]; }
    s = blockReduceSum(s, red);
    float mean = s * (1.f / EE);
    float s2 = 0.f;
    #pragma unroll
    for (int i = 0; i < 4; i++) { float d = v[i] - mean; s2 += d * d; }
    s2 = blockReduceSum(s2, red);
    float inv = rsqrtf(s2 * (1.f / EE) + 1e-5f);
    #pragma unroll
    for (int i = 0; i < 4; i++) {
        int c = tid + 256 * i;
        out[(size_t)row * EE + c] = (v[i] - mean) * inv * g[c] + b[c];
    }
}

// ---------------- softmax per row ----------------
__global__ void k_softmax() {
    __shared__ float red[32];
    size_t row = blockIdx.x;
    float* r = g_S + row * (size_t)TT;
    int tid = threadIdx.x;
    float v[4], m = -1e30f;
    #pragma unroll
    for (int i = 0; i < 4; i++) { v[i] = r[tid + 256 * i]; m = fmaxf(m, v[i]); }
    #pragma unroll
    for (int o = 16; o; o >>= 1) m = fmaxf(m, __shfl_xor_sync(0xffffffffu, m, o));
    if ((tid & 31) == 0) red[tid >> 5] = m;
    __syncthreads();
    if (tid < 32) {
        float t = (tid < 8) ? red[tid] : -1e30f;
        #pragma unroll
        for (int o = 4; o; o >>= 1) t = fmaxf(t, __shfl_xor_sync(0xffffffffu, t, o));
        if (tid == 0) red[0] = t;
    }
    __syncthreads();
    m = red[0];
    __syncthreads();
    float s = 0.f;
    #pragma unroll
    for (int i = 0; i < 4; i++) { v[i] = __expf(v[i] - m); s += v[i]; }
    s = blockReduceSum(s, red);
    float inv = 1.f / s;
    #pragma unroll
    for (int i = 0; i < 4; i++) r[tid + 256 * i] = v[i] * inv;
}

// ---------------- host orchestration ----------------
extern "C" void kernel_launch(void* const* d_in, const int* in_sizes, int n_in,
                              void* d_out, int out_size) {
    const int*   idx  = (const int*)  d_in[0];
    const float* tok  = (const float*)d_in[1];
    const float* pos  = (const float*)d_in[2];
    const float* Wq   = (const float*)d_in[3];
    const float* Wk   = (const float*)d_in[4];
    const float* Wv   = (const float*)d_in[5];
    const float* Wp   = (const float*)d_in[6];
    const float* bp   = (const float*)d_in[7];
    const float* g1   = (const float*)d_in[8];
    const float* b1   = (const float*)d_in[9];
    const float* g2   = (const float*)d_in[10];
    const float* b2   = (const float*)d_in[11];
    const float* W1   = (const float*)d_in[12];
    const float* bf1  = (const float*)d_in[13];
    const float* W2   = (const float*)d_in[14];
    const float* bf2  = (const float*)d_in[15];
    const float* gf   = (const float*)d_in[16];
    const float* bff  = (const float*)d_in[17];
    const float* Wlm  = (const float*)d_in[18];
    const float* blm  = (const float*)d_in[19];
    float* out = (float*)d_out;

    float *x, *h, *q, *k, *v, *o, *ff;
    cudaGetSymbolAddress((void**)&x,  g_x);
    cudaGetSymbolAddress((void**)&h,  g_h);
    cudaGetSymbolAddress((void**)&q,  g_q);
    cudaGetSymbolAddress((void**)&k,  g_k);
    cudaGetSymbolAddress((void**)&v,  g_v);
    cudaGetSymbolAddress((void**)&o,  g_o);
    cudaGetSymbolAddress((void**)&ff, g_ff);

    cudaFuncSetAttribute(k_tgemm<false,false,false>,
                         cudaFuncAttributeMaxDynamicSharedMemorySize, TG_SMEM);
    cudaFuncSetAttribute(k_tgemm<true,false,true>,
                         cudaFuncAttributeMaxDynamicSharedMemorySize, TG_SMEM);
    cudaFuncSetAttribute(k_tgemm<true,true,false>,
                         cudaFuncAttributeMaxDynamicSharedMemorySize, TG_SMEM);
    cudaFuncSetAttribute(k_tgemm<true,false,false>,
                         cudaFuncAttributeMaxDynamicSharedMemorySize, TG_SMEM);
    cudaFuncSetAttribute(k_scores_t,
                         cudaFuncAttributeMaxDynamicSharedMemorySize, SC_SMEM);
    cudaFuncSetAttribute(k_av_t,
                         cudaFuncAttributeMaxDynamicSharedMemorySize, AV_SMEM);

    k_embed<<<RR, 256>>>(idx, tok, pos, x);

    dim3 gEE(EE / 128, RR / 128);      // (8, 16)
    dim3 gFF(FF / 128, RR / 128);      // (32, 16)
    dim3 gLM(VV / 128, RR / 128);      // (250, 16)

    for (int l = 0; l < LL; l++) {
        const float* wq = Wq + (size_t)l * EE * EE;
        const float* wk = Wk + (size_t)l * EE * EE;
        const float* wv = Wv + (size_t)l * EE * EE;
        const float* wp = Wp + (size_t)l * EE * EE;
        const float* w1 = W1 + (size_t)l * EE * FF;
        const float* w2 = W2 + (size_t)l * FF * EE;

        k_ln<<<RR, 256>>>(x, g1 + l * EE, b1 + l * EE, h);
        k_tgemm<false,false,false><<<gEE, 512, TG_SMEM>>>(h, wq, nullptr, nullptr, q, RR, EE, EE);
        k_tgemm<false,false,false><<<gEE, 512, TG_SMEM>>>(h, wk, nullptr, nullptr, k, RR, EE, EE);
        k_tgemm<false,false,false><<<gEE, 512, TG_SMEM>>>(h, wv, nullptr, nullptr, v, RR, EE, EE);

        k_scores_t<<<dim3(8, 8, 32), 512, SC_SMEM>>>(q, k);
        k_softmax<<<BB * HH * TT, 256>>>();
        k_av_t<<<dim3(8, 32), 256, AV_SMEM>>>(v, o);

        // x = x + o @ Wp + bp
        k_tgemm<true,false,true><<<gEE, 512, TG_SMEM>>>(o, wp, bp + l * EE, x, x, RR, EE, EE);

        k_ln<<<RR, 256>>>(x, g2 + l * EE, b2 + l * EE, h);
        // ff = relu(h @ W1 + bf1)
        k_tgemm<true,true,false><<<gFF, 512, TG_SMEM>>>(h, w1, bf1 + l * FF, nullptr, ff, RR, FF, EE);
        // x = x + ff @ W2 + bf2
        k_tgemm<true,false,true><<<gEE, 512, TG_SMEM>>>(ff, w2, bf2 + l * EE, x, x, RR, EE, FF);
    }

    k_ln<<<RR, 256>>>(x, gf, bff, h);
    k_tgemm<true,false,false><<<gLM, 512, TG_SMEM>>>(h, Wlm, blm, nullptr, out, RR, VV, EE);
}

// round 11
// speedup vs baseline: 3.1208x; 1.0255x over previous
#include <cuda_runtime.h>
#include <cstdint>

// ---------------- problem constants ----------------
#define BB 2
#define TT 1024
#define EE 1024
#define HH 16
#define DD 64
#define LL 6
#define FF 4096
#define VV 32000
#define RR (BB*TT)   // 2048 token rows

// ---------------- device scratch (static, no allocations) ----------------
__device__ float g_x [RR*EE];
__device__ float g_h [RR*EE];
__device__ float g_q [RR*EE];
__device__ float g_k [RR*EE];
__device__ float g_v [RR*EE];
__device__ float g_o [RR*EE];
__device__ float g_ff[RR*FF];
__device__ float g_S [(size_t)BB*HH*TT*TT];   // 134 MB attention scores

__device__ __forceinline__ uint32_t smem_u32(const void* p) {
    uint32_t a;
    asm("{ .reg .u64 t; cvta.to.shared.u64 t, %1; cvt.u32.u64 %0, t; }"
        : "=r"(a) : "l"(p));
    return a;
}

__device__ __forceinline__ void ldsm_x4(uint32_t& r0, uint32_t& r1,
                                        uint32_t& r2, uint32_t& r3, uint32_t addr) {
    asm volatile("ldmatrix.sync.aligned.m8n8.x4.shared.b16 {%0,%1,%2,%3}, [%4];"
                 : "=r"(r0), "=r"(r1), "=r"(r2), "=r"(r3) : "r"(addr));
}

__device__ __forceinline__ void mma_bf16(float& c0, float& c1, float& c2, float& c3,
                                         uint32_t a0, uint32_t a1, uint32_t a2, uint32_t a3,
                                         uint32_t b0, uint32_t b1) {
    asm volatile("mma.sync.aligned.m16n8k16.row.col.f32.bf16.bf16.f32 "
                 "{%0,%1,%2,%3}, {%4,%5,%6,%7}, {%8,%9}, {%0,%1,%2,%3};"
                 : "+f"(c0), "+f"(c1), "+f"(c2), "+f"(c3)
                 : "r"(a0), "r"(a1), "r"(a2), "r"(a3), "r"(b0), "r"(b1));
}

// split two fp32 (k-consecutive x0,x1) into packed bf16x2 hi and lo
__device__ __forceinline__ void split2(float x0, float x1, uint32_t& h, uint32_t& l) {
    uint32_t hh;
    asm("cvt.rn.bf16x2.f32 %0, %1, %2;" : "=r"(hh) : "f"(x1), "f"(x0));
    float h0 = __uint_as_float(hh << 16);
    float h1 = __uint_as_float(hh & 0xFFFF0000u);
    float l0 = x0 - h0, l1 = x1 - h1;
    uint32_t ll;
    asm("cvt.rn.bf16x2.f32 %0, %1, %2;" : "=r"(ll) : "f"(l1), "f"(l0));
    h = hh; l = ll;
}

// 3 mma terms: ah*bh + ah*bl + al*bh
#define MMA3(ACC, AH, AL, BH0, BH1, BL0, BL1) do { \
    mma_bf16((ACC)[0], (ACC)[1], (ACC)[2], (ACC)[3], \
             (AH)[0], (AH)[1], (AH)[2], (AH)[3], (BH0), (BH1)); \
    mma_bf16((ACC)[0], (ACC)[1], (ACC)[2], (ACC)[3], \
             (AH)[0], (AH)[1], (AH)[2], (AH)[3], (BL0), (BL1)); \
    mma_bf16((ACC)[0], (ACC)[1], (ACC)[2], (ACC)[3], \
             (AL)[0], (AL)[1], (AL)[2], (AL)[3], (BH0), (BH1)); \
} while (0)

// ================= 3xBF16 tensor-core GEMM (fp32-accurate) =================
#define TG_SMEM 65536

template<bool BIAS, bool RELU, bool RESID>
__global__ void __launch_bounds__(512, 1)
k_tgemm(const float* __restrict__ A, const float* __restrict__ B,
        const float* __restrict__ bias, const float* __restrict__ resid,
        float* __restrict__ C, int M, int N, int K) {
    extern __shared__ char smem[];
    const uint32_t sb = smem_u32(smem);
    const int tid = threadIdx.x, lane = tid & 31, wid = tid >> 5;
    const int wm = wid & 3, wn = wid >> 2;
    const int rowBase = blockIdx.y * 128;
    const int colBase = blockIdx.x * 128;

    float acc[2][4][4];
    #pragma unroll
    for (int i = 0; i < 2; i++)
        #pragma unroll
        for (int j = 0; j < 4; j++)
            #pragma unroll
            for (int r = 0; r < 4; r++) acc[i][j][r] = 0.f;

    const int a_m = tid >> 3, a_kq = tid & 7;
    const int b_n = tid & 127, b_q = tid >> 7;
    const int b_s = (b_n >> 3) & 7;

    const int a_m_in = (lane & 7) + ((lane >> 3) & 1) * 8;
    const int a_kb   = ((lane >> 4) & 1) * 16;
    const int b_n_in = (lane & 7) + ((lane >> 4) & 1) * 8;
    const int b_kb   = ((lane >> 3) & 1) * 16;

    const int nchunk = K >> 5;
    float4 pa[2], pb[2];

    {
        #pragma unroll
        for (int i = 0; i < 2; i++) {
            int m = a_m + 64 * i;
            pa[i] = *(const float4*)(A + (size_t)(rowBase + m) * K + a_kq * 4);
        }
        #pragma unroll
        for (int i = 0; i < 2; i++) {
            int kq = (b_q + 4 * i) ^ b_s;
            const float* bp = B + (size_t)(kq * 4) * N + colBase + b_n;
            pb[i] = make_float4(bp[0], bp[(size_t)N], bp[(size_t)2 * N], bp[(size_t)3 * N]);
        }
        #pragma unroll
        for (int i = 0; i < 2; i++) {
            int m = a_m + 64 * i;
            uint32_t h01, l01, h23, l23;
            split2(pa[i].x, pa[i].y, h01, l01);
            split2(pa[i].z, pa[i].w, h23, l23);
            uint32_t off = (uint32_t)(m * 64 + ((a_kq * 8) ^ (((m >> 1) & 3) << 4)));
            *(uint2*)(smem + off)        = make_uint2(h01, h23);
            *(uint2*)(smem + 8192 + off) = make_uint2(l01, l23);
        }
        #pragma unroll
        for (int i = 0; i < 2; i++) {
            int kq = (b_q + 4 * i) ^ b_s;
            uint32_t h01, l01, h23, l23;
            split2(pb[i].x, pb[i].y, h01, l01);
            split2(pb[i].z, pb[i].w, h23, l23);
            uint32_t off = (uint32_t)(b_n * 64 + ((kq * 8) ^ (((b_n >> 1) & 3) << 4)));
            *(uint2*)(smem + 16384 + off) = make_uint2(h01, h23);
            *(uint2*)(smem + 24576 + off) = make_uint2(l01, l23);
        }
    }
    __syncthreads();

    for (int c = 0; c < nchunk; c++) {
        const uint32_t base = sb + (uint32_t)(c & 1) * 32768;
        const uint32_t ah = base, al = base + 8192;
        const uint32_t bh = base + 16384, bl = base + 24576;

        if (c + 1 < nchunk) {
            int k0 = (c + 1) << 5;
            #pragma unroll
            for (int i = 0; i < 2; i++) {
                int m = a_m + 64 * i;
                pa[i] = *(const float4*)(A + (size_t)(rowBase + m) * K + k0 + a_kq * 4);
            }
            #pragma unroll
            for (int i = 0; i < 2; i++) {
                int kq = (b_q + 4 * i) ^ b_s;
                const float* bp = B + (size_t)(k0 + kq * 4) * N + colBase + b_n;
                pb[i] = make_float4(bp[0], bp[(size_t)N], bp[(size_t)2 * N], bp[(size_t)3 * N]);
            }
        }

        #pragma unroll
        for (int kt = 0; kt < 2; kt++) {
            uint32_t afh[2][4], afl[2][4], bfh[2][4], bfl[2][4];
            #pragma unroll
            for (int mt = 0; mt < 2; mt++) {
                int row = wm * 32 + mt * 16 + a_m_in;
                uint32_t off = (uint32_t)(row * 64 + ((kt * 32 + a_kb) ^ (((row >> 1) & 3) << 4)));
                ldsm_x4(afh[mt][0], afh[mt][1], afh[mt][2], afh[mt][3], ah + off);
                ldsm_x4(afl[mt][0], afl[mt][1], afl[mt][2], afl[mt][3], al + off);
            }
            #pragma unroll
            for (int ntp = 0; ntp < 2; ntp++) {
                int row = wn * 32 + ntp * 16 + b_n_in;
                uint32_t off = (uint32_t)(row * 64 + ((kt * 32 + b_kb) ^ (((row >> 1) & 3) << 4)));
                ldsm_x4(bfh[ntp][0], bfh[ntp][1], bfh[ntp][2], bfh[ntp][3], bh + off);
                ldsm_x4(bfl[ntp][0], bfl[ntp][1], bfl[ntp][2], bfl[ntp][3], bl + off);
            }
            #pragma unroll
            for (int mt = 0; mt < 2; mt++)
                #pragma unroll
                for (int nt = 0; nt < 4; nt++) {
                    const int np = nt >> 1, ne = (nt & 1) * 2;
                    MMA3(acc[mt][nt], afh[mt], afl[mt],
                         bfh[np][ne], bfh[np][ne + 1], bfl[np][ne], bfl[np][ne + 1]);
                }
        }

        // single sync per chunk: writes target buffer (c+1), whose readers all
        // finished before the collective sync at the end of chunk c-1.
        if (c + 1 < nchunk) {
            char* nb = smem + ((c + 1) & 1) * 32768;
            #pragma unroll
            for (int i = 0; i < 2; i++) {
                int m = a_m + 64 * i;
                uint32_t h01, l01, h23, l23;
                split2(pa[i].x, pa[i].y, h01, l01);
                split2(pa[i].z, pa[i].w, h23, l23);
                uint32_t off = (uint32_t)(m * 64 + ((a_kq * 8) ^ (((m >> 1) & 3) << 4)));
                *(uint2*)(nb + off)        = make_uint2(h01, h23);
                *(uint2*)(nb + 8192 + off) = make_uint2(l01, l23);
            }
            #pragma unroll
            for (int i = 0; i < 2; i++) {
                int kq = (b_q + 4 * i) ^ b_s;
                uint32_t h01, l01, h23, l23;
                split2(pb[i].x, pb[i].y, h01, l01);
                split2(pb[i].z, pb[i].w, h23, l23);
                uint32_t off = (uint32_t)(b_n * 64 + ((kq * 8) ^ (((b_n >> 1) & 3) << 4)));
                *(uint2*)(nb + 16384 + off) = make_uint2(h01, h23);
                *(uint2*)(nb + 24576 + off) = make_uint2(l01, l23);
            }
            __syncthreads();
        }
    }

    const int row0 = lane >> 2, col0 = (lane & 3) * 2;
    #pragma unroll
    for (int mt = 0; mt < 2; mt++) {
        #pragma unroll
        for (int nt = 0; nt < 4; nt++) {
            int gm = rowBase + wm * 32 + mt * 16 + row0;
            int gn = colBase + wn * 32 + nt * 8 + col0;
            float o0 = acc[mt][nt][0], o1 = acc[mt][nt][1];
            float o2 = acc[mt][nt][2], o3 = acc[mt][nt][3];
            if (BIAS) {
                float bv0 = bias[gn], bv1 = bias[gn + 1];
                o0 += bv0; o1 += bv1; o2 += bv0; o3 += bv1;
            }
            size_t p0 = (size_t)gm * N + gn;
            size_t p1 = (size_t)(gm + 8) * N + gn;
            if (RESID) {
                float2 r0v = *(const float2*)(resid + p0);
                float2 r1v = *(const float2*)(resid + p1);
                o0 += r0v.x; o1 += r0v.y; o2 += r1v.x; o3 += r1v.y;
            }
            if (RELU) {
                o0 = fmaxf(o0, 0.f); o1 = fmaxf(o1, 0.f);
                o2 = fmaxf(o2, 0.f); o3 = fmaxf(o3, 0.f);
            }
            *(float2*)(C + p0) = make_float2(o0, o1);
            *(float2*)(C + p1) = make_float2(o2, o3);
        }
    }
}

// ================= tensor-core attention scores =================
// Fully-masked tiles (k0 > q0+127) are never read downstream (k_av only reads
// cols < q0+128; softmax is variable-length) — early return, no fill.
#define SC_SMEM 65536

__global__ void __launch_bounds__(512, 1)
k_scores_t(const float* __restrict__ q, const float* __restrict__ k) {
    const int bh = blockIdx.z, b = bh >> 4, h = bh & 15;
    const int q0 = blockIdx.y * 128, k0 = blockIdx.x * 128;
    if (k0 > q0 + 127) return;

    extern __shared__ char smem[];
    const uint32_t sb = smem_u32(smem);
    const int tid = threadIdx.x, lane = tid & 31, wid = tid >> 5;
    const int wm = wid & 3, wn = wid >> 2;

    {
        #pragma unroll
        for (int i = 0; i < 4; i++) {
            int idx = tid + 512 * i;
            int row = idx >> 4, dq = idx & 15;
            float4 v = *(const float4*)(q + (size_t)(b * TT + q0 + row) * EE + h * DD + dq * 4);
            uint32_t h01, l01, h23, l23;
            split2(v.x, v.y, h01, l01);
            split2(v.z, v.w, h23, l23);
            uint32_t off = (uint32_t)(row * 128 + ((dq * 8) ^ ((row & 7) << 4)));
            *(uint2*)(smem + off)         = make_uint2(h01, h23);
            *(uint2*)(smem + 16384 + off) = make_uint2(l01, l23);
        }
        #pragma unroll
        for (int i = 0; i < 4; i++) {
            int idx = tid + 512 * i;
            int row = idx >> 4, dq = idx & 15;
            float4 v = *(const float4*)(k + (size_t)(b * TT + k0 + row) * EE + h * DD + dq * 4);
            uint32_t h01, l01, h23, l23;
            split2(v.x, v.y, h01, l01);
            split2(v.z, v.w, h23, l23);
            uint32_t off = (uint32_t)(row * 128 + ((dq * 8) ^ ((row & 7) << 4)));
            *(uint2*)(smem + 32768 + off) = make_uint2(h01, h23);
            *(uint2*)(smem + 49152 + off) = make_uint2(l01, l23);
        }
    }
    __syncthreads();

    const int a_m_in = (lane & 7) + ((lane >> 3) & 1) * 8;
    const int a_kb   = ((lane >> 4) & 1) * 16;
    const int b_n_in = (lane & 7) + ((lane >> 4) & 1) * 8;
    const int b_kb   = ((lane >> 3) & 1) * 16;

    float acc[2][4][4];
    #pragma unroll
    for (int i = 0; i < 2; i++)
        #pragma unroll
        for (int j = 0; j < 4; j++)
            #pragma unroll
            for (int r = 0; r < 4; r++) acc[i][j][r] = 0.f;

    #pragma unroll
    for (int kt = 0; kt < 4; kt++) {
        uint32_t afh[2][4], afl[2][4], bfh[2][4], bfl[2][4];
        #pragma unroll
        for (int mt = 0; mt < 2; mt++) {
            int row = wm * 32 + mt * 16 + a_m_in;
            uint32_t off = (uint32_t)(row * 128 + ((kt * 32 + a_kb) ^ ((row & 7) << 4)));
            ldsm_x4(afh[mt][0], afh[mt][1], afh[mt][2], afh[mt][3], sb + off);
            ldsm_x4(afl[mt][0], afl[mt][1], afl[mt][2], afl[mt][3], sb + 16384 + off);
        }
        #pragma unroll
        for (int ntp = 0; ntp < 2; ntp++) {
            int row = wn * 32 + ntp * 16 + b_n_in;
            uint32_t off = (uint32_t)(row * 128 + ((kt * 32 + b_kb) ^ ((row & 7) << 4)));
            ldsm_x4(bfh[ntp][0], bfh[ntp][1], bfh[ntp][2], bfh[ntp][3], sb + 32768 + off);
            ldsm_x4(bfl[ntp][0], bfl[ntp][1], bfl[ntp][2], bfl[ntp][3], sb + 49152 + off);
        }
        #pragma unroll
        for (int mt = 0; mt < 2; mt++)
            #pragma unroll
            for (int nt = 0; nt < 4; nt++) {
                const int np = nt >> 1, ne = (nt & 1) * 2;
                MMA3(acc[mt][nt], afh[mt], afl[mt],
                     bfh[np][ne], bfh[np][ne + 1], bfl[np][ne], bfl[np][ne + 1]);
            }
    }

    const int row0 = lane >> 2, col0 = (lane & 3) * 2;
    #pragma unroll
    for (int mt = 0; mt < 2; mt++) {
        #pragma unroll
        for (int nt = 0; nt < 4; nt++) {
            int qi = q0 + wm * 32 + mt * 16 + row0;
            int kj = k0 + wn * 32 + nt * 8 + col0;
            float s0 = (kj     <= qi) ? acc[mt][nt][0] * 0.125f : -1e30f;
            float s1 = (kj + 1 <= qi) ? acc[mt][nt][1] * 0.125f : -1e30f;
            float s2 = (kj     <= qi + 8) ? acc[mt][nt][2] * 0.125f : -1e30f;
            float s3 = (kj + 1 <= qi + 8) ? acc[mt][nt][3] * 0.125f : -1e30f;
            *(float2*)(g_S + ((size_t)bh * TT + qi) * TT + kj)       = make_float2(s0, s1);
            *(float2*)(g_S + ((size_t)bh * TT + qi + 8) * TT + kj)   = make_float2(s2, s3);
        }
    }
}

// ================= tensor-core O = P @ V =================
#define AV_SMEM 49152

__global__ void __launch_bounds__(256, 1)
k_av_t(const float* __restrict__ v, float* __restrict__ o) {
    extern __shared__ char smem[];
    const uint32_t sb = smem_u32(smem);
    const int bh = blockIdx.y, b = bh >> 4, h = bh & 15;
    const int q0 = blockIdx.x * 128;
    const int tid = threadIdx.x, lane = tid & 31, wid = tid >> 5;
    const int wm = wid & 3, wn = wid >> 2;

    const int a_m = tid >> 3, a_kq = tid & 7;
    const int b_n = tid & 63;
    const int b_q0 = tid >> 6;
    const int b_s = (b_n >> 3) & 7;

    const int a_m_in = (lane & 7) + ((lane >> 3) & 1) * 8;
    const int a_kb   = ((lane >> 4) & 1) * 16;
    const int b_n_in = (lane & 7) + ((lane >> 4) & 1) * 8;
    const int b_kb   = ((lane >> 3) & 1) * 16;

    float acc[2][4][4];
    #pragma unroll
    for (int i = 0; i < 2; i++)
        #pragma unroll
        for (int j = 0; j < 4; j++)
            #pragma unroll
            for (int r = 0; r < 4; r++) acc[i][j][r] = 0.f;

    const int nchunk = (q0 + 128) >> 5;
    const float* Prow = g_S + ((size_t)bh * TT + q0) * TT;
    float4 pa[4], pb[2];

    {
        #pragma unroll
        for (int i = 0; i < 4; i++) {
            int idx = tid + 256 * i;
            int m = idx >> 3, kq = idx & 7;
            pa[i] = *(const float4*)(Prow + (size_t)m * TT + kq * 4);
        }
        #pragma unroll
        for (int i = 0; i < 2; i++) {
            int kq = (b_q0 + 4 * i) ^ b_s;
            const float* bp = v + (size_t)(b * TT + kq * 4) * EE + h * DD + b_n;
            pb[i] = make_float4(bp[0], bp[(size_t)EE], bp[(size_t)2 * EE], bp[(size_t)3 * EE]);
        }
        #pragma unroll
        for (int i = 0; i < 4; i++) {
            int idx = tid + 256 * i;
            int m = idx >> 3, kq = idx & 7;
            uint32_t h01, l01, h23, l23;
            split2(pa[i].x, pa[i].y, h01, l01);
            split2(pa[i].z, pa[i].w, h23, l23);
            uint32_t off = (uint32_t)(m * 64 + ((kq * 8) ^ (((m >> 1) & 3) << 4)));
            *(uint2*)(smem + off)        = make_uint2(h01, h23);
            *(uint2*)(smem + 8192 + off) = make_uint2(l01, l23);
        }
        #pragma unroll
        for (int i = 0; i < 2; i++) {
            int kq = (b_q0 + 4 * i) ^ b_s;
            uint32_t h01, l01, h23, l23;
            split2(pb[i].x, pb[i].y, h01, l01);
            split2(pb[i].z, pb[i].w, h23, l23);
            uint32_t off = (uint32_t)(b_n * 64 + ((kq * 8) ^ (((b_n >> 1) & 3) << 4)));
            *(uint2*)(smem + 16384 + off) = make_uint2(h01, h23);
            *(uint2*)(smem + 20480 + off) = make_uint2(l01, l23);
        }
    }
    __syncthreads();

    for (int c = 0; c < nchunk; c++) {
        const uint32_t base = sb + (uint32_t)(c & 1) * 24576;
        const uint32_t ph = base, pl = base + 8192;
        const uint32_t vh = base + 16384, vl = base + 20480;

        if (c + 1 < nchunk) {
            int j0 = (c + 1) << 5;
            #pragma unroll
            for (int i = 0; i < 4; i++) {
                int idx = tid + 256 * i;
                int m = idx >> 3, kq = idx & 7;
                pa[i] = *(const float4*)(Prow + (size_t)m * TT + j0 + kq * 4);
            }
            #pragma unroll
            for (int i = 0; i < 2; i++) {
                int kq = (b_q0 + 4 * i) ^ b_s;
                const float* bp = v + (size_t)(b * TT + j0 + kq * 4) * EE + h * DD + b_n;
                pb[i] = make_float4(bp[0], bp[(size_t)EE], bp[(size_t)2 * EE], bp[(size_t)3 * EE]);
            }
        }

        #pragma unroll
        for (int kt = 0; kt < 2; kt++) {
            uint32_t afh[2][4], afl[2][4], bfh[2][4], bfl[2][4];
            #pragma unroll
            for (int mt = 0; mt < 2; mt++) {
                int row = wm * 32 + mt * 16 + a_m_in;
                uint32_t off = (uint32_t)(row * 64 + ((kt * 32 + a_kb) ^ (((row >> 1) & 3) << 4)));
                ldsm_x4(afh[mt][0], afh[mt][1], afh[mt][2], afh[mt][3], ph + off);
                ldsm_x4(afl[mt][0], afl[mt][1], afl[mt][2], afl[mt][3], pl + off);
            }
            #pragma unroll
            for (int ntp = 0; ntp < 2; ntp++) {
                int row = wn * 32 + ntp * 16 + b_n_in;
                uint32_t off = (uint32_t)(row * 64 + ((kt * 32 + b_kb) ^ (((row >> 1) & 3) << 4)));
                ldsm_x4(bfh[ntp][0], bfh[ntp][1], bfh[ntp][2], bfh[ntp][3], vh + off);
                ldsm_x4(bfl[ntp][0], bfl[ntp][1], bfl[ntp][2], bfl[ntp][3], vl + off);
            }
            #pragma unroll
            for (int mt = 0; mt < 2; mt++)
                #pragma unroll
                for (int nt = 0; nt < 4; nt++) {
                    const int np = nt >> 1, ne = (nt & 1) * 2;
                    MMA3(acc[mt][nt], afh[mt], afl[mt],
                         bfh[np][ne], bfh[np][ne + 1], bfl[np][ne], bfl[np][ne + 1]);
                }
        }

        if (c + 1 < nchunk) {
            char* nb = smem + ((c + 1) & 1) * 24576;
            #pragma unroll
            for (int i = 0; i < 4; i++) {
                int idx = tid + 256 * i;
                int m = idx >> 3, kq = idx & 7;
                uint32_t h01, l01, h23, l23;
                split2(pa[i].x, pa[i].y, h01, l01);
                split2(pa[i].z, pa[i].w, h23, l23);
                uint32_t off = (uint32_t)(m * 64 + ((kq * 8) ^ (((m >> 1) & 3) << 4)));
                *(uint2*)(nb + off)        = make_uint2(h01, h23);
                *(uint2*)(nb + 8192 + off) = make_uint2(l01, l23);
            }
            #pragma unroll
            for (int i = 0; i < 2; i++) {
                int kq = (b_q0 + 4 * i) ^ b_s;
                uint32_t h01, l01, h23, l23;
                split2(pb[i].x, pb[i].y, h01, l01);
                split2(pb[i].z, pb[i].w, h23, l23);
                uint32_t off = (uint32_t)(b_n * 64 + ((kq * 8) ^ (((b_n >> 1) & 3) << 4)));
                *(uint2*)(nb + 16384 + off) = make_uint2(h01, h23);
                *(uint2*)(nb + 20480 + off) = make_uint2(l01, l23);
            }
            __syncthreads();
        }
    }

    const int row0 = lane >> 2, col0 = (lane & 3) * 2;
    #pragma unroll
    for (int mt = 0; mt < 2; mt++) {
        #pragma unroll
        for (int nt = 0; nt < 4; nt++) {
            int gm = q0 + wm * 32 + mt * 16 + row0;
            int gn = wn * 32 + nt * 8 + col0;
            size_t p0 = (size_t)(b * TT + gm) * EE + h * DD + gn;
            size_t p1 = (size_t)(b * TT + gm + 8) * EE + h * DD + gn;
            *(float2*)(o + p0) = make_float2(acc[mt][nt][0], acc[mt][nt][1]);
            *(float2*)(o + p1) = make_float2(acc[mt][nt][2], acc[mt][nt][3]);
        }
    }
}

// ---------------- embed ----------------
__global__ void k_embed(const int* __restrict__ idx, const float* __restrict__ tok,
                        const float* __restrict__ pos, float* __restrict__ x) {
    int r = blockIdx.x;
    int t = r & (TT - 1);
    int tokid = idx[r];
    const float4* te = (const float4*)(tok + (size_t)tokid * EE);
    const float4* pe = (const float4*)(pos + (size_t)t * EE);
    float4* xr = (float4*)(x + (size_t)r * EE);
    int c = threadIdx.x;
    float4 a = te[c], b = pe[c];
    xr[c] = make_float4(a.x + b.x, a.y + b.y, a.z + b.z, a.w + b.w);
}

// ---------------- block reduce ----------------
__device__ __forceinline__ float blockReduceSum(float val, float* red) {
    int tid = threadIdx.x;
    #pragma unroll
    for (int o = 16; o; o >>= 1) val += __shfl_xor_sync(0xffffffffu, val, o);
    if ((tid & 31) == 0) red[tid >> 5] = val;
    __syncthreads();
    if (tid < 32) {
        float v = (tid < 8) ? red[tid] : 0.f;
        #pragma unroll
        for (int o = 4; o; o >>= 1) v += __shfl_xor_sync(0xffffffffu, v, o);
        if (tid == 0) red[0] = v;
    }
    __syncthreads();
    float r = red[0];
    __syncthreads();
    return r;
}

// ---------------- layernorm ----------------
__global__ void k_ln(const float* __restrict__ x, const float* __restrict__ g,
                     const float* __restrict__ b, float* __restrict__ out) {
    __shared__ float red[32];
    int row = blockIdx.x, tid = threadIdx.x;
    const float* xr = x + (size_t)row * EE;
    float v[4];
    float s = 0.f;
    #pragma unroll
    for (int i = 0; i < 4; i++) { v[i] = xr[tid + 256 * i]; s += v[i]; }
    s = blockReduceSum(s, red);
    float mean = s * (1.f / EE);
    float s2 = 0.f;
    #pragma unroll
    for (int i = 0; i < 4; i++) { float d = v[i] - mean; s2 += d * d; }
    s2 = blockReduceSum(s2, red);
    float inv = rsqrtf(s2 * (1.f / EE) + 1e-5f);
    #pragma unroll
    for (int i = 0; i < 4; i++) {
        int c = tid + 256 * i;
        out[(size_t)row * EE + c] = (v[i] - mean) * inv * g[c] + b[c];
    }
}

// ---------------- softmax per row (variable length) ----------------
// Row q only has valid scores in cols [0, q]; cols beyond (q|127) are
// never written by k_scores_t and never read by k_av_t — process L=(q|127)+1.
__global__ void k_softmax() {
    __shared__ float red[32];
    int row = blockIdx.x;
    int qpos = row & (TT - 1);
    int L = (qpos | 127) + 1;
    float* r = g_S + (size_t)row * TT;
    int tid = threadIdx.x;
    float v[4], m = -1e30f;
    #pragma unroll
    for (int i = 0; i < 4; i++) {
        int c = tid + 256 * i;
        v[i] = (c < L) ? r[c] : -1e30f;
        m = fmaxf(m, v[i]);
    }
    #pragma unroll
    for (int o = 16; o; o >>= 1) m = fmaxf(m, __shfl_xor_sync(0xffffffffu, m, o));
    if ((tid & 31) == 0) red[tid >> 5] = m;
    __syncthreads();
    if (tid < 32) {
        float t = (tid < 8) ? red[tid] : -1e30f;
        #pragma unroll
        for (int o = 4; o; o >>= 1) t = fmaxf(t, __shfl_xor_sync(0xffffffffu, t, o));
        if (tid == 0) red[0] = t;
    }
    __syncthreads();
    m = red[0];
    __syncthreads();
    float s = 0.f;
    #pragma unroll
    for (int i = 0; i < 4; i++) { v[i] = __expf(v[i] - m); s += v[i]; }
    s = blockReduceSum(s, red);
    float inv = 1.f / s;
    #pragma unroll
    for (int i = 0; i < 4; i++) {
        int c = tid + 256 * i;
        if (c < L) r[c] = v[i] * inv;
    }
}

// ---------------- host orchestration ----------------
extern "C" void kernel_launch(void* const* d_in, const int* in_sizes, int n_in,
                              void* d_out, int out_size) {
    const int*   idx  = (const int*)  d_in[0];
    const float* tok  = (const float*)d_in[1];
    const float* pos  = (const float*)d_in[2];
    const float* Wq   = (const float*)d_in[3];
    const float* Wk   = (const float*)d_in[4];
    const float* Wv   = (const float*)d_in[5];
    const float* Wp   = (const float*)d_in[6];
    const float* bp   = (const float*)d_in[7];
    const float* g1   = (const float*)d_in[8];
    const float* b1   = (const float*)d_in[9];
    const float* g2   = (const float*)d_in[10];
    const float* b2   = (const float*)d_in[11];
    const float* W1   = (const float*)d_in[12];
    const float* bf1  = (const float*)d_in[13];
    const float* W2   = (const float*)d_in[14];
    const float* bf2  = (const float*)d_in[15];
    const float* gf   = (const float*)d_in[16];
    const float* bff  = (const float*)d_in[17];
    const float* Wlm  = (const float*)d_in[18];
    const float* blm  = (const float*)d_in[19];
    float* out = (float*)d_out;

    float *x, *h, *q, *k, *v, *o, *ff;
    cudaGetSymbolAddress((void**)&x,  g_x);
    cudaGetSymbolAddress((void**)&h,  g_h);
    cudaGetSymbolAddress((void**)&q,  g_q);
    cudaGetSymbolAddress((void**)&k,  g_k);
    cudaGetSymbolAddress((void**)&v,  g_v);
    cudaGetSymbolAddress((void**)&o,  g_o);
    cudaGetSymbolAddress((void**)&ff, g_ff);

    cudaFuncSetAttribute(k_tgemm<false,false,false>,
                         cudaFuncAttributeMaxDynamicSharedMemorySize, TG_SMEM);
    cudaFuncSetAttribute(k_tgemm<true,false,true>,
                         cudaFuncAttributeMaxDynamicSharedMemorySize, TG_SMEM);
    cudaFuncSetAttribute(k_tgemm<true,true,false>,
                         cudaFuncAttributeMaxDynamicSharedMemorySize, TG_SMEM);
    cudaFuncSetAttribute(k_tgemm<true,false,false>,
                         cudaFuncAttributeMaxDynamicSharedMemorySize, TG_SMEM);
    cudaFuncSetAttribute(k_scores_t,
                         cudaFuncAttributeMaxDynamicSharedMemorySize, SC_SMEM);
    cudaFuncSetAttribute(k_av_t,
                         cudaFuncAttributeMaxDynamicSharedMemorySize, AV_SMEM);

    k_embed<<<RR, 256>>>(idx, tok, pos, x);

    dim3 gEE(EE / 128, RR / 128);      // (8, 16)
    dim3 gFF(FF / 128, RR / 128);      // (32, 16)
    dim3 gLM(VV / 128, RR / 128);      // (250, 16)

    for (int l = 0; l < LL; l++) {
        const float* wq = Wq + (size_t)l * EE * EE;
        const float* wk = Wk + (size_t)l * EE * EE;
        const float* wv = Wv + (size_t)l * EE * EE;
        const float* wp = Wp + (size_t)l * EE * EE;
        const float* w1 = W1 + (size_t)l * EE * FF;
        const float* w2 = W2 + (size_t)l * FF * EE;

        k_ln<<<RR, 256>>>(x, g1 + l * EE, b1 + l * EE, h);
        k_tgemm<false,false,false><<<gEE, 512, TG_SMEM>>>(h, wq, nullptr, nullptr, q, RR, EE, EE);
        k_tgemm<false,false,false><<<gEE, 512, TG_SMEM>>>(h, wk, nullptr, nullptr, k, RR, EE, EE);
        k_tgemm<false,false,false><<<gEE, 512, TG_SMEM>>>(h, wv, nullptr, nullptr, v, RR, EE, EE);

        k_scores_t<<<dim3(8, 8, 32), 512, SC_SMEM>>>(q, k);
        k_softmax<<<BB * HH * TT, 256>>>();
        k_av_t<<<dim3(8, 32), 256, AV_SMEM>>>(v, o);

        // x = x + o @ Wp + bp
        k_tgemm<true,false,true><<<gEE, 512, TG_SMEM>>>(o, wp, bp + l * EE, x, x, RR, EE, EE);

        k_ln<<<RR, 256>>>(x, g2 + l * EE, b2 + l * EE, h);
        // ff = relu(h @ W1 + bf1)
        k_tgemm<true,true,false><<<gFF, 512, TG_SMEM>>>(h, w1, bf1 + l * FF, nullptr, ff, RR, FF, EE);
        // x = x + ff @ W2 + bf2
        k_tgemm<true,false,true><<<gEE, 512, TG_SMEM>>>(ff, w2, bf2 + l * EE, x, x, RR, EE, FF);
    }

    k_ln<<<RR, 256>>>(x, gf, bff, h);
    k_tgemm<true,false,false><<<gLM, 512, TG_SMEM>>>(h, Wlm, blm, nullptr, out, RR, VV, EE);
}

// round 12
// speedup vs baseline: 3.4421x; 1.1030x over previous
#include <cuda_runtime.h>
#include <cstdint>

// ---------------- problem constants ----------------
#define BB 2
#define TT 1024
#define EE 1024
#define HH 16
#define DD 64
#define LL 6
#define FF 4096
#define VV 32000
#define RR (BB*TT)   // 2048 token rows

// ---------------- device scratch (static, no allocations) ----------------
__device__ float g_x [RR*EE];
__device__ float g_h [RR*EE];
__device__ float g_q [RR*EE];
__device__ float g_k [RR*EE];
__device__ float g_v [RR*EE];
__device__ float g_o [RR*EE];
__device__ float g_ff[RR*FF];
__device__ float g_S [(size_t)BB*HH*TT*TT];   // 134 MB attention scores

__device__ __forceinline__ uint32_t smem_u32(const void* p) {
    uint32_t a;
    asm("{ .reg .u64 t; cvta.to.shared.u64 t, %1; cvt.u32.u64 %0, t; }"
        : "=r"(a) : "l"(p));
    return a;
}

__device__ __forceinline__ void ldsm_x4(uint32_t& r0, uint32_t& r1,
                                        uint32_t& r2, uint32_t& r3, uint32_t addr) {
    asm volatile("ldmatrix.sync.aligned.m8n8.x4.shared.b16 {%0,%1,%2,%3}, [%4];"
                 : "=r"(r0), "=r"(r1), "=r"(r2), "=r"(r3) : "r"(addr));
}

__device__ __forceinline__ void mma_bf16(float& c0, float& c1, float& c2, float& c3,
                                         uint32_t a0, uint32_t a1, uint32_t a2, uint32_t a3,
                                         uint32_t b0, uint32_t b1) {
    asm volatile("mma.sync.aligned.m16n8k16.row.col.f32.bf16.bf16.f32 "
                 "{%0,%1,%2,%3}, {%4,%5,%6,%7}, {%8,%9}, {%0,%1,%2,%3};"
                 : "+f"(c0), "+f"(c1), "+f"(c2), "+f"(c3)
                 : "r"(a0), "r"(a1), "r"(a2), "r"(a3), "r"(b0), "r"(b1));
}

// split two fp32 (k-consecutive x0,x1) into packed bf16x2 hi and lo
__device__ __forceinline__ void split2(float x0, float x1, uint32_t& h, uint32_t& l) {
    uint32_t hh;
    asm("cvt.rn.bf16x2.f32 %0, %1, %2;" : "=r"(hh) : "f"(x1), "f"(x0));
    float h0 = __uint_as_float(hh << 16);
    float h1 = __uint_as_float(hh & 0xFFFF0000u);
    float l0 = x0 - h0, l1 = x1 - h1;
    uint32_t ll;
    asm("cvt.rn.bf16x2.f32 %0, %1, %2;" : "=r"(ll) : "f"(l1), "f"(l0));
    h = hh; l = ll;
}

// 3 mma terms: ah*bh + ah*bl + al*bh
#define MMA3(ACC, AH, AL, BH0, BH1, BL0, BL1) do { \
    mma_bf16((ACC)[0], (ACC)[1], (ACC)[2], (ACC)[3], \
             (AH)[0], (AH)[1], (AH)[2], (AH)[3], (BH0), (BH1)); \
    mma_bf16((ACC)[0], (ACC)[1], (ACC)[2], (ACC)[3], \
             (AH)[0], (AH)[1], (AH)[2], (AH)[3], (BL0), (BL1)); \
    mma_bf16((ACC)[0], (ACC)[1], (ACC)[2], (ACC)[3], \
             (AL)[0], (AL)[1], (AL)[2], (AL)[3], (BH0), (BH1)); \
} while (0)

// ================= 3xBF16 tensor-core GEMM (fp32-accurate) =================
// C[M,N] = A[M,K] @ B[K,N] (+bias)(+resid)(relu). 128x64 CTA tile, BK=32.
// grid = (N/64, M/128), 256 threads (8 warps, 4x2 grid of 32x32 warp tiles).
// SMEM per buffer (24KB): Ah@0(8K), Al@8K, Bh@16K(4K), Bl@20K. Double: 48KB.
// 2 CTAs/SM via __launch_bounds__(256,2): co-resident CTAs hide each other's
// sync/memory stalls.
#define TG_SMEM 49152

template<bool BIAS, bool RELU, bool RESID>
__global__ void __launch_bounds__(256, 2)
k_tgemm(const float* __restrict__ A, const float* __restrict__ B,
        const float* __restrict__ bias, const float* __restrict__ resid,
        float* __restrict__ C, int M, int N, int K) {
    extern __shared__ char smem[];
    const uint32_t sb = smem_u32(smem);
    const int tid = threadIdx.x, lane = tid & 31, wid = tid >> 5;
    const int wm = wid & 3, wn = wid >> 2;           // 4 x 2 warp grid
    const int rowBase = blockIdx.y * 128;
    const int colBase = blockIdx.x * 64;

    float acc[2][4][4];
    #pragma unroll
    for (int i = 0; i < 2; i++)
        #pragma unroll
        for (int j = 0; j < 4; j++)
            #pragma unroll
            for (int r = 0; r < 4; r++) acc[i][j][r] = 0.f;

    const int a_m = tid >> 3, a_kq = tid & 7;        // A: float4 at (m + 32i, kq*4)
    const int b_n = tid & 63, b_q0 = tid >> 6;       // B: col n, kq = (q0+4i)^s
    const int b_s = (b_n >> 3) & 7;

    const int a_m_in = (lane & 7) + ((lane >> 3) & 1) * 8;
    const int a_kb   = ((lane >> 4) & 1) * 16;
    const int b_n_in = (lane & 7) + ((lane >> 4) & 1) * 8;
    const int b_kb   = ((lane >> 3) & 1) * 16;

    const int nchunk = K >> 5;
    float4 pa[4], pb[2];

    {
        #pragma unroll
        for (int i = 0; i < 4; i++) {
            int m = a_m + 32 * i;
            pa[i] = *(const float4*)(A + (size_t)(rowBase + m) * K + a_kq * 4);
        }
        #pragma unroll
        for (int i = 0; i < 2; i++) {
            int kq = (b_q0 + 4 * i) ^ b_s;
            const float* bp = B + (size_t)(kq * 4) * N + colBase + b_n;
            pb[i] = make_float4(bp[0], bp[(size_t)N], bp[(size_t)2 * N], bp[(size_t)3 * N]);
        }
        #pragma unroll
        for (int i = 0; i < 4; i++) {
            int m = a_m + 32 * i;
            uint32_t h01, l01, h23, l23;
            split2(pa[i].x, pa[i].y, h01, l01);
            split2(pa[i].z, pa[i].w, h23, l23);
            uint32_t off = (uint32_t)(m * 64 + ((a_kq * 8) ^ (((m >> 1) & 3) << 4)));
            *(uint2*)(smem + off)        = make_uint2(h01, h23);
            *(uint2*)(smem + 8192 + off) = make_uint2(l01, l23);
        }
        #pragma unroll
        for (int i = 0; i < 2; i++) {
            int kq = (b_q0 + 4 * i) ^ b_s;
            uint32_t h01, l01, h23, l23;
            split2(pb[i].x, pb[i].y, h01, l01);
            split2(pb[i].z, pb[i].w, h23, l23);
            uint32_t off = (uint32_t)(b_n * 64 + ((kq * 8) ^ (((b_n >> 1) & 3) << 4)));
            *(uint2*)(smem + 16384 + off) = make_uint2(h01, h23);
            *(uint2*)(smem + 20480 + off) = make_uint2(l01, l23);
        }
    }
    __syncthreads();

    for (int c = 0; c < nchunk; c++) {
        const uint32_t base = sb + (uint32_t)(c & 1) * 24576;
        const uint32_t ah = base, al = base + 8192;
        const uint32_t bh = base + 16384, bl = base + 20480;

        if (c + 1 < nchunk) {
            int k0 = (c + 1) << 5;
            #pragma unroll
            for (int i = 0; i < 4; i++) {
                int m = a_m + 32 * i;
                pa[i] = *(const float4*)(A + (size_t)(rowBase + m) * K + k0 + a_kq * 4);
            }
            #pragma unroll
            for (int i = 0; i < 2; i++) {
                int kq = (b_q0 + 4 * i) ^ b_s;
                const float* bp = B + (size_t)(k0 + kq * 4) * N + colBase + b_n;
                pb[i] = make_float4(bp[0], bp[(size_t)N], bp[(size_t)2 * N], bp[(size_t)3 * N]);
            }
        }

        #pragma unroll
        for (int kt = 0; kt < 2; kt++) {
            uint32_t afh[2][4], afl[2][4], bfh[2][4], bfl[2][4];
            #pragma unroll
            for (int mt = 0; mt < 2; mt++) {
                int row = wm * 32 + mt * 16 + a_m_in;
                uint32_t off = (uint32_t)(row * 64 + ((kt * 32 + a_kb) ^ (((row >> 1) & 3) << 4)));
                ldsm_x4(afh[mt][0], afh[mt][1], afh[mt][2], afh[mt][3], ah + off);
                ldsm_x4(afl[mt][0], afl[mt][1], afl[mt][2], afl[mt][3], al + off);
            }
            #pragma unroll
            for (int ntp = 0; ntp < 2; ntp++) {
                int row = wn * 32 + ntp * 16 + b_n_in;
                uint32_t off = (uint32_t)(row * 64 + ((kt * 32 + b_kb) ^ (((row >> 1) & 3) << 4)));
                ldsm_x4(bfh[ntp][0], bfh[ntp][1], bfh[ntp][2], bfh[ntp][3], bh + off);
                ldsm_x4(bfl[ntp][0], bfl[ntp][1], bfl[ntp][2], bfl[ntp][3], bl + off);
            }
            #pragma unroll
            for (int mt = 0; mt < 2; mt++)
                #pragma unroll
                for (int nt = 0; nt < 4; nt++) {
                    const int np = nt >> 1, ne = (nt & 1) * 2;
                    MMA3(acc[mt][nt], afh[mt], afl[mt],
                         bfh[np][ne], bfh[np][ne + 1], bfl[np][ne], bfl[np][ne + 1]);
                }
        }

        if (c + 1 < nchunk) {
            char* nb = smem + ((c + 1) & 1) * 24576;
            #pragma unroll
            for (int i = 0; i < 4; i++) {
                int m = a_m + 32 * i;
                uint32_t h01, l01, h23, l23;
                split2(pa[i].x, pa[i].y, h01, l01);
                split2(pa[i].z, pa[i].w, h23, l23);
                uint32_t off = (uint32_t)(m * 64 + ((a_kq * 8) ^ (((m >> 1) & 3) << 4)));
                *(uint2*)(nb + off)        = make_uint2(h01, h23);
                *(uint2*)(nb + 8192 + off) = make_uint2(l01, l23);
            }
            #pragma unroll
            for (int i = 0; i < 2; i++) {
                int kq = (b_q0 + 4 * i) ^ b_s;
                uint32_t h01, l01, h23, l23;
                split2(pb[i].x, pb[i].y, h01, l01);
                split2(pb[i].z, pb[i].w, h23, l23);
                uint32_t off = (uint32_t)(b_n * 64 + ((kq * 8) ^ (((b_n >> 1) & 3) << 4)));
                *(uint2*)(nb + 16384 + off) = make_uint2(h01, h23);
                *(uint2*)(nb + 20480 + off) = make_uint2(l01, l23);
            }
            __syncthreads();
        }
    }

    const int row0 = lane >> 2, col0 = (lane & 3) * 2;
    #pragma unroll
    for (int mt = 0; mt < 2; mt++) {
        #pragma unroll
        for (int nt = 0; nt < 4; nt++) {
            int gm = rowBase + wm * 32 + mt * 16 + row0;
            int gn = colBase + wn * 32 + nt * 8 + col0;
            float o0 = acc[mt][nt][0], o1 = acc[mt][nt][1];
            float o2 = acc[mt][nt][2], o3 = acc[mt][nt][3];
            if (BIAS) {
                float bv0 = bias[gn], bv1 = bias[gn + 1];
                o0 += bv0; o1 += bv1; o2 += bv0; o3 += bv1;
            }
            size_t p0 = (size_t)gm * N + gn;
            size_t p1 = (size_t)(gm + 8) * N + gn;
            if (RESID) {
                float2 r0v = *(const float2*)(resid + p0);
                float2 r1v = *(const float2*)(resid + p1);
                o0 += r0v.x; o1 += r0v.y; o2 += r1v.x; o3 += r1v.y;
            }
            if (RELU) {
                o0 = fmaxf(o0, 0.f); o1 = fmaxf(o1, 0.f);
                o2 = fmaxf(o2, 0.f); o3 = fmaxf(o3, 0.f);
            }
            *(float2*)(C + p0) = make_float2(o0, o1);
            *(float2*)(C + p1) = make_float2(o2, o3);
        }
    }
}

// ================= tensor-core attention scores =================
// Fully-masked tiles (k0 > q0+127) are never read downstream — early return.
#define SC_SMEM 65536

__global__ void __launch_bounds__(512, 1)
k_scores_t(const float* __restrict__ q, const float* __restrict__ k) {
    const int bh = blockIdx.z, b = bh >> 4, h = bh & 15;
    const int q0 = blockIdx.y * 128, k0 = blockIdx.x * 128;
    if (k0 > q0 + 127) return;

    extern __shared__ char smem[];
    const uint32_t sb = smem_u32(smem);
    const int tid = threadIdx.x, lane = tid & 31, wid = tid >> 5;
    const int wm = wid & 3, wn = wid >> 2;

    {
        #pragma unroll
        for (int i = 0; i < 4; i++) {
            int idx = tid + 512 * i;
            int row = idx >> 4, dq = idx & 15;
            float4 v = *(const float4*)(q + (size_t)(b * TT + q0 + row) * EE + h * DD + dq * 4);
            uint32_t h01, l01, h23, l23;
            split2(v.x, v.y, h01, l01);
            split2(v.z, v.w, h23, l23);
            uint32_t off = (uint32_t)(row * 128 + ((dq * 8) ^ ((row & 7) << 4)));
            *(uint2*)(smem + off)         = make_uint2(h01, h23);
            *(uint2*)(smem + 16384 + off) = make_uint2(l01, l23);
        }
        #pragma unroll
        for (int i = 0; i < 4; i++) {
            int idx = tid + 512 * i;
            int row = idx >> 4, dq = idx & 15;
            float4 v = *(const float4*)(k + (size_t)(b * TT + k0 + row) * EE + h * DD + dq * 4);
            uint32_t h01, l01, h23, l23;
            split2(v.x, v.y, h01, l01);
            split2(v.z, v.w, h23, l23);
            uint32_t off = (uint32_t)(row * 128 + ((dq * 8) ^ ((row & 7) << 4)));
            *(uint2*)(smem + 32768 + off) = make_uint2(h01, h23);
            *(uint2*)(smem + 49152 + off) = make_uint2(l01, l23);
        }
    }
    __syncthreads();

    const int a_m_in = (lane & 7) + ((lane >> 3) & 1) * 8;
    const int a_kb   = ((lane >> 4) & 1) * 16;
    const int b_n_in = (lane & 7) + ((lane >> 4) & 1) * 8;
    const int b_kb   = ((lane >> 3) & 1) * 16;

    float acc[2][4][4];
    #pragma unroll
    for (int i = 0; i < 2; i++)
        #pragma unroll
        for (int j = 0; j < 4; j++)
            #pragma unroll
            for (int r = 0; r < 4; r++) acc[i][j][r] = 0.f;

    #pragma unroll
    for (int kt = 0; kt < 4; kt++) {
        uint32_t afh[2][4], afl[2][4], bfh[2][4], bfl[2][4];
        #pragma unroll
        for (int mt = 0; mt < 2; mt++) {
            int row = wm * 32 + mt * 16 + a_m_in;
            uint32_t off = (uint32_t)(row * 128 + ((kt * 32 + a_kb) ^ ((row & 7) << 4)));
            ldsm_x4(afh[mt][0], afh[mt][1], afh[mt][2], afh[mt][3], sb + off);
            ldsm_x4(afl[mt][0], afl[mt][1], afl[mt][2], afl[mt][3], sb + 16384 + off);
        }
        #pragma unroll
        for (int ntp = 0; ntp < 2; ntp++) {
            int row = wn * 32 + ntp * 16 + b_n_in;
            uint32_t off = (uint32_t)(row * 128 + ((kt * 32 + b_kb) ^ ((row & 7) << 4)));
            ldsm_x4(bfh[ntp][0], bfh[ntp][1], bfh[ntp][2], bfh[ntp][3], sb + 32768 + off);
            ldsm_x4(bfl[ntp][0], bfl[ntp][1], bfl[ntp][2], bfl[ntp][3], sb + 49152 + off);
        }
        #pragma unroll
        for (int mt = 0; mt < 2; mt++)
            #pragma unroll
            for (int nt = 0; nt < 4; nt++) {
                const int np = nt >> 1, ne = (nt & 1) * 2;
                MMA3(acc[mt][nt], afh[mt], afl[mt],
                     bfh[np][ne], bfh[np][ne + 1], bfl[np][ne], bfl[np][ne + 1]);
            }
    }

    const int row0 = lane >> 2, col0 = (lane & 3) * 2;
    #pragma unroll
    for (int mt = 0; mt < 2; mt++) {
        #pragma unroll
        for (int nt = 0; nt < 4; nt++) {
            int qi = q0 + wm * 32 + mt * 16 + row0;
            int kj = k0 + wn * 32 + nt * 8 + col0;
            float s0 = (kj     <= qi) ? acc[mt][nt][0] * 0.125f : -1e30f;
            float s1 = (kj + 1 <= qi) ? acc[mt][nt][1] * 0.125f : -1e30f;
            float s2 = (kj     <= qi + 8) ? acc[mt][nt][2] * 0.125f : -1e30f;
            float s3 = (kj + 1 <= qi + 8) ? acc[mt][nt][3] * 0.125f : -1e30f;
            *(float2*)(g_S + ((size_t)bh * TT + qi) * TT + kj)       = make_float2(s0, s1);
            *(float2*)(g_S + ((size_t)bh * TT + qi + 8) * TT + kj)   = make_float2(s2, s3);
        }
    }
}

// ================= tensor-core O = P @ V =================
#define AV_SMEM 49152

__global__ void __launch_bounds__(256, 2)
k_av_t(const float* __restrict__ v, float* __restrict__ o) {
    extern __shared__ char smem[];
    const uint32_t sb = smem_u32(smem);
    const int bh = blockIdx.y, b = bh >> 4, h = bh & 15;
    const int q0 = blockIdx.x * 128;
    const int tid = threadIdx.x, lane = tid & 31, wid = tid >> 5;
    const int wm = wid & 3, wn = wid >> 2;

    const int a_m = tid >> 3, a_kq = tid & 7;
    const int b_n = tid & 63;
    const int b_q0 = tid >> 6;
    const int b_s = (b_n >> 3) & 7;

    const int a_m_in = (lane & 7) + ((lane >> 3) & 1) * 8;
    const int a_kb   = ((lane >> 4) & 1) * 16;
    const int b_n_in = (lane & 7) + ((lane >> 4) & 1) * 8;
    const int b_kb   = ((lane >> 3) & 1) * 16;

    float acc[2][4][4];
    #pragma unroll
    for (int i = 0; i < 2; i++)
        #pragma unroll
        for (int j = 0; j < 4; j++)
            #pragma unroll
            for (int r = 0; r < 4; r++) acc[i][j][r] = 0.f;

    const int nchunk = (q0 + 128) >> 5;
    const float* Prow = g_S + ((size_t)bh * TT + q0) * TT;
    float4 pa[4], pb[2];

    {
        #pragma unroll
        for (int i = 0; i < 4; i++) {
            int idx = tid + 256 * i;
            int m = idx >> 3, kq = idx & 7;
            pa[i] = *(const float4*)(Prow + (size_t)m * TT + kq * 4);
        }
        #pragma unroll
        for (int i = 0; i < 2; i++) {
            int kq = (b_q0 + 4 * i) ^ b_s;
            const float* bp = v + (size_t)(b * TT + kq * 4) * EE + h * DD + b_n;
            pb[i] = make_float4(bp[0], bp[(size_t)EE], bp[(size_t)2 * EE], bp[(size_t)3 * EE]);
        }
        #pragma unroll
        for (int i = 0; i < 4; i++) {
            int idx = tid + 256 * i;
            int m = idx >> 3, kq = idx & 7;
            uint32_t h01, l01, h23, l23;
            split2(pa[i].x, pa[i].y, h01, l01);
            split2(pa[i].z, pa[i].w, h23, l23);
            uint32_t off = (uint32_t)(m * 64 + ((kq * 8) ^ (((m >> 1) & 3) << 4)));
            *(uint2*)(smem + off)        = make_uint2(h01, h23);
            *(uint2*)(smem + 8192 + off) = make_uint2(l01, l23);
        }
        #pragma unroll
        for (int i = 0; i < 2; i++) {
            int kq = (b_q0 + 4 * i) ^ b_s;
            uint32_t h01, l01, h23, l23;
            split2(pb[i].x, pb[i].y, h01, l01);
            split2(pb[i].z, pb[i].w, h23, l23);
            uint32_t off = (uint32_t)(b_n * 64 + ((kq * 8) ^ (((b_n >> 1) & 3) << 4)));
            *(uint2*)(smem + 16384 + off) = make_uint2(h01, h23);
            *(uint2*)(smem + 20480 + off) = make_uint2(l01, l23);
        }
    }
    __syncthreads();

    for (int c = 0; c < nchunk; c++) {
        const uint32_t base = sb + (uint32_t)(c & 1) * 24576;
        const uint32_t ph = base, pl = base + 8192;
        const uint32_t vh = base + 16384, vl = base + 20480;

        if (c + 1 < nchunk) {
            int j0 = (c + 1) << 5;
            #pragma unroll
            for (int i = 0; i < 4; i++) {
                int idx = tid + 256 * i;
                int m = idx >> 3, kq = idx & 7;
                pa[i] = *(const float4*)(Prow + (size_t)m * TT + j0 + kq * 4);
            }
            #pragma unroll
            for (int i = 0; i < 2; i++) {
                int kq = (b_q0 + 4 * i) ^ b_s;
                const float* bp = v + (size_t)(b * TT + j0 + kq * 4) * EE + h * DD + b_n;
                pb[i] = make_float4(bp[0], bp[(size_t)EE], bp[(size_t)2 * EE], bp[(size_t)3 * EE]);
            }
        }

        #pragma unroll
        for (int kt = 0; kt < 2; kt++) {
            uint32_t afh[2][4], afl[2][4], bfh[2][4], bfl[2][4];
            #pragma unroll
            for (int mt = 0; mt < 2; mt++) {
                int row = wm * 32 + mt * 16 + a_m_in;
                uint32_t off = (uint32_t)(row * 64 + ((kt * 32 + a_kb) ^ (((row >> 1) & 3) << 4)));
                ldsm_x4(afh[mt][0], afh[mt][1], afh[mt][2], afh[mt][3], ph + off);
                ldsm_x4(afl[mt][0], afl[mt][1], afl[mt][2], afl[mt][3], pl + off);
            }
            #pragma unroll
            for (int ntp = 0; ntp < 2; ntp++) {
                int row = wn * 32 + ntp * 16 + b_n_in;
                uint32_t off = (uint32_t)(row * 64 + ((kt * 32 + b_kb) ^ (((row >> 1) & 3) << 4)));
                ldsm_x4(bfh[ntp][0], bfh[ntp][1], bfh[ntp][2], bfh[ntp][3], vh + off);
                ldsm_x4(bfl[ntp][0], bfl[ntp][1], bfl[ntp][2], bfl[ntp][3], vl + off);
            }
            #pragma unroll
            for (int mt = 0; mt < 2; mt++)
                #pragma unroll
                for (int nt = 0; nt < 4; nt++) {
                    const int np = nt >> 1, ne = (nt & 1) * 2;
                    MMA3(acc[mt][nt], afh[mt], afl[mt],
                         bfh[np][ne], bfh[np][ne + 1], bfl[np][ne], bfl[np][ne + 1]);
                }
        }

        if (c + 1 < nchunk) {
            char* nb = smem + ((c + 1) & 1) * 24576;
            #pragma unroll
            for (int i = 0; i < 4; i++) {
                int idx = tid + 256 * i;
                int m = idx >> 3, kq = idx & 7;
                uint32_t h01, l01, h23, l23;
                split2(pa[i].x, pa[i].y, h01, l01);
                split2(pa[i].z, pa[i].w, h23, l23);
                uint32_t off = (uint32_t)(m * 64 + ((kq * 8) ^ (((m >> 1) & 3) << 4)));
                *(uint2*)(nb + off)        = make_uint2(h01, h23);
                *(uint2*)(nb + 8192 + off) = make_uint2(l01, l23);
            }
            #pragma unroll
            for (int i = 0; i < 2; i++) {
                int kq = (b_q0 + 4 * i) ^ b_s;
                uint32_t h01, l01, h23, l23;
                split2(pb[i].x, pb[i].y, h01, l01);
                split2(pb[i].z, pb[i].w, h23, l23);
                uint32_t off = (uint32_t)(b_n * 64 + ((kq * 8) ^ (((b_n >> 1) & 3) << 4)));
                *(uint2*)(nb + 16384 + off) = make_uint2(h01, h23);
                *(uint2*)(nb + 20480 + off) = make_uint2(l01, l23);
            }
            __syncthreads();
        }
    }

    const int row0 = lane >> 2, col0 = (lane & 3) * 2;
    #pragma unroll
    for (int mt = 0; mt < 2; mt++) {
        #pragma unroll
        for (int nt = 0; nt < 4; nt++) {
            int gm = q0 + wm * 32 + mt * 16 + row0;
            int gn = wn * 32 + nt * 8 + col0;
            size_t p0 = (size_t)(b * TT + gm) * EE + h * DD + gn;
            size_t p1 = (size_t)(b * TT + gm + 8) * EE + h * DD + gn;
            *(float2*)(o + p0) = make_float2(acc[mt][nt][0], acc[mt][nt][1]);
            *(float2*)(o + p1) = make_float2(acc[mt][nt][2], acc[mt][nt][3]);
        }
    }
}

// ---------------- embed ----------------
__global__ void k_embed(const int* __restrict__ idx, const float* __restrict__ tok,
                        const float* __restrict__ pos, float* __restrict__ x) {
    int r = blockIdx.x;
    int t = r & (TT - 1);
    int tokid = idx[r];
    const float4* te = (const float4*)(tok + (size_t)tokid * EE);
    const float4* pe = (const float4*)(pos + (size_t)t * EE);
    float4* xr = (float4*)(x + (size_t)r * EE);
    int c = threadIdx.x;
    float4 a = te[c], b = pe[c];
    xr[c] = make_float4(a.x + b.x, a.y + b.y, a.z + b.z, a.w + b.w);
}

// ---------------- block reduce ----------------
__device__ __forceinline__ float blockReduceSum(float val, float* red) {
    int tid = threadIdx.x;
    #pragma unroll
    for (int o = 16; o; o >>= 1) val += __shfl_xor_sync(0xffffffffu, val, o);
    if ((tid & 31) == 0) red[tid >> 5] = val;
    __syncthreads();
    if (tid < 32) {
        float v = (tid < 8) ? red[tid] : 0.f;
        #pragma unroll
        for (int o = 4; o; o >>= 1) v += __shfl_xor_sync(0xffffffffu, v, o);
        if (tid == 0) red[0] = v;
    }
    __syncthreads();
    float r = red[0];
    __syncthreads();
    return r;
}

// ---------------- layernorm ----------------
__global__ void k_ln(const float* __restrict__ x, const float* __restrict__ g,
                     const float* __restrict__ b, float* __restrict__ out) {
    __shared__ float red[32];
    int row = blockIdx.x, tid = threadIdx.x;
    const float* xr = x + (size_t)row * EE;
    float v[4];
    float s = 0.f;
    #pragma unroll
    for (int i = 0; i < 4; i++) { v[i] = xr[tid + 256 * i]; s += v[i]; }
    s = blockReduceSum(s, red);
    float mean = s * (1.f / EE);
    float s2 = 0.f;
    #pragma unroll
    for (int i = 0; i < 4; i++) { float d = v[i] - mean; s2 += d * d; }
    s2 = blockReduceSum(s2, red);
    float inv = rsqrtf(s2 * (1.f / EE) + 1e-5f);
    #pragma unroll
    for (int i = 0; i < 4; i++) {
        int c = tid + 256 * i;
        out[(size_t)row * EE + c] = (v[i] - mean) * inv * g[c] + b[c];
    }
}

// ---------------- softmax per row (variable length) ----------------
__global__ void k_softmax() {
    __shared__ float red[32];
    int row = blockIdx.x;
    int qpos = row & (TT - 1);
    int L = (qpos | 127) + 1;
    float* r = g_S + (size_t)row * TT;
    int tid = threadIdx.x;
    float v[4], m = -1e30f;
    #pragma unroll
    for (int i = 0; i < 4; i++) {
        int c = tid + 256 * i;
        v[i] = (c < L) ? r[c] : -1e30f;
        m = fmaxf(m, v[i]);
    }
    #pragma unroll
    for (int o = 16; o; o >>= 1) m = fmaxf(m, __shfl_xor_sync(0xffffffffu, m, o));
    if ((tid & 31) == 0) red[tid >> 5] = m;
    __syncthreads();
    if (tid < 32) {
        float t = (tid < 8) ? red[tid] : -1e30f;
        #pragma unroll
        for (int o = 4; o; o >>= 1) t = fmaxf(t, __shfl_xor_sync(0xffffffffu, t, o));
        if (tid == 0) red[0] = t;
    }
    __syncthreads();
    m = red[0];
    __syncthreads();
    float s = 0.f;
    #pragma unroll
    for (int i = 0; i < 4; i++) { v[i] = __expf(v[i] - m); s += v[i]; }
    s = blockReduceSum(s, red);
    float inv = 1.f / s;
    #pragma unroll
    for (int i = 0; i < 4; i++) {
        int c = tid + 256 * i;
        if (c < L) r[c] = v[i] * inv;
    }
}

// ---------------- host orchestration ----------------
extern "C" void kernel_launch(void* const* d_in, const int* in_sizes, int n_in,
                              void* d_out, int out_size) {
    const int*   idx  = (const int*)  d_in[0];
    const float* tok  = (const float*)d_in[1];
    const float* pos  = (const float*)d_in[2];
    const float* Wq   = (const float*)d_in[3];
    const float* Wk   = (const float*)d_in[4];
    const float* Wv   = (const float*)d_in[5];
    const float* Wp   = (const float*)d_in[6];
    const float* bp   = (const float*)d_in[7];
    const float* g1   = (const float*)d_in[8];
    const float* b1   = (const float*)d_in[9];
    const float* g2   = (const float*)d_in[10];
    const float* b2   = (const float*)d_in[11];
    const float* W1   = (const float*)d_in[12];
    const float* bf1  = (const float*)d_in[13];
    const float* W2   = (const float*)d_in[14];
    const float* bf2  = (const float*)d_in[15];
    const float* gf   = (const float*)d_in[16];
    const float* bff  = (const float*)d_in[17];
    const float* Wlm  = (const float*)d_in[18];
    const float* blm  = (const float*)d_in[19];
    float* out = (float*)d_out;

    float *x, *h, *q, *k, *v, *o, *ff;
    cudaGetSymbolAddress((void**)&x,  g_x);
    cudaGetSymbolAddress((void**)&h,  g_h);
    cudaGetSymbolAddress((void**)&q,  g_q);
    cudaGetSymbolAddress((void**)&k,  g_k);
    cudaGetSymbolAddress((void**)&v,  g_v);
    cudaGetSymbolAddress((void**)&o,  g_o);
    cudaGetSymbolAddress((void**)&ff, g_ff);

    cudaFuncSetAttribute(k_tgemm<false,false,false>,
                         cudaFuncAttributeMaxDynamicSharedMemorySize, TG_SMEM);
    cudaFuncSetAttribute(k_tgemm<true,false,true>,
                         cudaFuncAttributeMaxDynamicSharedMemorySize, TG_SMEM);
    cudaFuncSetAttribute(k_tgemm<true,true,false>,
                         cudaFuncAttributeMaxDynamicSharedMemorySize, TG_SMEM);
    cudaFuncSetAttribute(k_tgemm<true,false,false>,
                         cudaFuncAttributeMaxDynamicSharedMemorySize, TG_SMEM);
    cudaFuncSetAttribute(k_scores_t,
                         cudaFuncAttributeMaxDynamicSharedMemorySize, SC_SMEM);
    cudaFuncSetAttribute(k_av_t,
                         cudaFuncAttributeMaxDynamicSharedMemorySize, AV_SMEM);

    k_embed<<<RR, 256>>>(idx, tok, pos, x);

    dim3 gEE(EE / 64, RR / 128);       // (16, 16)
    dim3 gFF(FF / 64, RR / 128);       // (64, 16)
    dim3 gLM(VV / 64, RR / 128);       // (500, 16)

    for (int l = 0; l < LL; l++) {
        const float* wq = Wq + (size_t)l * EE * EE;
        const float* wk = Wk + (size_t)l * EE * EE;
        const float* wv = Wv + (size_t)l * EE * EE;
        const float* wp = Wp + (size_t)l * EE * EE;
        const float* w1 = W1 + (size_t)l * EE * FF;
        const float* w2 = W2 + (size_t)l * FF * EE;

        k_ln<<<RR, 256>>>(x, g1 + l * EE, b1 + l * EE, h);
        k_tgemm<false,false,false><<<gEE, 256, TG_SMEM>>>(h, wq, nullptr, nullptr, q, RR, EE, EE);
        k_tgemm<false,false,false><<<gEE, 256, TG_SMEM>>>(h, wk, nullptr, nullptr, k, RR, EE, EE);
        k_tgemm<false,false,false><<<gEE, 256, TG_SMEM>>>(h, wv, nullptr, nullptr, v, RR, EE, EE);

        k_scores_t<<<dim3(8, 8, 32), 512, SC_SMEM>>>(q, k);
        k_softmax<<<BB * HH * TT, 256>>>();
        k_av_t<<<dim3(8, 32), 256, AV_SMEM>>>(v, o);

        // x = x + o @ Wp + bp
        k_tgemm<true,false,true><<<gEE, 256, TG_SMEM>>>(o, wp, bp + l * EE, x, x, RR, EE, EE);

        k_ln<<<RR, 256>>>(x, g2 + l * EE, b2 + l * EE, h);
        // ff = relu(h @ W1 + bf1)
        k_tgemm<true,true,false><<<gFF, 256, TG_SMEM>>>(h, w1, bf1 + l * FF, nullptr, ff, RR, FF, EE);
        // x = x + ff @ W2 + bf2
        k_tgemm<true,false,true><<<gEE, 256, TG_SMEM>>>(ff, w2, bf2 + l * EE, x, x, RR, EE, FF);
    }

    k_ln<<<RR, 256>>>(x, gf, bff, h);
    k_tgemm<true,false,false><<<gLM, 256, TG_SMEM>>>(h, Wlm, blm, nullptr, out, RR, VV, EE);
}

// round 13
// speedup vs baseline: 3.6034x; 1.0469x over previous
#include <cuda_runtime.h>
#include <cstdint>

// ---------------- problem constants ----------------
#define BB 2
#define TT 1024
#define EE 1024
#define HH 16
#define DD 64
#define LL 6
#define FF 4096
#define VV 32000
#define RR (BB*TT)   // 2048 token rows

// ---------------- device scratch (static, no allocations) ----------------
__device__ float g_x [RR*EE];
__device__ float g_h [RR*EE];
__device__ float g_q [RR*EE];
__device__ float g_k [RR*EE];
__device__ float g_v [RR*EE];
__device__ float g_o [RR*EE];
__device__ float g_ff[RR*FF];
__device__ float g_S [(size_t)BB*HH*TT*TT];   // attention scores

__device__ __forceinline__ uint32_t smem_u32(const void* p) {
    uint32_t a;
    asm("{ .reg .u64 t; cvta.to.shared.u64 t, %1; cvt.u32.u64 %0, t; }"
        : "=r"(a) : "l"(p));
    return a;
}

__device__ __forceinline__ void ldsm_x4(uint32_t& r0, uint32_t& r1,
                                        uint32_t& r2, uint32_t& r3, uint32_t addr) {
    asm volatile("ldmatrix.sync.aligned.m8n8.x4.shared.b16 {%0,%1,%2,%3}, [%4];"
                 : "=r"(r0), "=r"(r1), "=r"(r2), "=r"(r3) : "r"(addr));
}

__device__ __forceinline__ void mma_bf16(float& c0, float& c1, float& c2, float& c3,
                                         uint32_t a0, uint32_t a1, uint32_t a2, uint32_t a3,
                                         uint32_t b0, uint32_t b1) {
    asm volatile("mma.sync.aligned.m16n8k16.row.col.f32.bf16.bf16.f32 "
                 "{%0,%1,%2,%3}, {%4,%5,%6,%7}, {%8,%9}, {%0,%1,%2,%3};"
                 : "+f"(c0), "+f"(c1), "+f"(c2), "+f"(c3)
                 : "r"(a0), "r"(a1), "r"(a2), "r"(a3), "r"(b0), "r"(b1));
}

// split two fp32 (k-consecutive x0,x1) into packed bf16x2 hi and lo
__device__ __forceinline__ void split2(float x0, float x1, uint32_t& h, uint32_t& l) {
    uint32_t hh;
    asm("cvt.rn.bf16x2.f32 %0, %1, %2;" : "=r"(hh) : "f"(x1), "f"(x0));
    float h0 = __uint_as_float(hh << 16);
    float h1 = __uint_as_float(hh & 0xFFFF0000u);
    float l0 = x0 - h0, l1 = x1 - h1;
    uint32_t ll;
    asm("cvt.rn.bf16x2.f32 %0, %1, %2;" : "=r"(ll) : "f"(l1), "f"(l0));
    h = hh; l = ll;
}

// 3 mma terms: ah*bh + ah*bl + al*bh
#define MMA3(ACC, AH, AL, BH0, BH1, BL0, BL1) do { \
    mma_bf16((ACC)[0], (ACC)[1], (ACC)[2], (ACC)[3], \
             (AH)[0], (AH)[1], (AH)[2], (AH)[3], (BH0), (BH1)); \
    mma_bf16((ACC)[0], (ACC)[1], (ACC)[2], (ACC)[3], \
             (AH)[0], (AH)[1], (AH)[2], (AH)[3], (BL0), (BL1)); \
    mma_bf16((ACC)[0], (ACC)[1], (ACC)[2], (ACC)[3], \
             (AL)[0], (AL)[1], (AL)[2], (AL)[3], (BH0), (BH1)); \
} while (0)

// ================= 3xBF16 tensor-core GEMM (fp32-accurate) =================
// C[M,N] = A[M,K] @ B[K,N] (+bias)(+resid)(relu). 128x64 CTA tile, BK=32.
// grid = (M/128, N/64) — x walks rows so consecutive CTAs share the same B
// column block (L2 reuse; matters for the 131MB LM head).
// 128 threads (4 warps, 2x2 grid of 64x32 warp tiles) -> 16 MMA chains/warp.
// SMEM per buffer (24KB): Ah@0(8K), Al@8K, Bh@16K(4K), Bl@20K. Double: 48KB.
// 2 CTAs/SM via __launch_bounds__(128,2).
#define TG_SMEM 49152

template<bool BIAS, bool RELU, bool RESID>
__global__ void __launch_bounds__(128, 2)
k_tgemm(const float* __restrict__ A, const float* __restrict__ B,
        const float* __restrict__ bias, const float* __restrict__ resid,
        float* __restrict__ C, int M, int N, int K) {
    extern __shared__ char smem[];
    const uint32_t sb = smem_u32(smem);
    const int tid = threadIdx.x, lane = tid & 31, wid = tid >> 5;
    const int wm = wid & 1, wn = wid >> 1;           // 2 x 2 warp grid
    const int rowBase = blockIdx.x * 128;
    const int colBase = blockIdx.y * 64;

    float acc[4][4][4];
    #pragma unroll
    for (int i = 0; i < 4; i++)
        #pragma unroll
        for (int j = 0; j < 4; j++)
            #pragma unroll
            for (int r = 0; r < 4; r++) acc[i][j][r] = 0.f;

    const int a_m = tid >> 3, a_kq = tid & 7;        // A: float4 at (a_m + 16i, kq*4)
    const int b_n = tid & 63, b_q0 = tid >> 6;       // B: col n, kq = (q0+2i)^s
    const int b_s = (b_n >> 3) & 7;

    const int a_m_in = (lane & 7) + ((lane >> 3) & 1) * 8;
    const int a_kb   = ((lane >> 4) & 1) * 16;
    const int b_n_in = (lane & 7) + ((lane >> 4) & 1) * 8;
    const int b_kb   = ((lane >> 3) & 1) * 16;

    const int nchunk = K >> 5;
    float4 pa[8], pb[4];

    {
        #pragma unroll
        for (int i = 0; i < 8; i++) {
            int m = a_m + 16 * i;
            pa[i] = *(const float4*)(A + (size_t)(rowBase + m) * K + a_kq * 4);
        }
        #pragma unroll
        for (int i = 0; i < 4; i++) {
            int kq = (b_q0 + 2 * i) ^ b_s;
            const float* bp = B + (size_t)(kq * 4) * N + colBase + b_n;
            pb[i] = make_float4(bp[0], bp[(size_t)N], bp[(size_t)2 * N], bp[(size_t)3 * N]);
        }
        #pragma unroll
        for (int i = 0; i < 8; i++) {
            int m = a_m + 16 * i;
            uint32_t h01, l01, h23, l23;
            split2(pa[i].x, pa[i].y, h01, l01);
            split2(pa[i].z, pa[i].w, h23, l23);
            uint32_t off = (uint32_t)(m * 64 + ((a_kq * 8) ^ (((m >> 1) & 3) << 4)));
            *(uint2*)(smem + off)        = make_uint2(h01, h23);
            *(uint2*)(smem + 8192 + off) = make_uint2(l01, l23);
        }
        #pragma unroll
        for (int i = 0; i < 4; i++) {
            int kq = (b_q0 + 2 * i) ^ b_s;
            uint32_t h01, l01, h23, l23;
            split2(pb[i].x, pb[i].y, h01, l01);
            split2(pb[i].z, pb[i].w, h23, l23);
            uint32_t off = (uint32_t)(b_n * 64 + ((kq * 8) ^ (((b_n >> 1) & 3) << 4)));
            *(uint2*)(smem + 16384 + off) = make_uint2(h01, h23);
            *(uint2*)(smem + 20480 + off) = make_uint2(l01, l23);
        }
    }
    __syncthreads();

    for (int c = 0; c < nchunk; c++) {
        const uint32_t base = sb + (uint32_t)(c & 1) * 24576;
        const uint32_t ah = base, al = base + 8192;
        const uint32_t bh = base + 16384, bl = base + 20480;

        if (c + 1 < nchunk) {
            int k0 = (c + 1) << 5;
            #pragma unroll
            for (int i = 0; i < 8; i++) {
                int m = a_m + 16 * i;
                pa[i] = *(const float4*)(A + (size_t)(rowBase + m) * K + k0 + a_kq * 4);
            }
            #pragma unroll
            for (int i = 0; i < 4; i++) {
                int kq = (b_q0 + 2 * i) ^ b_s;
                const float* bp = B + (size_t)(k0 + kq * 4) * N + colBase + b_n;
                pb[i] = make_float4(bp[0], bp[(size_t)N], bp[(size_t)2 * N], bp[(size_t)3 * N]);
            }
        }

        #pragma unroll
        for (int kt = 0; kt < 2; kt++) {
            uint32_t afh[4][4], afl[4][4], bfh[2][4], bfl[2][4];
            #pragma unroll
            for (int mt = 0; mt < 4; mt++) {
                int row = wm * 64 + mt * 16 + a_m_in;
                uint32_t off = (uint32_t)(row * 64 + ((kt * 32 + a_kb) ^ (((row >> 1) & 3) << 4)));
                ldsm_x4(afh[mt][0], afh[mt][1], afh[mt][2], afh[mt][3], ah + off);
                ldsm_x4(afl[mt][0], afl[mt][1], afl[mt][2], afl[mt][3], al + off);
            }
            #pragma unroll
            for (int ntp = 0; ntp < 2; ntp++) {
                int row = wn * 32 + ntp * 16 + b_n_in;
                uint32_t off = (uint32_t)(row * 64 + ((kt * 32 + b_kb) ^ (((row >> 1) & 3) << 4)));
                ldsm_x4(bfh[ntp][0], bfh[ntp][1], bfh[ntp][2], bfh[ntp][3], bh + off);
                ldsm_x4(bfl[ntp][0], bfl[ntp][1], bfl[ntp][2], bfl[ntp][3], bl + off);
            }
            #pragma unroll
            for (int mt = 0; mt < 4; mt++)
                #pragma unroll
                for (int nt = 0; nt < 4; nt++) {
                    const int np = nt >> 1, ne = (nt & 1) * 2;
                    MMA3(acc[mt][nt], afh[mt], afl[mt],
                         bfh[np][ne], bfh[np][ne + 1], bfl[np][ne], bfl[np][ne + 1]);
                }
        }

        if (c + 1 < nchunk) {
            char* nb = smem + ((c + 1) & 1) * 24576;
            #pragma unroll
            for (int i = 0; i < 8; i++) {
                int m = a_m + 16 * i;
                uint32_t h01, l01, h23, l23;
                split2(pa[i].x, pa[i].y, h01, l01);
                split2(pa[i].z, pa[i].w, h23, l23);
                uint32_t off = (uint32_t)(m * 64 + ((a_kq * 8) ^ (((m >> 1) & 3) << 4)));
                *(uint2*)(nb + off)        = make_uint2(h01, h23);
                *(uint2*)(nb + 8192 + off) = make_uint2(l01, l23);
            }
            #pragma unroll
            for (int i = 0; i < 4; i++) {
                int kq = (b_q0 + 2 * i) ^ b_s;
                uint32_t h01, l01, h23, l23;
                split2(pb[i].x, pb[i].y, h01, l01);
                split2(pb[i].z, pb[i].w, h23, l23);
                uint32_t off = (uint32_t)(b_n * 64 + ((kq * 8) ^ (((b_n >> 1) & 3) << 4)));
                *(uint2*)(nb + 16384 + off) = make_uint2(h01, h23);
                *(uint2*)(nb + 20480 + off) = make_uint2(l01, l23);
            }
            __syncthreads();
        }
    }

    const int row0 = lane >> 2, col0 = (lane & 3) * 2;
    #pragma unroll
    for (int mt = 0; mt < 4; mt++) {
        #pragma unroll
        for (int nt = 0; nt < 4; nt++) {
            int gm = rowBase + wm * 64 + mt * 16 + row0;
            int gn = colBase + wn * 32 + nt * 8 + col0;
            float o0 = acc[mt][nt][0], o1 = acc[mt][nt][1];
            float o2 = acc[mt][nt][2], o3 = acc[mt][nt][3];
            if (BIAS) {
                float bv0 = bias[gn], bv1 = bias[gn + 1];
                o0 += bv0; o1 += bv1; o2 += bv0; o3 += bv1;
            }
            size_t p0 = (size_t)gm * N + gn;
            size_t p1 = (size_t)(gm + 8) * N + gn;
            if (RESID) {
                float2 r0v = *(const float2*)(resid + p0);
                float2 r1v = *(const float2*)(resid + p1);
                o0 += r0v.x; o1 += r0v.y; o2 += r1v.x; o3 += r1v.y;
            }
            if (RELU) {
                o0 = fmaxf(o0, 0.f); o1 = fmaxf(o1, 0.f);
                o2 = fmaxf(o2, 0.f); o3 = fmaxf(o3, 0.f);
            }
            *(float2*)(C + p0) = make_float2(o0, o1);
            *(float2*)(C + p1) = make_float2(o2, o3);
        }
    }
}

// ================= tensor-core attention scores =================
// Fully-masked tiles (k0 > q0+127) are never read downstream — early return.
#define SC_SMEM 65536

__global__ void __launch_bounds__(512, 1)
k_scores_t(const float* __restrict__ q, const float* __restrict__ k) {
    const int bh = blockIdx.z, b = bh >> 4, h = bh & 15;
    const int q0 = blockIdx.y * 128, k0 = blockIdx.x * 128;
    if (k0 > q0 + 127) return;

    extern __shared__ char smem[];
    const uint32_t sb = smem_u32(smem);
    const int tid = threadIdx.x, lane = tid & 31, wid = tid >> 5;
    const int wm = wid & 3, wn = wid >> 2;

    {
        #pragma unroll
        for (int i = 0; i < 4; i++) {
            int idx = tid + 512 * i;
            int row = idx >> 4, dq = idx & 15;
            float4 v = *(const float4*)(q + (size_t)(b * TT + q0 + row) * EE + h * DD + dq * 4);
            uint32_t h01, l01, h23, l23;
            split2(v.x, v.y, h01, l01);
            split2(v.z, v.w, h23, l23);
            uint32_t off = (uint32_t)(row * 128 + ((dq * 8) ^ ((row & 7) << 4)));
            *(uint2*)(smem + off)         = make_uint2(h01, h23);
            *(uint2*)(smem + 16384 + off) = make_uint2(l01, l23);
        }
        #pragma unroll
        for (int i = 0; i < 4; i++) {
            int idx = tid + 512 * i;
            int row = idx >> 4, dq = idx & 15;
            float4 v = *(const float4*)(k + (size_t)(b * TT + k0 + row) * EE + h * DD + dq * 4);
            uint32_t h01, l01, h23, l23;
            split2(v.x, v.y, h01, l01);
            split2(v.z, v.w, h23, l23);
            uint32_t off = (uint32_t)(row * 128 + ((dq * 8) ^ ((row & 7) << 4)));
            *(uint2*)(smem + 32768 + off) = make_uint2(h01, h23);
            *(uint2*)(smem + 49152 + off) = make_uint2(l01, l23);
        }
    }
    __syncthreads();

    const int a_m_in = (lane & 7) + ((lane >> 3) & 1) * 8;
    const int a_kb   = ((lane >> 4) & 1) * 16;
    const int b_n_in = (lane & 7) + ((lane >> 4) & 1) * 8;
    const int b_kb   = ((lane >> 3) & 1) * 16;

    float acc[2][4][4];
    #pragma unroll
    for (int i = 0; i < 2; i++)
        #pragma unroll
        for (int j = 0; j < 4; j++)
            #pragma unroll
            for (int r = 0; r < 4; r++) acc[i][j][r] = 0.f;

    #pragma unroll
    for (int kt = 0; kt < 4; kt++) {
        uint32_t afh[2][4], afl[2][4], bfh[2][4], bfl[2][4];
        #pragma unroll
        for (int mt = 0; mt < 2; mt++) {
            int row = wm * 32 + mt * 16 + a_m_in;
            uint32_t off = (uint32_t)(row * 128 + ((kt * 32 + a_kb) ^ ((row & 7) << 4)));
            ldsm_x4(afh[mt][0], afh[mt][1], afh[mt][2], afh[mt][3], sb + off);
            ldsm_x4(afl[mt][0], afl[mt][1], afl[mt][2], afl[mt][3], sb + 16384 + off);
        }
        #pragma unroll
        for (int ntp = 0; ntp < 2; ntp++) {
            int row = wn * 32 + ntp * 16 + b_n_in;
            uint32_t off = (uint32_t)(row * 128 + ((kt * 32 + b_kb) ^ ((row & 7) << 4)));
            ldsm_x4(bfh[ntp][0], bfh[ntp][1], bfh[ntp][2], bfh[ntp][3], sb + 32768 + off);
            ldsm_x4(bfl[ntp][0], bfl[ntp][1], bfl[ntp][2], bfl[ntp][3], sb + 49152 + off);
        }
        #pragma unroll
        for (int mt = 0; mt < 2; mt++)
            #pragma unroll
            for (int nt = 0; nt < 4; nt++) {
                const int np = nt >> 1, ne = (nt & 1) * 2;
                MMA3(acc[mt][nt], afh[mt], afl[mt],
                     bfh[np][ne], bfh[np][ne + 1], bfl[np][ne], bfl[np][ne + 1]);
            }
    }

    const int row0 = lane >> 2, col0 = (lane & 3) * 2;
    #pragma unroll
    for (int mt = 0; mt < 2; mt++) {
        #pragma unroll
        for (int nt = 0; nt < 4; nt++) {
            int qi = q0 + wm * 32 + mt * 16 + row0;
            int kj = k0 + wn * 32 + nt * 8 + col0;
            float s0 = (kj     <= qi) ? acc[mt][nt][0] * 0.125f : -1e30f;
            float s1 = (kj + 1 <= qi) ? acc[mt][nt][1] * 0.125f : -1e30f;
            float s2 = (kj     <= qi + 8) ? acc[mt][nt][2] * 0.125f : -1e30f;
            float s3 = (kj + 1 <= qi + 8) ? acc[mt][nt][3] * 0.125f : -1e30f;
            *(float2*)(g_S + ((size_t)bh * TT + qi) * TT + kj)       = make_float2(s0, s1);
            *(float2*)(g_S + ((size_t)bh * TT + qi + 8) * TT + kj)   = make_float2(s2, s3);
        }
    }
}

// ================= tensor-core O = P @ V =================
#define AV_SMEM 49152

__global__ void __launch_bounds__(256, 2)
k_av_t(const float* __restrict__ v, float* __restrict__ o) {
    extern __shared__ char smem[];
    const uint32_t sb = smem_u32(smem);
    const int bh = blockIdx.y, b = bh >> 4, h = bh & 15;
    const int q0 = blockIdx.x * 128;
    const int tid = threadIdx.x, lane = tid & 31, wid = tid >> 5;
    const int wm = wid & 3, wn = wid >> 2;

    const int a_m = tid >> 3, a_kq = tid & 7;
    const int b_n = tid & 63;
    const int b_q0 = tid >> 6;
    const int b_s = (b_n >> 3) & 7;

    const int a_m_in = (lane & 7) + ((lane >> 3) & 1) * 8;
    const int a_kb   = ((lane >> 4) & 1) * 16;
    const int b_n_in = (lane & 7) + ((lane >> 4) & 1) * 8;
    const int b_kb   = ((lane >> 3) & 1) * 16;

    float acc[2][4][4];
    #pragma unroll
    for (int i = 0; i < 2; i++)
        #pragma unroll
        for (int j = 0; j < 4; j++)
            #pragma unroll
            for (int r = 0; r < 4; r++) acc[i][j][r] = 0.f;

    const int nchunk = (q0 + 128) >> 5;
    const float* Prow = g_S + ((size_t)bh * TT + q0) * TT;
    float4 pa[4], pb[2];

    {
        #pragma unroll
        for (int i = 0; i < 4; i++) {
            int idx = tid + 256 * i;
            int m = idx >> 3, kq = idx & 7;
            pa[i] = *(const float4*)(Prow + (size_t)m * TT + kq * 4);
        }
        #pragma unroll
        for (int i = 0; i < 2; i++) {
            int kq = (b_q0 + 4 * i) ^ b_s;
            const float* bp = v + (size_t)(b * TT + kq * 4) * EE + h * DD + b_n;
            pb[i] = make_float4(bp[0], bp[(size_t)EE], bp[(size_t)2 * EE], bp[(size_t)3 * EE]);
        }
        #pragma unroll
        for (int i = 0; i < 4; i++) {
            int idx = tid + 256 * i;
            int m = idx >> 3, kq = idx & 7;
            uint32_t h01, l01, h23, l23;
            split2(pa[i].x, pa[i].y, h01, l01);
            split2(pa[i].z, pa[i].w, h23, l23);
            uint32_t off = (uint32_t)(m * 64 + ((kq * 8) ^ (((m >> 1) & 3) << 4)));
            *(uint2*)(smem + off)        = make_uint2(h01, h23);
            *(uint2*)(smem + 8192 + off) = make_uint2(l01, l23);
        }
        #pragma unroll
        for (int i = 0; i < 2; i++) {
            int kq = (b_q0 + 4 * i) ^ b_s;
            uint32_t h01, l01, h23, l23;
            split2(pb[i].x, pb[i].y, h01, l01);
            split2(pb[i].z, pb[i].w, h23, l23);
            uint32_t off = (uint32_t)(b_n * 64 + ((kq * 8) ^ (((b_n >> 1) & 3) << 4)));
            *(uint2*)(smem + 16384 + off) = make_uint2(h01, h23);
            *(uint2*)(smem + 20480 + off) = make_uint2(l01, l23);
        }
    }
    __syncthreads();

    for (int c = 0; c < nchunk; c++) {
        const uint32_t base = sb + (uint32_t)(c & 1) * 24576;
        const uint32_t ph = base, pl = base + 8192;
        const uint32_t vh = base + 16384, vl = base + 20480;

        if (c + 1 < nchunk) {
            int j0 = (c + 1) << 5;
            #pragma unroll
            for (int i = 0; i < 4; i++) {
                int idx = tid + 256 * i;
                int m = idx >> 3, kq = idx & 7;
                pa[i] = *(const float4*)(Prow + (size_t)m * TT + j0 + kq * 4);
            }
            #pragma unroll
            for (int i = 0; i < 2; i++) {
                int kq = (b_q0 + 4 * i) ^ b_s;
                const float* bp = v + (size_t)(b * TT + j0 + kq * 4) * EE + h * DD + b_n;
                pb[i] = make_float4(bp[0], bp[(size_t)EE], bp[(size_t)2 * EE], bp[(size_t)3 * EE]);
            }
        }

        #pragma unroll
        for (int kt = 0; kt < 2; kt++) {
            uint32_t afh[2][4], afl[2][4], bfh[2][4], bfl[2][4];
            #pragma unroll
            for (int mt = 0; mt < 2; mt++) {
                int row = wm * 32 + mt * 16 + a_m_in;
                uint32_t off = (uint32_t)(row * 64 + ((kt * 32 + a_kb) ^ (((row >> 1) & 3) << 4)));
                ldsm_x4(afh[mt][0], afh[mt][1], afh[mt][2], afh[mt][3], ph + off);
                ldsm_x4(afl[mt][0], afl[mt][1], afl[mt][2], afl[mt][3], pl + off);
            }
            #pragma unroll
            for (int ntp = 0; ntp < 2; ntp++) {
                int row = wn * 32 + ntp * 16 + b_n_in;
                uint32_t off = (uint32_t)(row * 64 + ((kt * 32 + b_kb) ^ (((row >> 1) & 3) << 4)));
                ldsm_x4(bfh[ntp][0], bfh[ntp][1], bfh[ntp][2], bfh[ntp][3], vh + off);
                ldsm_x4(bfl[ntp][0], bfl[ntp][1], bfl[ntp][2], bfl[ntp][3], vl + off);
            }
            #pragma unroll
            for (int mt = 0; mt < 2; mt++)
                #pragma unroll
                for (int nt = 0; nt < 4; nt++) {
                    const int np = nt >> 1, ne = (nt & 1) * 2;
                    MMA3(acc[mt][nt], afh[mt], afl[mt],
                         bfh[np][ne], bfh[np][ne + 1], bfl[np][ne], bfl[np][ne + 1]);
                }
        }

        if (c + 1 < nchunk) {
            char* nb = smem + ((c + 1) & 1) * 24576;
            #pragma unroll
            for (int i = 0; i < 4; i++) {
                int idx = tid + 256 * i;
                int m = idx >> 3, kq = idx & 7;
                uint32_t h01, l01, h23, l23;
                split2(pa[i].x, pa[i].y, h01, l01);
                split2(pa[i].z, pa[i].w, h23, l23);
                uint32_t off = (uint32_t)(m * 64 + ((kq * 8) ^ (((m >> 1) & 3) << 4)));
                *(uint2*)(nb + off)        = make_uint2(h01, h23);
                *(uint2*)(nb + 8192 + off) = make_uint2(l01, l23);
            }
            #pragma unroll
            for (int i = 0; i < 2; i++) {
                int kq = (b_q0 + 4 * i) ^ b_s;
                uint32_t h01, l01, h23, l23;
                split2(pb[i].x, pb[i].y, h01, l01);
                split2(pb[i].z, pb[i].w, h23, l23);
                uint32_t off = (uint32_t)(b_n * 64 + ((kq * 8) ^ (((b_n >> 1) & 3) << 4)));
                *(uint2*)(nb + 16384 + off) = make_uint2(h01, h23);
                *(uint2*)(nb + 20480 + off) = make_uint2(l01, l23);
            }
            __syncthreads();
        }
    }

    const int row0 = lane >> 2, col0 = (lane & 3) * 2;
    #pragma unroll
    for (int mt = 0; mt < 2; mt++) {
        #pragma unroll
        for (int nt = 0; nt < 4; nt++) {
            int gm = q0 + wm * 32 + mt * 16 + row0;
            int gn = wn * 32 + nt * 8 + col0;
            size_t p0 = (size_t)(b * TT + gm) * EE + h * DD + gn;
            size_t p1 = (size_t)(b * TT + gm + 8) * EE + h * DD + gn;
            *(float2*)(o + p0) = make_float2(acc[mt][nt][0], acc[mt][nt][1]);
            *(float2*)(o + p1) = make_float2(acc[mt][nt][2], acc[mt][nt][3]);
        }
    }
}

// ---------------- embed ----------------
__global__ void k_embed(const int* __restrict__ idx, const float* __restrict__ tok,
                        const float* __restrict__ pos, float* __restrict__ x) {
    int r = blockIdx.x;
    int t = r & (TT - 1);
    int tokid = idx[r];
    const float4* te = (const float4*)(tok + (size_t)tokid * EE);
    const float4* pe = (const float4*)(pos + (size_t)t * EE);
    float4* xr = (float4*)(x + (size_t)r * EE);
    int c = threadIdx.x;
    float4 a = te[c], b = pe[c];
    xr[c] = make_float4(a.x + b.x, a.y + b.y, a.z + b.z, a.w + b.w);
}

// ---------------- block reduce ----------------
__device__ __forceinline__ float blockReduceSum(float val, float* red) {
    int tid = threadIdx.x;
    #pragma unroll
    for (int o = 16; o; o >>= 1) val += __shfl_xor_sync(0xffffffffu, val, o);
    if ((tid & 31) == 0) red[tid >> 5] = val;
    __syncthreads();
    if (tid < 32) {
        float v = (tid < 8) ? red[tid] : 0.f;
        #pragma unroll
        for (int o = 4; o; o >>= 1) v += __shfl_xor_sync(0xffffffffu, v, o);
        if (tid == 0) red[0] = v;
    }
    __syncthreads();
    float r = red[0];
    __syncthreads();
    return r;
}

// ---------------- layernorm ----------------
__global__ void k_ln(const float* __restrict__ x, const float* __restrict__ g,
                     const float* __restrict__ b, float* __restrict__ out) {
    __shared__ float red[32];
    int row = blockIdx.x, tid = threadIdx.x;
    const float* xr = x + (size_t)row * EE;
    float v[4];
    float s = 0.f;
    #pragma unroll
    for (int i = 0; i < 4; i++) { v[i] = xr[tid + 256 * i]; s += v[i]; }
    s = blockReduceSum(s, red);
    float mean = s * (1.f / EE);
    float s2 = 0.f;
    #pragma unroll
    for (int i = 0; i < 4; i++) { float d = v[i] - mean; s2 += d * d; }
    s2 = blockReduceSum(s2, red);
    float inv = rsqrtf(s2 * (1.f / EE) + 1e-5f);
    #pragma unroll
    for (int i = 0; i < 4; i++) {
        int c = tid + 256 * i;
        out[(size_t)row * EE + c] = (v[i] - mean) * inv * g[c] + b[c];
    }
}

// ---------------- softmax per row (variable length) ----------------
__global__ void k_softmax() {
    __shared__ float red[32];
    int row = blockIdx.x;
    int qpos = row & (TT - 1);
    int L = (qpos | 127) + 1;
    float* r = g_S + (size_t)row * TT;
    int tid = threadIdx.x;
    float v[4], m = -1e30f;
    #pragma unroll
    for (int i = 0; i < 4; i++) {
        int c = tid + 256 * i;
        v[i] = (c < L) ? r[c] : -1e30f;
        m = fmaxf(m, v[i]);
    }
    #pragma unroll
    for (int o = 16; o; o >>= 1) m = fmaxf(m, __shfl_xor_sync(0xffffffffu, m, o));
    if ((tid & 31) == 0) red[tid >> 5] = m;
    __syncthreads();
    if (tid < 32) {
        float t = (tid < 8) ? red[tid] : -1e30f;
        #pragma unroll
        for (int o = 4; o; o >>= 1) t = fmaxf(t, __shfl_xor_sync(0xffffffffu, t, o));
        if (tid == 0) red[0] = t;
    }
    __syncthreads();
    m = red[0];
    __syncthreads();
    float s = 0.f;
    #pragma unroll
    for (int i = 0; i < 4; i++) { v[i] = __expf(v[i] - m); s += v[i]; }
    s = blockReduceSum(s, red);
    float inv = 1.f / s;
    #pragma unroll
    for (int i = 0; i < 4; i++) {
        int c = tid + 256 * i;
        if (c < L) r[c] = v[i] * inv;
    }
}

// ---------------- host orchestration ----------------
extern "C" void kernel_launch(void* const* d_in, const int* in_sizes, int n_in,
                              void* d_out, int out_size) {
    const int*   idx  = (const int*)  d_in[0];
    const float* tok  = (const float*)d_in[1];
    const float* pos  = (const float*)d_in[2];
    const float* Wq   = (const float*)d_in[3];
    const float* Wk   = (const float*)d_in[4];
    const float* Wv   = (const float*)d_in[5];
    const float* Wp   = (const float*)d_in[6];
    const float* bp   = (const float*)d_in[7];
    const float* g1   = (const float*)d_in[8];
    const float* b1   = (const float*)d_in[9];
    const float* g2   = (const float*)d_in[10];
    const float* b2   = (const float*)d_in[11];
    const float* W1   = (const float*)d_in[12];
    const float* bf1  = (const float*)d_in[13];
    const float* W2   = (const float*)d_in[14];
    const float* bf2  = (const float*)d_in[15];
    const float* gf   = (const float*)d_in[16];
    const float* bff  = (const float*)d_in[17];
    const float* Wlm  = (const float*)d_in[18];
    const float* blm  = (const float*)d_in[19];
    float* out = (float*)d_out;

    float *x, *h, *q, *k, *v, *o, *ff;
    cudaGetSymbolAddress((void**)&x,  g_x);
    cudaGetSymbolAddress((void**)&h,  g_h);
    cudaGetSymbolAddress((void**)&q,  g_q);
    cudaGetSymbolAddress((void**)&k,  g_k);
    cudaGetSymbolAddress((void**)&v,  g_v);
    cudaGetSymbolAddress((void**)&o,  g_o);
    cudaGetSymbolAddress((void**)&ff, g_ff);

    cudaFuncSetAttribute(k_tgemm<false,false,false>,
                         cudaFuncAttributeMaxDynamicSharedMemorySize, TG_SMEM);
    cudaFuncSetAttribute(k_tgemm<true,false,true>,
                         cudaFuncAttributeMaxDynamicSharedMemorySize, TG_SMEM);
    cudaFuncSetAttribute(k_tgemm<true,true,false>,
                         cudaFuncAttributeMaxDynamicSharedMemorySize, TG_SMEM);
    cudaFuncSetAttribute(k_tgemm<true,false,false>,
                         cudaFuncAttributeMaxDynamicSharedMemorySize, TG_SMEM);
    cudaFuncSetAttribute(k_scores_t,
                         cudaFuncAttributeMaxDynamicSharedMemorySize, SC_SMEM);
    cudaFuncSetAttribute(k_av_t,
                         cudaFuncAttributeMaxDynamicSharedMemorySize, AV_SMEM);

    k_embed<<<RR, 256>>>(idx, tok, pos, x);

    // grid: x = M/128 (row tiles), y = N/64 (col tiles)
    dim3 gEE(RR / 128, EE / 64);       // (16, 16)
    dim3 gFF(RR / 128, FF / 64);       // (16, 64)
    dim3 gLM(RR / 128, VV / 64);       // (16, 500)

    for (int l = 0; l < LL; l++) {
        const float* wq = Wq + (size_t)l * EE * EE;
        const float* wk = Wk + (size_t)l * EE * EE;
        const float* wv = Wv + (size_t)l * EE * EE;
        const float* wp = Wp + (size_t)l * EE * EE;
        const float* w1 = W1 + (size_t)l * EE * FF;
        const float* w2 = W2 + (size_t)l * FF * EE;

        k_ln<<<RR, 256>>>(x, g1 + l * EE, b1 + l * EE, h);
        k_tgemm<false,false,false><<<gEE, 128, TG_SMEM>>>(h, wq, nullptr, nullptr, q, RR, EE, EE);
        k_tgemm<false,false,false><<<gEE, 128, TG_SMEM>>>(h, wk, nullptr, nullptr, k, RR, EE, EE);
        k_tgemm<false,false,false><<<gEE, 128, TG_SMEM>>>(h, wv, nullptr, nullptr, v, RR, EE, EE);

        k_scores_t<<<dim3(8, 8, 32), 512, SC_SMEM>>>(q, k);
        k_softmax<<<BB * HH * TT, 256>>>();
        k_av_t<<<dim3(8, 32), 256, AV_SMEM>>>(v, o);

        // x = x + o @ Wp + bp
        k_tgemm<true,false,true><<<gEE, 128, TG_SMEM>>>(o, wp, bp + l * EE, x, x, RR, EE, EE);

        k_ln<<<RR, 256>>>(x, g2 + l * EE, b2 + l * EE, h);
        // ff = relu(h @ W1 + bf1)
        k_tgemm<true,true,false><<<gFF, 128, TG_SMEM>>>(h, w1, bf1 + l * FF, nullptr, ff, RR, FF, EE);
        // x = x + ff @ W2 + bf2
        k_tgemm<true,false,true><<<gEE, 128, TG_SMEM>>>(ff, w2, bf2 + l * EE, x, x, RR, EE, FF);
    }

    k_ln<<<RR, 256>>>(x, gf, bff, h);
    k_tgemm<true,false,false><<<gLM, 128, TG_SMEM>>>(h, Wlm, blm, nullptr, out, RR, VV, EE);
}